// round 1
// baseline (speedup 1.0000x reference)
#include <cuda_runtime.h>
#include <math.h>

#define Bc 2
#define Lc 2048
#define Dc 1024
#define Hc 16
#define HDc 64
#define Rc 256
#define Ec 8
#define Kc 2
#define Fc 1024
#define Tc (Bc*Lc)   // 4096

// ---------------- scratch (device globals; no allocation allowed) ----------------
__device__ float g_xn[Tc*Dc];
__device__ float g_q[Tc*Hc*HDc];
__device__ float g_lat[Tc*Rc];
__device__ float g_kv[Tc*2*Hc*HDc];
__device__ float g_attn[Tc*Hc*HDc];
__device__ float g_h[Tc*Dc];
__device__ float g_hn[Tc*Dc];
__device__ float g_g1[Tc*Fc];
__device__ float g_g3[Tc*Fc];
__device__ float g_shared[Tc*Dc];
__device__ float g_eh1[(long)Ec*Tc*Fc];
__device__ float g_eh3[(long)Ec*Tc*Fc];
__device__ float g_eo[(long)Ec*Tc*Dc];
__device__ int   g_cnt[Ec];
__device__ int   g_idx[Ec*Tc];
__device__ int   g_slot[Tc*Kc];
__device__ float g_tw[Tc*Kc];

// ---------------- small kernels ----------------
__global__ void zero_cnt_k() {
    if (threadIdx.x < Ec) g_cnt[threadIdx.x] = 0;
}

// rmsnorm: one block per row
__global__ void rmsnorm_k(const float* __restrict__ x, const float* __restrict__ w,
                          float* __restrict__ o, int dim) {
    int row = blockIdx.x;
    int tid = threadIdx.x;
    const float* xr = x + (long)row * dim;
    float s = 0.f;
    for (int d = tid; d < dim; d += blockDim.x) { float v = xr[d]; s += v * v; }
    __shared__ float red[256];
    red[tid] = s;
    __syncthreads();
    for (int off = 128; off > 0; off >>= 1) {
        if (tid < off) red[tid] += red[tid + off];
        __syncthreads();
    }
    float inv = rsqrtf(red[0] / (float)dim + 1e-6f);
    float* orow = o + (long)row * dim;
    for (int d = tid; d < dim; d += blockDim.x) orow[d] = w[d] * xr[d] * inv;
}

// o = silu(a) * b  (elementwise, float4)
__global__ void silu_mul_k(const float* __restrict__ a, const float* __restrict__ b,
                           float* __restrict__ o, long n4) {
    long i = (long)blockIdx.x * blockDim.x + threadIdx.x;
    if (i >= n4) return;
    float4 av = ((const float4*)a)[i];
    float4 bv = ((const float4*)b)[i];
    float4 r;
    r.x = av.x / (1.f + expf(-av.x)) * bv.x;
    r.y = av.y / (1.f + expf(-av.y)) * bv.y;
    r.z = av.z / (1.f + expf(-av.z)) * bv.z;
    r.w = av.w / (1.f + expf(-av.w)) * bv.w;
    ((float4*)o)[i] = r;
}

// expert-guarded silu-mul on g_eh1 *= with g_eh3
__global__ void silu_mul_expert_k() {
    int e = blockIdx.y;
    int cnt = g_cnt[e];
    long i4 = (long)blockIdx.x * blockDim.x + threadIdx.x;  // float4 idx within expert
    if (i4 >= (long)Tc * Fc / 4) return;
    int row = (int)((i4 * 4) / Fc);
    if (row >= cnt) return;
    long base = (long)e * Tc * Fc / 4;
    float4 av = ((const float4*)g_eh1)[base + i4];
    float4 bv = ((const float4*)g_eh3)[base + i4];
    float4 r;
    r.x = av.x / (1.f + expf(-av.x)) * bv.x;
    r.y = av.y / (1.f + expf(-av.y)) * bv.y;
    r.z = av.z / (1.f + expf(-av.z)) * bv.z;
    r.w = av.w / (1.f + expf(-av.w)) * bv.w;
    ((float4*)g_eh1)[base + i4] = r;
}

// ---------------- generic fp32 GEMM, 64x64 tile, BK=16, 256 threads, 4x4 microtile ----------------
template<bool GATHER, bool HAS_CNT, bool RESID>
__global__ void gemm64(const float* __restrict__ A, const float* __restrict__ Bw,
                       float* __restrict__ C, const float* __restrict__ resid,
                       const int* __restrict__ gidx, const int* __restrict__ cntp,
                       int M, int N, int Kd,
                       long aEs, long bEs, long cEs, int iEs) {
    int e = blockIdx.z;
    A += (long)e * aEs;
    Bw += (long)e * bEs;
    C += (long)e * cEs;
    int Me = M;
    if (HAS_CNT) Me = cntp[e];
    int bm = blockIdx.y * 64, bn = blockIdx.x * 64;
    if (bm >= Me) return;

    __shared__ float As[16][64];
    __shared__ float Bs[16][64];
    int tid = threadIdx.x;
    int tx = tid & 15, ty = tid >> 4;
    int lar = tid >> 2;            // A: 64 rows x 4 threads/row
    int lac = (tid & 3) * 4;       // 4 floats each
    int lbr = tid >> 4;            // B: 16 rows x 16 threads/row
    int lbc = (tid & 15) * 4;

    int am = bm + lar;
    bool avalid = true;
    long arow;
    if (HAS_CNT && am >= Me) { avalid = false; arow = 0; }
    else if (GATHER) {
        int g = gidx[e * iEs + am];
        if (g < 0) g = 0; if (g >= Tc) g = 0;
        arow = (long)g * Kd;
    } else {
        arow = (long)am * Kd;
    }

    float acc[4][4];
    #pragma unroll
    for (int i = 0; i < 4; i++)
        #pragma unroll
        for (int j = 0; j < 4; j++) acc[i][j] = 0.f;

    for (int k0 = 0; k0 < Kd; k0 += 16) {
        float4 av = avalid ? *(const float4*)(A + arow + k0 + lac) : make_float4(0, 0, 0, 0);
        float4 bv = *(const float4*)(Bw + (long)(k0 + lbr) * N + bn + lbc);
        As[lac + 0][lar] = av.x;
        As[lac + 1][lar] = av.y;
        As[lac + 2][lar] = av.z;
        As[lac + 3][lar] = av.w;
        *(float4*)&Bs[lbr][lbc] = bv;
        __syncthreads();
        #pragma unroll
        for (int kk = 0; kk < 16; kk++) {
            float4 a4 = *(const float4*)&As[kk][ty * 4];
            float4 b4 = *(const float4*)&Bs[kk][tx * 4];
            float aa[4] = {a4.x, a4.y, a4.z, a4.w};
            float bb[4] = {b4.x, b4.y, b4.z, b4.w};
            #pragma unroll
            for (int i = 0; i < 4; i++)
                #pragma unroll
                for (int j = 0; j < 4; j++) acc[i][j] += aa[i] * bb[j];
        }
        __syncthreads();
    }

    #pragma unroll
    for (int i = 0; i < 4; i++) {
        int m = bm + ty * 4 + i;
        if (HAS_CNT && m >= Me) continue;
        long off = (long)m * N + bn + tx * 4;
        float4 r = make_float4(acc[i][0], acc[i][1], acc[i][2], acc[i][3]);
        if (RESID) {
            float4 rv = *(const float4*)(resid + off);
            r.x += rv.x; r.y += rv.y; r.z += rv.z; r.w += rv.w;
        }
        *(float4*)(C + off) = r;
    }
}

// ---------------- causal flash attention (fp32) ----------------
// grid: (L/128, H, B), block 128; thread owns one query row
__global__ void attn_kernel(const float* __restrict__ q, const float* __restrict__ kv,
                            float* __restrict__ o) {
    const int b = blockIdx.z, h = blockIdx.y;
    const int q0 = blockIdx.x * 128;
    const int tid = threadIdx.x;
    const int ql = q0 + tid;

    __shared__ float Ks[64][64];
    __shared__ float Vs[64][64];

    float qreg[64];
    const long qbase = ((long)(b * Lc + ql)) * (Hc * HDc) + h * HDc;
    #pragma unroll
    for (int d = 0; d < 64; d += 4) {
        float4 v = *(const float4*)(q + qbase + d);
        qreg[d] = v.x; qreg[d + 1] = v.y; qreg[d + 2] = v.z; qreg[d + 3] = v.w;
    }
    float acc[64];
    #pragma unroll
    for (int d = 0; d < 64; d++) acc[d] = 0.f;
    float mi = -INFINITY, li = 0.f;

    const int kend = q0 + 127;
    for (int kt = 0; kt <= kend; kt += 64) {
        // load K,V 64x64 tiles: each thread loads half a row (32 floats) of each
        int j = tid >> 1, d0 = (tid & 1) * 32;
        long kvbase = ((long)(b * Lc + kt + j)) * (2 * Hc * HDc) + h * HDc;
        #pragma unroll
        for (int dd = 0; dd < 32; dd += 4) {
            *(float4*)&Ks[j][d0 + dd] = *(const float4*)(kv + kvbase + d0 + dd);
            *(float4*)&Vs[j][d0 + dd] = *(const float4*)(kv + kvbase + Hc * HDc + d0 + dd);
        }
        __syncthreads();

        int jmax = ql - kt + 1;
        if (jmax > 64) jmax = 64;
        for (int jj = 0; jj < jmax; jj++) {
            float s0 = 0.f, s1 = 0.f, s2 = 0.f, s3 = 0.f;
            #pragma unroll
            for (int d = 0; d < 64; d += 4) {
                float4 k4 = *(const float4*)&Ks[jj][d];
                s0 += qreg[d] * k4.x;
                s1 += qreg[d + 1] * k4.y;
                s2 += qreg[d + 2] * k4.z;
                s3 += qreg[d + 3] * k4.w;
            }
            float s = 0.125f * ((s0 + s1) + (s2 + s3));
            if (s <= mi) {
                float p = __expf(s - mi);
                li += p;
                #pragma unroll
                for (int d = 0; d < 64; d += 4) {
                    float4 v4 = *(const float4*)&Vs[jj][d];
                    acc[d] += p * v4.x; acc[d + 1] += p * v4.y;
                    acc[d + 2] += p * v4.z; acc[d + 3] += p * v4.w;
                }
            } else {
                float corr = __expf(mi - s);
                mi = s;
                li = li * corr + 1.f;
                #pragma unroll
                for (int d = 0; d < 64; d += 4) {
                    float4 v4 = *(const float4*)&Vs[jj][d];
                    acc[d] = acc[d] * corr + v4.x; acc[d + 1] = acc[d + 1] * corr + v4.y;
                    acc[d + 2] = acc[d + 2] * corr + v4.z; acc[d + 3] = acc[d + 3] * corr + v4.w;
                }
            }
        }
        __syncthreads();
    }

    float inv = 1.f / li;
    #pragma unroll
    for (int d = 0; d < 64; d += 4) {
        float4 r = make_float4(acc[d] * inv, acc[d + 1] * inv, acc[d + 2] * inv, acc[d + 3] * inv);
        *(float4*)(o + qbase + d) = r;
    }
}

// ---------------- router: warp per token ----------------
__global__ void router_kernel(const float* __restrict__ hn, const float* __restrict__ gw,
                              float* __restrict__ probs_out) {
    int warp = (blockIdx.x * blockDim.x + threadIdx.x) >> 5;
    int lane = threadIdx.x & 31;
    if (warp >= Tc) return;
    const float* row = hn + (long)warp * Dc;
    float acc[8] = {0, 0, 0, 0, 0, 0, 0, 0};
    for (int d = lane; d < Dc; d += 32) {
        float xv = row[d];
        const float* g = gw + d * 8;
        #pragma unroll
        for (int e = 0; e < 8; e++) acc[e] += xv * g[e];
    }
    #pragma unroll
    for (int e = 0; e < 8; e++)
        #pragma unroll
        for (int off = 16; off > 0; off >>= 1)
            acc[e] += __shfl_xor_sync(0xffffffffu, acc[e], off);

    if (lane == 0) {
        float mx = acc[0];
        #pragma unroll
        for (int e = 1; e < 8; e++) mx = fmaxf(mx, acc[e]);
        float p[8], s = 0.f;
        #pragma unroll
        for (int e = 0; e < 8; e++) { p[e] = expf(acc[e] - mx); s += p[e]; }
        float invs = 1.f / s;
        #pragma unroll
        for (int e = 0; e < 8; e++) { p[e] *= invs; probs_out[(long)warp * 8 + e] = p[e]; }
        int i1 = 0;
        #pragma unroll
        for (int e = 1; e < 8; e++) if (p[e] > p[i1]) i1 = e;
        int i2 = (i1 == 0) ? 1 : 0;
        #pragma unroll
        for (int e = 0; e < 8; e++) if (e != i1 && p[e] > p[i2]) i2 = e;
        float w1 = p[i1], w2 = p[i2];
        float inv2 = 1.f / (w1 + w2);
        w1 *= inv2; w2 *= inv2;
        int pos1 = atomicAdd(&g_cnt[i1], 1);
        g_idx[i1 * Tc + pos1] = warp;
        g_slot[warp * 2 + 0] = i1 * Tc + pos1;
        g_tw[warp * 2 + 0] = w1;
        int pos2 = atomicAdd(&g_cnt[i2], 1);
        g_idx[i2 * Tc + pos2] = warp;
        g_slot[warp * 2 + 1] = i2 * Tc + pos2;
        g_tw[warp * 2 + 1] = w2;
    }
}

// ---------------- final combine: out = h + shared + w0*eo[slot0] + w1*eo[slot1] ----------------
__global__ void final_kernel(const float* __restrict__ h, const float* __restrict__ sh,
                             float* __restrict__ out) {
    long i4 = (long)blockIdx.x * blockDim.x + threadIdx.x;
    if (i4 >= (long)Tc * Dc / 4) return;
    int t = (int)(i4 / (Dc / 4));
    int d4 = (int)(i4 % (Dc / 4));
    int s0 = g_slot[t * 2 + 0], s1 = g_slot[t * 2 + 1];
    float w0 = g_tw[t * 2 + 0], w1 = g_tw[t * 2 + 1];
    float4 e0 = *(const float4*)(g_eo + (long)s0 * Dc + d4 * 4);
    float4 e1 = *(const float4*)(g_eo + (long)s1 * Dc + d4 * 4);
    float4 hv = ((const float4*)h)[i4];
    float4 sv = ((const float4*)sh)[i4];
    float4 r;
    r.x = hv.x + sv.x + w0 * e0.x + w1 * e1.x;
    r.y = hv.y + sv.y + w0 * e0.y + w1 * e1.y;
    r.z = hv.z + sv.z + w0 * e0.z + w1 * e1.z;
    r.w = hv.w + sv.w + w0 * e0.w + w1 * e1.w;
    ((float4*)out)[i4] = r;
}

// ---------------- launch ----------------
extern "C" void kernel_launch(void* const* d_in, const int* in_sizes, int n_in,
                              void* d_out, int out_size) {
    const float* x     = (const float*)d_in[0];
    const float* ln1_w = (const float*)d_in[1];
    const float* q_w   = (const float*)d_in[2];
    const float* kvd_w = (const float*)d_in[3];
    const float* kvn_w = (const float*)d_in[4];
    const float* kvu_w = (const float*)d_in[5];
    const float* o_w   = (const float*)d_in[6];
    const float* ln2_w = (const float*)d_in[7];
    const float* gate_w= (const float*)d_in[8];
    const float* sh_w1 = (const float*)d_in[9];
    const float* sh_w2 = (const float*)d_in[10];
    const float* sh_w3 = (const float*)d_in[11];
    const float* re_w1 = (const float*)d_in[12];
    const float* re_w2 = (const float*)d_in[13];
    const float* re_w3 = (const float*)d_in[14];

    float* outy = (float*)d_out;                 // [B,L,D]
    float* outp = outy + (long)Tc * Dc;          // [T,E]

    float *xn, *qb, *lat, *kvb, *attn, *hb, *hnb, *g1, *g3, *shb, *eh1, *eh3, *eo;
    cudaGetSymbolAddress((void**)&xn, g_xn);
    cudaGetSymbolAddress((void**)&qb, g_q);
    cudaGetSymbolAddress((void**)&lat, g_lat);
    cudaGetSymbolAddress((void**)&kvb, g_kv);
    cudaGetSymbolAddress((void**)&attn, g_attn);
    cudaGetSymbolAddress((void**)&hb, g_h);
    cudaGetSymbolAddress((void**)&hnb, g_hn);
    cudaGetSymbolAddress((void**)&g1, g_g1);
    cudaGetSymbolAddress((void**)&g3, g_g3);
    cudaGetSymbolAddress((void**)&shb, g_shared);
    cudaGetSymbolAddress((void**)&eh1, g_eh1);
    cudaGetSymbolAddress((void**)&eh3, g_eh3);
    cudaGetSymbolAddress((void**)&eo, g_eo);
    int* idxp; int* cntp;
    cudaGetSymbolAddress((void**)&idxp, g_idx);
    cudaGetSymbolAddress((void**)&cntp, g_cnt);

    zero_cnt_k<<<1, 32>>>();

    // attention path
    rmsnorm_k<<<Tc, 256>>>(x, ln1_w, xn, Dc);
    gemm64<false, false, false><<<dim3(16, 64, 1), 256>>>(xn, q_w, qb, nullptr, nullptr, nullptr,
                                                          Tc, Hc * HDc, Dc, 0, 0, 0, 0);
    gemm64<false, false, false><<<dim3(4, 64, 1), 256>>>(xn, kvd_w, lat, nullptr, nullptr, nullptr,
                                                         Tc, Rc, Dc, 0, 0, 0, 0);
    rmsnorm_k<<<Tc, 256>>>(lat, kvn_w, lat, Rc);
    gemm64<false, false, false><<<dim3(32, 64, 1), 256>>>(lat, kvu_w, kvb, nullptr, nullptr, nullptr,
                                                          Tc, 2 * Hc * HDc, Rc, 0, 0, 0, 0);
    attn_kernel<<<dim3(Lc / 128, Hc, Bc), 128>>>(qb, kvb, attn);
    gemm64<false, false, true><<<dim3(16, 64, 1), 256>>>(attn, o_w, hb, x, nullptr, nullptr,
                                                         Tc, Dc, Hc * HDc, 0, 0, 0, 0);

    // MoE path
    rmsnorm_k<<<Tc, 256>>>(hb, ln2_w, hnb, Dc);
    gemm64<false, false, false><<<dim3(16, 64, 1), 256>>>(hnb, sh_w1, g1, nullptr, nullptr, nullptr,
                                                          Tc, Fc, Dc, 0, 0, 0, 0);
    gemm64<false, false, false><<<dim3(16, 64, 1), 256>>>(hnb, sh_w3, g3, nullptr, nullptr, nullptr,
                                                          Tc, Fc, Dc, 0, 0, 0, 0);
    silu_mul_k<<<(Tc * Fc / 4 + 255) / 256, 256>>>(g1, g3, g1, (long)Tc * Fc / 4);
    gemm64<false, false, false><<<dim3(16, 64, 1), 256>>>(g1, sh_w2, shb, nullptr, nullptr, nullptr,
                                                          Tc, Dc, Fc, 0, 0, 0, 0);

    router_kernel<<<Tc / 8, 256>>>(hnb, gate_w, outp);

    // routed experts: gathered GEMMs (grid.z = expert, early-exit past count)
    gemm64<true, true, false><<<dim3(16, 64, Ec), 256>>>(hnb, re_w1, eh1, nullptr, idxp, cntp,
                                                         Tc, Fc, Dc, 0, (long)Dc * Fc, (long)Tc * Fc, Tc);
    gemm64<true, true, false><<<dim3(16, 64, Ec), 256>>>(hnb, re_w3, eh3, nullptr, idxp, cntp,
                                                         Tc, Fc, Dc, 0, (long)Dc * Fc, (long)Tc * Fc, Tc);
    silu_mul_expert_k<<<dim3((Tc * Fc / 4 + 255) / 256, Ec), 256>>>();
    gemm64<false, true, false><<<dim3(16, 64, Ec), 256>>>(eh1, re_w2, eo, nullptr, nullptr, cntp,
                                                          Tc, Dc, Fc, (long)Tc * Fc, (long)Fc * Dc, (long)Tc * Dc, 0);

    final_kernel<<<(Tc * Dc / 4 + 255) / 256, 256>>>(hb, shb, outy);
}

// round 3
// speedup vs baseline: 1.2892x; 1.2892x over previous
#include <cuda_runtime.h>
#include <mma.h>
#include <math.h>

using namespace nvcuda;

#define Bc 2
#define Lc 2048
#define Dc 1024
#define Hc 16
#define HDc 64
#define Rc 256
#define Ec 8
#define Kc 2
#define Fc 1024
#define Tc (Bc*Lc)   // 4096

// ---------------- scratch (device globals; no allocation allowed) ----------------
__device__ float g_xn[Tc*Dc];
__device__ float g_q[Tc*Hc*HDc];
__device__ float g_lat[Tc*Rc];
__device__ float g_kv[Tc*2*Hc*HDc];
__device__ float g_attn[Tc*Hc*HDc];
__device__ float g_h[Tc*Dc];
__device__ float g_hn[Tc*Dc];
__device__ float g_g1[Tc*Fc];
__device__ float g_g3[Tc*Fc];
__device__ float g_shared[Tc*Dc];
__device__ float g_eh1[(long)Ec*Tc*Fc];
__device__ float g_eh3[(long)Ec*Tc*Fc];
__device__ float g_eo[(long)Ec*Tc*Dc];
__device__ int   g_cnt[Ec];
__device__ int   g_idx[Ec*Tc];
__device__ int   g_slot[Tc*Kc];
__device__ float g_tw[Tc*Kc];

__device__ __forceinline__ float to_tf32(float x) {
    asm("cvt.rna.tf32.f32 %0, %1;" : "=f"(x) : "f"(x));
    return x;
}

// ---------------- small kernels ----------------
__global__ void zero_cnt_k() {
    if (threadIdx.x < Ec) g_cnt[threadIdx.x] = 0;
}

__global__ void rmsnorm_k(const float* __restrict__ x, const float* __restrict__ w,
                          float* __restrict__ o, int dim) {
    int row = blockIdx.x;
    int tid = threadIdx.x;
    const float* xr = x + (long)row * dim;
    float s = 0.f;
    for (int d = tid; d < dim; d += blockDim.x) { float v = xr[d]; s += v * v; }
    __shared__ float red[256];
    red[tid] = s;
    __syncthreads();
    for (int off = 128; off > 0; off >>= 1) {
        if (tid < off) red[tid] += red[tid + off];
        __syncthreads();
    }
    float inv = rsqrtf(red[0] / (float)dim + 1e-6f);
    float* orow = o + (long)row * dim;
    for (int d = tid; d < dim; d += blockDim.x) orow[d] = w[d] * xr[d] * inv;
}

__global__ void silu_mul_k(const float* __restrict__ a, const float* __restrict__ b,
                           float* __restrict__ o, long n4) {
    long i = (long)blockIdx.x * blockDim.x + threadIdx.x;
    if (i >= n4) return;
    float4 av = ((const float4*)a)[i];
    float4 bv = ((const float4*)b)[i];
    float4 r;
    r.x = av.x / (1.f + expf(-av.x)) * bv.x;
    r.y = av.y / (1.f + expf(-av.y)) * bv.y;
    r.z = av.z / (1.f + expf(-av.z)) * bv.z;
    r.w = av.w / (1.f + expf(-av.w)) * bv.w;
    ((float4*)o)[i] = r;
}

__global__ void silu_mul_expert_k() {
    int e = blockIdx.y;
    int cnt = g_cnt[e];
    long i4 = (long)blockIdx.x * blockDim.x + threadIdx.x;
    if (i4 >= (long)Tc * Fc / 4) return;
    int row = (int)((i4 * 4) / Fc);
    if (row >= cnt) return;
    long base = (long)e * Tc * Fc / 4;
    float4 av = ((const float4*)g_eh1)[base + i4];
    float4 bv = ((const float4*)g_eh3)[base + i4];
    float4 r;
    r.x = av.x / (1.f + expf(-av.x)) * bv.x;
    r.y = av.y / (1.f + expf(-av.y)) * bv.y;
    r.z = av.z / (1.f + expf(-av.z)) * bv.z;
    r.w = av.w / (1.f + expf(-av.w)) * bv.w;
    ((float4*)g_eh1)[base + i4] = r;
}

// ---------------- tf32 tensor-core GEMM ----------------
#define BM 128
#define BN 128
#define BK 32
#define ASTRIDE (BK + 8)     // 40
#define BSTRIDE (BN + 8)     // 136

template<bool GATHER, bool HAS_CNT, bool RESID>
__global__ void __launch_bounds__(256)
gemm_tc(const float* __restrict__ A, const float* __restrict__ Bw,
        float* __restrict__ C, const float* __restrict__ resid,
        const int* __restrict__ gidx, const int* __restrict__ cntp,
        int M, int N, int Kd,
        long aEs, long bEs, long cEs, int iEs) {
    int e = blockIdx.z;
    A += (long)e * aEs;
    Bw += (long)e * bEs;
    C += (long)e * cEs;
    int Me = M;
    if (HAS_CNT) Me = cntp[e];
    int bm = blockIdx.y * BM, bn = blockIdx.x * BN;
    if (bm >= Me) return;

    __shared__ float As[BM][ASTRIDE];
    __shared__ float Bs[BK][BSTRIDE];

    const int tid = threadIdx.x;
    const int warpId = tid >> 5;
    const int wm = warpId >> 1;        // 0..3   (rows wm*32)
    const int wn = warpId & 1;         // 0..1   (cols wn*64)

    const int arow0 = tid >> 3;        // 0..31
    const int acol  = (tid & 7) * 4;
    long aBase[4];
    #pragma unroll
    for (int i = 0; i < 4; i++) {
        int am = bm + arow0 + 32 * i;
        long r;
        if (GATHER) {
            int g = gidx[e * iEs + am];
            if (g < 0) g = 0;
            if (g >= Tc) g = 0;
            r = (long)g * Kd;
        } else {
            r = (long)am * Kd;
        }
        aBase[i] = r;
    }
    const int brow0 = tid >> 5;        // 0..7
    const int bcol  = (tid & 31) * 4;

    wmma::fragment<wmma::accumulator, 16, 16, 8, float> cf[2][4];
    if (RESID) {
        #pragma unroll
        for (int i = 0; i < 2; i++)
            #pragma unroll
            for (int j = 0; j < 4; j++)
                wmma::load_matrix_sync(cf[i][j],
                    resid + (long)(bm + wm * 32 + i * 16) * N + bn + wn * 64 + j * 16,
                    N, wmma::mem_row_major);
    } else {
        #pragma unroll
        for (int i = 0; i < 2; i++)
            #pragma unroll
            for (int j = 0; j < 4; j++)
                wmma::fill_fragment(cf[i][j], 0.f);
    }

    float4 aR[4], bR[4];
    #pragma unroll
    for (int i = 0; i < 4; i++)
        aR[i] = *(const float4*)(A + aBase[i] + acol);
    #pragma unroll
    for (int i = 0; i < 4; i++)
        bR[i] = *(const float4*)(Bw + (long)(brow0 + 8 * i) * N + bn + bcol);

    for (int k0 = 0; k0 < Kd; k0 += BK) {
        #pragma unroll
        for (int i = 0; i < 4; i++) {
            float* p = &As[arow0 + 32 * i][acol];
            p[0] = to_tf32(aR[i].x); p[1] = to_tf32(aR[i].y);
            p[2] = to_tf32(aR[i].z); p[3] = to_tf32(aR[i].w);
        }
        #pragma unroll
        for (int i = 0; i < 4; i++) {
            float* p = &Bs[brow0 + 8 * i][bcol];
            p[0] = to_tf32(bR[i].x); p[1] = to_tf32(bR[i].y);
            p[2] = to_tf32(bR[i].z); p[3] = to_tf32(bR[i].w);
        }
        __syncthreads();
        if (k0 + BK < Kd) {
            #pragma unroll
            for (int i = 0; i < 4; i++)
                aR[i] = *(const float4*)(A + aBase[i] + k0 + BK + acol);
            #pragma unroll
            for (int i = 0; i < 4; i++)
                bR[i] = *(const float4*)(Bw + (long)(k0 + BK + brow0 + 8 * i) * N + bn + bcol);
        }
        #pragma unroll
        for (int kk = 0; kk < BK / 8; kk++) {
            wmma::fragment<wmma::matrix_a, 16, 16, 8, wmma::precision::tf32, wmma::row_major> af[2];
            wmma::fragment<wmma::matrix_b, 16, 16, 8, wmma::precision::tf32, wmma::row_major> bf[4];
            #pragma unroll
            for (int i = 0; i < 2; i++)
                wmma::load_matrix_sync(af[i], &As[wm * 32 + i * 16][kk * 8], ASTRIDE);
            #pragma unroll
            for (int j = 0; j < 4; j++)
                wmma::load_matrix_sync(bf[j], &Bs[kk * 8][wn * 64 + j * 16], BSTRIDE);
            #pragma unroll
            for (int i = 0; i < 2; i++)
                #pragma unroll
                for (int j = 0; j < 4; j++)
                    wmma::mma_sync(cf[i][j], af[i], bf[j], cf[i][j]);
        }
        __syncthreads();
    }

    #pragma unroll
    for (int i = 0; i < 2; i++)
        #pragma unroll
        for (int j = 0; j < 4; j++)
            wmma::store_matrix_sync(
                C + (long)(bm + wm * 32 + i * 16) * N + bn + wn * 64 + j * 16,
                cf[i][j], N, wmma::mem_row_major);
}

// ---------------- causal flash attention (fp32) ----------------
__global__ void attn_kernel(const float* __restrict__ q, const float* __restrict__ kv,
                            float* __restrict__ o) {
    const int b = blockIdx.z, h = blockIdx.y;
    const int q0 = blockIdx.x * 128;
    const int tid = threadIdx.x;
    const int ql = q0 + tid;

    __shared__ float Ks[64][64];
    __shared__ float Vs[64][64];

    float qreg[64];
    const long qbase = ((long)(b * Lc + ql)) * (Hc * HDc) + h * HDc;
    #pragma unroll
    for (int d = 0; d < 64; d += 4) {
        float4 v = *(const float4*)(q + qbase + d);
        qreg[d] = v.x; qreg[d + 1] = v.y; qreg[d + 2] = v.z; qreg[d + 3] = v.w;
    }
    float acc[64];
    #pragma unroll
    for (int d = 0; d < 64; d++) acc[d] = 0.f;
    float mi = -INFINITY, li = 0.f;

    const int kend = q0 + 127;
    for (int kt = 0; kt <= kend; kt += 64) {
        int j = tid >> 1, d0 = (tid & 1) * 32;
        long kvbase = ((long)(b * Lc + kt + j)) * (2 * Hc * HDc) + h * HDc;
        #pragma unroll
        for (int dd = 0; dd < 32; dd += 4) {
            *(float4*)&Ks[j][d0 + dd] = *(const float4*)(kv + kvbase + d0 + dd);
            *(float4*)&Vs[j][d0 + dd] = *(const float4*)(kv + kvbase + Hc * HDc + d0 + dd);
        }
        __syncthreads();

        int jmax = ql - kt + 1;
        if (jmax > 64) jmax = 64;
        for (int jj = 0; jj < jmax; jj++) {
            float s0 = 0.f, s1 = 0.f, s2 = 0.f, s3 = 0.f;
            #pragma unroll
            for (int d = 0; d < 64; d += 4) {
                float4 k4 = *(const float4*)&Ks[jj][d];
                s0 += qreg[d] * k4.x;
                s1 += qreg[d + 1] * k4.y;
                s2 += qreg[d + 2] * k4.z;
                s3 += qreg[d + 3] * k4.w;
            }
            float s = 0.125f * ((s0 + s1) + (s2 + s3));
            if (s <= mi) {
                float p = __expf(s - mi);
                li += p;
                #pragma unroll
                for (int d = 0; d < 64; d += 4) {
                    float4 v4 = *(const float4*)&Vs[jj][d];
                    acc[d] += p * v4.x; acc[d + 1] += p * v4.y;
                    acc[d + 2] += p * v4.z; acc[d + 3] += p * v4.w;
                }
            } else {
                float corr = __expf(mi - s);
                mi = s;
                li = li * corr + 1.f;
                #pragma unroll
                for (int d = 0; d < 64; d += 4) {
                    float4 v4 = *(const float4*)&Vs[jj][d];
                    acc[d] = acc[d] * corr + v4.x; acc[d + 1] = acc[d + 1] * corr + v4.y;
                    acc[d + 2] = acc[d + 2] * corr + v4.z; acc[d + 3] = acc[d + 3] * corr + v4.w;
                }
            }
        }
        __syncthreads();
    }

    float inv = 1.f / li;
    #pragma unroll
    for (int d = 0; d < 64; d += 4) {
        float4 r = make_float4(acc[d] * inv, acc[d + 1] * inv, acc[d + 2] * inv, acc[d + 3] * inv);
        *(float4*)(o + qbase + d) = r;
    }
}

// ---------------- router ----------------
__global__ void router_kernel(const float* __restrict__ hn, const float* __restrict__ gw,
                              float* __restrict__ probs_out) {
    int warp = (blockIdx.x * blockDim.x + threadIdx.x) >> 5;
    int lane = threadIdx.x & 31;
    if (warp >= Tc) return;
    const float* row = hn + (long)warp * Dc;
    float acc[8] = {0, 0, 0, 0, 0, 0, 0, 0};
    for (int d = lane; d < Dc; d += 32) {
        float xv = row[d];
        const float* g = gw + d * 8;
        #pragma unroll
        for (int e = 0; e < 8; e++) acc[e] += xv * g[e];
    }
    #pragma unroll
    for (int e = 0; e < 8; e++)
        #pragma unroll
        for (int off = 16; off > 0; off >>= 1)
            acc[e] += __shfl_xor_sync(0xffffffffu, acc[e], off);

    if (lane == 0) {
        float mx = acc[0];
        #pragma unroll
        for (int e = 1; e < 8; e++) mx = fmaxf(mx, acc[e]);
        float p[8], s = 0.f;
        #pragma unroll
        for (int e = 0; e < 8; e++) { p[e] = expf(acc[e] - mx); s += p[e]; }
        float invs = 1.f / s;
        #pragma unroll
        for (int e = 0; e < 8; e++) { p[e] *= invs; probs_out[(long)warp * 8 + e] = p[e]; }
        int i1 = 0;
        #pragma unroll
        for (int e = 1; e < 8; e++) if (p[e] > p[i1]) i1 = e;
        int i2 = (i1 == 0) ? 1 : 0;
        #pragma unroll
        for (int e = 0; e < 8; e++) if (e != i1 && p[e] > p[i2]) i2 = e;
        float w1 = p[i1], w2 = p[i2];
        float inv2 = 1.f / (w1 + w2);
        w1 *= inv2; w2 *= inv2;
        int pos1 = atomicAdd(&g_cnt[i1], 1);
        g_idx[i1 * Tc + pos1] = warp;
        g_slot[warp * 2 + 0] = i1 * Tc + pos1;
        g_tw[warp * 2 + 0] = w1;
        int pos2 = atomicAdd(&g_cnt[i2], 1);
        g_idx[i2 * Tc + pos2] = warp;
        g_slot[warp * 2 + 1] = i2 * Tc + pos2;
        g_tw[warp * 2 + 1] = w2;
    }
}

// ---------------- final combine ----------------
__global__ void final_kernel(const float* __restrict__ h, const float* __restrict__ sh,
                             float* __restrict__ out) {
    long i4 = (long)blockIdx.x * blockDim.x + threadIdx.x;
    if (i4 >= (long)Tc * Dc / 4) return;
    int t = (int)(i4 / (Dc / 4));
    int d4 = (int)(i4 % (Dc / 4));
    int s0 = g_slot[t * 2 + 0], s1 = g_slot[t * 2 + 1];
    float w0 = g_tw[t * 2 + 0], w1 = g_tw[t * 2 + 1];
    float4 e0 = *(const float4*)(g_eo + (long)s0 * Dc + d4 * 4);
    float4 e1 = *(const float4*)(g_eo + (long)s1 * Dc + d4 * 4);
    float4 hv = ((const float4*)h)[i4];
    float4 sv = ((const float4*)sh)[i4];
    float4 r;
    r.x = hv.x + sv.x + w0 * e0.x + w1 * e1.x;
    r.y = hv.y + sv.y + w0 * e0.y + w1 * e1.y;
    r.z = hv.z + sv.z + w0 * e0.z + w1 * e1.z;
    r.w = hv.w + sv.w + w0 * e0.w + w1 * e1.w;
    ((float4*)out)[i4] = r;
}

// ---------------- launch ----------------
extern "C" void kernel_launch(void* const* d_in, const int* in_sizes, int n_in,
                              void* d_out, int out_size) {
    const float* x     = (const float*)d_in[0];
    const float* ln1_w = (const float*)d_in[1];
    const float* q_w   = (const float*)d_in[2];
    const float* kvd_w = (const float*)d_in[3];
    const float* kvn_w = (const float*)d_in[4];
    const float* kvu_w = (const float*)d_in[5];
    const float* o_w   = (const float*)d_in[6];
    const float* ln2_w = (const float*)d_in[7];
    const float* gate_w= (const float*)d_in[8];
    const float* sh_w1 = (const float*)d_in[9];
    const float* sh_w2 = (const float*)d_in[10];
    const float* sh_w3 = (const float*)d_in[11];
    const float* re_w1 = (const float*)d_in[12];
    const float* re_w2 = (const float*)d_in[13];
    const float* re_w3 = (const float*)d_in[14];

    float* outy = (float*)d_out;                 // [B,L,D]
    float* outp = outy + (long)Tc * Dc;          // [T,E]

    float *xn, *qb, *lat, *kvb, *attn, *hb, *hnb, *g1, *g3, *shb, *eh1, *eh3, *eo;
    cudaGetSymbolAddress((void**)&xn, g_xn);
    cudaGetSymbolAddress((void**)&qb, g_q);
    cudaGetSymbolAddress((void**)&lat, g_lat);
    cudaGetSymbolAddress((void**)&kvb, g_kv);
    cudaGetSymbolAddress((void**)&attn, g_attn);
    cudaGetSymbolAddress((void**)&hb, g_h);
    cudaGetSymbolAddress((void**)&hnb, g_hn);
    cudaGetSymbolAddress((void**)&g1, g_g1);
    cudaGetSymbolAddress((void**)&g3, g_g3);
    cudaGetSymbolAddress((void**)&shb, g_shared);
    cudaGetSymbolAddress((void**)&eh1, g_eh1);
    cudaGetSymbolAddress((void**)&eh3, g_eh3);
    cudaGetSymbolAddress((void**)&eo, g_eo);
    int* idxp; int* cntp;
    cudaGetSymbolAddress((void**)&idxp, g_idx);
    cudaGetSymbolAddress((void**)&cntp, g_cnt);

    zero_cnt_k<<<1, 32>>>();

    rmsnorm_k<<<Tc, 256>>>(x, ln1_w, xn, Dc);
    gemm_tc<false, false, false><<<dim3(Hc * HDc / BN, Tc / BM, 1), 256>>>(
        xn, q_w, qb, nullptr, nullptr, nullptr, Tc, Hc * HDc, Dc, 0, 0, 0, 0);
    gemm_tc<false, false, false><<<dim3(Rc / BN, Tc / BM, 1), 256>>>(
        xn, kvd_w, lat, nullptr, nullptr, nullptr, Tc, Rc, Dc, 0, 0, 0, 0);
    rmsnorm_k<<<Tc, 256>>>(lat, kvn_w, lat, Rc);
    gemm_tc<false, false, false><<<dim3(2 * Hc * HDc / BN, Tc / BM, 1), 256>>>(
        lat, kvu_w, kvb, nullptr, nullptr, nullptr, Tc, 2 * Hc * HDc, Rc, 0, 0, 0, 0);
    attn_kernel<<<dim3(Lc / 128, Hc, Bc), 128>>>(qb, kvb, attn);
    gemm_tc<false, false, true><<<dim3(Dc / BN, Tc / BM, 1), 256>>>(
        attn, o_w, hb, x, nullptr, nullptr, Tc, Dc, Hc * HDc, 0, 0, 0, 0);

    rmsnorm_k<<<Tc, 256>>>(hb, ln2_w, hnb, Dc);
    gemm_tc<false, false, false><<<dim3(Fc / BN, Tc / BM, 1), 256>>>(
        hnb, sh_w1, g1, nullptr, nullptr, nullptr, Tc, Fc, Dc, 0, 0, 0, 0);
    gemm_tc<false, false, false><<<dim3(Fc / BN, Tc / BM, 1), 256>>>(
        hnb, sh_w3, g3, nullptr, nullptr, nullptr, Tc, Fc, Dc, 0, 0, 0, 0);
    silu_mul_k<<<(Tc * Fc / 4 + 255) / 256, 256>>>(g1, g3, g1, (long)Tc * Fc / 4);
    gemm_tc<false, false, false><<<dim3(Dc / BN, Tc / BM, 1), 256>>>(
        g1, sh_w2, shb, nullptr, nullptr, nullptr, Tc, Dc, Fc, 0, 0, 0, 0);

    router_kernel<<<Tc / 8, 256>>>(hnb, gate_w, outp);

    gemm_tc<true, true, false><<<dim3(Fc / BN, Tc / BM, Ec), 256>>>(
        hnb, re_w1, eh1, nullptr, idxp, cntp, Tc, Fc, Dc, 0, (long)Dc * Fc, (long)Tc * Fc, Tc);
    gemm_tc<true, true, false><<<dim3(Fc / BN, Tc / BM, Ec), 256>>>(
        hnb, re_w3, eh3, nullptr, idxp, cntp, Tc, Fc, Dc, 0, (long)Dc * Fc, (long)Tc * Fc, Tc);
    silu_mul_expert_k<<<dim3((Tc * Fc / 4 + 255) / 256, Ec), 256>>>();
    gemm_tc<false, true, false><<<dim3(Dc / BN, Tc / BM, Ec), 256>>>(
        eh1, re_w2, eo, nullptr, nullptr, cntp, Tc, Dc, Fc, (long)Tc * Fc, (long)Fc * Dc, (long)Tc * Dc, 0);

    final_kernel<<<(Tc * Dc / 4 + 255) / 256, 256>>>(hb, shb, outy);
}

// round 4
// speedup vs baseline: 1.4712x; 1.1412x over previous
#include <cuda_runtime.h>
#include <mma.h>
#include <math.h>

using namespace nvcuda;

#define Bc 2
#define Lc 2048
#define Dc 1024
#define Hc 16
#define HDc 64
#define Rc 256
#define Ec 8
#define Kc 2
#define Fc 1024
#define Tc (Bc*Lc)   // 4096

// ---------------- scratch (device globals; no allocation allowed) ----------------
__device__ float g_xn[Tc*Dc];
__device__ float g_q[Tc*Hc*HDc];
__device__ float g_lat[Tc*Rc];
__device__ float g_kv[Tc*2*Hc*HDc];
__device__ float g_attn[Tc*Hc*HDc];
__device__ float g_h[Tc*Dc];
__device__ float g_hn[Tc*Dc];
__device__ float g_g1[Tc*Fc];
__device__ float g_g3[Tc*Fc];
__device__ float g_shared[Tc*Dc];
__device__ float g_eh1[(long)Ec*Tc*Fc];
__device__ float g_eh3[(long)Ec*Tc*Fc];
__device__ float g_eo[(long)Ec*Tc*Dc];
__device__ int   g_cnt[Ec];
__device__ int   g_idx[Ec*Tc];
__device__ int   g_slot[Tc*Kc];
__device__ float g_tw[Tc*Kc];

// ---------------- small kernels ----------------
__global__ void zero_cnt_k() {
    if (threadIdx.x < Ec) g_cnt[threadIdx.x] = 0;
}

__global__ void rmsnorm_k(const float* __restrict__ x, const float* __restrict__ w,
                          float* __restrict__ o, int dim) {
    int row = blockIdx.x;
    int tid = threadIdx.x;
    const float* xr = x + (long)row * dim;
    float s = 0.f;
    for (int d = tid; d < dim; d += blockDim.x) { float v = xr[d]; s += v * v; }
    __shared__ float red[256];
    red[tid] = s;
    __syncthreads();
    for (int off = 128; off > 0; off >>= 1) {
        if (tid < off) red[tid] += red[tid + off];
        __syncthreads();
    }
    float inv = rsqrtf(red[0] / (float)dim + 1e-6f);
    float* orow = o + (long)row * dim;
    for (int d = tid; d < dim; d += blockDim.x) orow[d] = w[d] * xr[d] * inv;
}

__global__ void silu_mul_k(const float* __restrict__ a, const float* __restrict__ b,
                           float* __restrict__ o, long n4) {
    long i = (long)blockIdx.x * blockDim.x + threadIdx.x;
    if (i >= n4) return;
    float4 av = ((const float4*)a)[i];
    float4 bv = ((const float4*)b)[i];
    float4 r;
    r.x = av.x / (1.f + expf(-av.x)) * bv.x;
    r.y = av.y / (1.f + expf(-av.y)) * bv.y;
    r.z = av.z / (1.f + expf(-av.z)) * bv.z;
    r.w = av.w / (1.f + expf(-av.w)) * bv.w;
    ((float4*)o)[i] = r;
}

__global__ void silu_mul_expert_k() {
    int e = blockIdx.y;
    int cnt = g_cnt[e];
    long i4 = (long)blockIdx.x * blockDim.x + threadIdx.x;
    if (i4 >= (long)Tc * Fc / 4) return;
    int row = (int)((i4 * 4) / Fc);
    if (row >= cnt) return;
    long base = (long)e * Tc * Fc / 4;
    float4 av = ((const float4*)g_eh1)[base + i4];
    float4 bv = ((const float4*)g_eh3)[base + i4];
    float4 r;
    r.x = av.x / (1.f + expf(-av.x)) * bv.x;
    r.y = av.y / (1.f + expf(-av.y)) * bv.y;
    r.z = av.z / (1.f + expf(-av.z)) * bv.z;
    r.w = av.w / (1.f + expf(-av.w)) * bv.w;
    ((float4*)g_eh1)[base + i4] = r;
}

// ---------------- tf32 tensor-core GEMM, cp.async double-buffered ----------------
#define BM 128
#define BN 128
#define BK 32
#define AST 36                 // BM rows x 36 floats (144B, 16B aligned, 4-bank skew)
#define BST 132                // BK rows x 132 floats (528B, 16B aligned)
#define SM_A (BM*AST)          // floats per A stage
#define SM_B (BK*BST)          // floats per B stage
#define SMEM_FLOATS (2*(SM_A+SM_B))
#define SMEM_BYTES (SMEM_FLOATS*4)   // 70656 B

__device__ __forceinline__ void cp_async16(float* sdst, const float* gsrc) {
    unsigned s = (unsigned)__cvta_generic_to_shared(sdst);
    asm volatile("cp.async.cg.shared.global [%0], [%1], 16;" :: "r"(s), "l"(gsrc));
}
#define CP_COMMIT() asm volatile("cp.async.commit_group;")
#define CP_WAIT1()  asm volatile("cp.async.wait_group 1;")
#define CP_WAIT0()  asm volatile("cp.async.wait_group 0;")

template<bool GATHER, bool HAS_CNT, bool RESID>
__global__ void __launch_bounds__(256, 2)
gemm_tc(const float* __restrict__ A, const float* __restrict__ Bw,
        float* __restrict__ C, const float* __restrict__ resid,
        const int* __restrict__ gidx, const int* __restrict__ cntp,
        int M, int N, int Kd,
        long aEs, long bEs, long cEs, int iEs) {
    extern __shared__ float sm[];
    float* As = sm;               // [2][BM][AST]
    float* Bs = sm + 2 * SM_A;    // [2][BK][BST]

    int e = blockIdx.z;
    A += (long)e * aEs;
    Bw += (long)e * bEs;
    C += (long)e * cEs;
    int Me = HAS_CNT ? cntp[e] : M;
    int bm = blockIdx.y * BM, bn = blockIdx.x * BN;
    if (bm >= Me) return;

    const int tid = threadIdx.x;
    const int warpId = tid >> 5;
    const int wm = warpId >> 1;        // 0..3
    const int wn = warpId & 1;         // 0..1

    const int arow0 = tid >> 3;        // 0..31
    const int acol  = (tid & 7) * 4;
    const int brow0 = tid >> 5;        // 0..7
    const int bcol  = (tid & 31) * 4;

    long aBase[4];
    #pragma unroll
    for (int i = 0; i < 4; i++) {
        int am = bm + arow0 + 32 * i;
        if (GATHER) {
            int g = gidx[e * iEs + am];
            if (g < 0 || g >= Tc) g = 0;
            aBase[i] = (long)g * Kd;
        } else {
            aBase[i] = (long)am * Kd;
        }
    }

    wmma::fragment<wmma::accumulator, 16, 16, 8, float> cf[2][4];
    if (RESID) {
        #pragma unroll
        for (int i = 0; i < 2; i++)
            #pragma unroll
            for (int j = 0; j < 4; j++)
                wmma::load_matrix_sync(cf[i][j],
                    resid + (long)(bm + wm * 32 + i * 16) * N + bn + wn * 64 + j * 16,
                    N, wmma::mem_row_major);
    } else {
        #pragma unroll
        for (int i = 0; i < 2; i++)
            #pragma unroll
            for (int j = 0; j < 4; j++)
                wmma::fill_fragment(cf[i][j], 0.f);
    }

    // prefetch tile 0 into stage 0
    #pragma unroll
    for (int i = 0; i < 4; i++)
        cp_async16(&As[(arow0 + 32 * i) * AST + acol], A + aBase[i] + acol);
    #pragma unroll
    for (int i = 0; i < 4; i++)
        cp_async16(&Bs[(brow0 + 8 * i) * BST + bcol], Bw + (long)(brow0 + 8 * i) * N + bn + bcol);
    CP_COMMIT();

    const int T = Kd / BK;
    for (int t = 0; t < T; t++) {
        if (t + 1 < T) {
            int s = (t + 1) & 1;
            int k0 = (t + 1) * BK;
            #pragma unroll
            for (int i = 0; i < 4; i++)
                cp_async16(&As[s * SM_A + (arow0 + 32 * i) * AST + acol],
                           A + aBase[i] + k0 + acol);
            #pragma unroll
            for (int i = 0; i < 4; i++)
                cp_async16(&Bs[s * SM_B + (brow0 + 8 * i) * BST + bcol],
                           Bw + (long)(k0 + brow0 + 8 * i) * N + bn + bcol);
            CP_COMMIT();
            CP_WAIT1();
        } else {
            CP_WAIT0();
        }
        __syncthreads();

        int s = t & 1;
        #pragma unroll
        for (int kk = 0; kk < BK / 8; kk++) {
            wmma::fragment<wmma::matrix_a, 16, 16, 8, wmma::precision::tf32, wmma::row_major> af[2];
            wmma::fragment<wmma::matrix_b, 16, 16, 8, wmma::precision::tf32, wmma::row_major> bf[4];
            #pragma unroll
            for (int i = 0; i < 2; i++)
                wmma::load_matrix_sync(af[i], &As[s * SM_A + (wm * 32 + i * 16) * AST + kk * 8], AST);
            #pragma unroll
            for (int j = 0; j < 4; j++)
                wmma::load_matrix_sync(bf[j], &Bs[s * SM_B + (kk * 8) * BST + wn * 64 + j * 16], BST);
            #pragma unroll
            for (int i = 0; i < 2; i++)
                #pragma unroll
                for (int j = 0; j < 4; j++)
                    wmma::mma_sync(cf[i][j], af[i], bf[j], cf[i][j]);
        }
        __syncthreads();
    }

    #pragma unroll
    for (int i = 0; i < 2; i++)
        #pragma unroll
        for (int j = 0; j < 4; j++)
            wmma::store_matrix_sync(
                C + (long)(bm + wm * 32 + i * 16) * N + bn + wn * 64 + j * 16,
                cf[i][j], N, wmma::mem_row_major);
}

// ---------------- causal flash attention (fp32) ----------------
__global__ void attn_kernel(const float* __restrict__ q, const float* __restrict__ kv,
                            float* __restrict__ o) {
    const int b = blockIdx.z, h = blockIdx.y;
    const int q0 = blockIdx.x * 128;
    const int tid = threadIdx.x;
    const int ql = q0 + tid;

    __shared__ float Ks[64][64];
    __shared__ float Vs[64][64];

    float qreg[64];
    const long qbase = ((long)(b * Lc + ql)) * (Hc * HDc) + h * HDc;
    #pragma unroll
    for (int d = 0; d < 64; d += 4) {
        float4 v = *(const float4*)(q + qbase + d);
        qreg[d] = v.x; qreg[d + 1] = v.y; qreg[d + 2] = v.z; qreg[d + 3] = v.w;
    }
    float acc[64];
    #pragma unroll
    for (int d = 0; d < 64; d++) acc[d] = 0.f;
    float mi = -INFINITY, li = 0.f;

    const int kend = q0 + 127;
    for (int kt = 0; kt <= kend; kt += 64) {
        int j = tid >> 1, d0 = (tid & 1) * 32;
        long kvbase = ((long)(b * Lc + kt + j)) * (2 * Hc * HDc) + h * HDc;
        #pragma unroll
        for (int dd = 0; dd < 32; dd += 4) {
            *(float4*)&Ks[j][d0 + dd] = *(const float4*)(kv + kvbase + d0 + dd);
            *(float4*)&Vs[j][d0 + dd] = *(const float4*)(kv + kvbase + Hc * HDc + d0 + dd);
        }
        __syncthreads();

        int jmax = ql - kt + 1;
        if (jmax > 64) jmax = 64;
        for (int jj = 0; jj < jmax; jj++) {
            float s0 = 0.f, s1 = 0.f, s2 = 0.f, s3 = 0.f;
            #pragma unroll
            for (int d = 0; d < 64; d += 4) {
                float4 k4 = *(const float4*)&Ks[jj][d];
                s0 += qreg[d] * k4.x;
                s1 += qreg[d + 1] * k4.y;
                s2 += qreg[d + 2] * k4.z;
                s3 += qreg[d + 3] * k4.w;
            }
            float s = 0.125f * ((s0 + s1) + (s2 + s3));
            if (s <= mi) {
                float p = __expf(s - mi);
                li += p;
                #pragma unroll
                for (int d = 0; d < 64; d += 4) {
                    float4 v4 = *(const float4*)&Vs[jj][d];
                    acc[d] += p * v4.x; acc[d + 1] += p * v4.y;
                    acc[d + 2] += p * v4.z; acc[d + 3] += p * v4.w;
                }
            } else {
                float corr = __expf(mi - s);
                mi = s;
                li = li * corr + 1.f;
                #pragma unroll
                for (int d = 0; d < 64; d += 4) {
                    float4 v4 = *(const float4*)&Vs[jj][d];
                    acc[d] = acc[d] * corr + v4.x; acc[d + 1] = acc[d + 1] * corr + v4.y;
                    acc[d + 2] = acc[d + 2] * corr + v4.z; acc[d + 3] = acc[d + 3] * corr + v4.w;
                }
            }
        }
        __syncthreads();
    }

    float inv = 1.f / li;
    #pragma unroll
    for (int d = 0; d < 64; d += 4) {
        float4 r = make_float4(acc[d] * inv, acc[d + 1] * inv, acc[d + 2] * inv, acc[d + 3] * inv);
        *(float4*)(o + qbase + d) = r;
    }
}

// ---------------- router ----------------
__global__ void router_kernel(const float* __restrict__ hn, const float* __restrict__ gw,
                              float* __restrict__ probs_out) {
    int warp = (blockIdx.x * blockDim.x + threadIdx.x) >> 5;
    int lane = threadIdx.x & 31;
    if (warp >= Tc) return;
    const float* row = hn + (long)warp * Dc;
    float acc[8] = {0, 0, 0, 0, 0, 0, 0, 0};
    for (int d = lane; d < Dc; d += 32) {
        float xv = row[d];
        const float* g = gw + d * 8;
        #pragma unroll
        for (int e = 0; e < 8; e++) acc[e] += xv * g[e];
    }
    #pragma unroll
    for (int e = 0; e < 8; e++)
        #pragma unroll
        for (int off = 16; off > 0; off >>= 1)
            acc[e] += __shfl_xor_sync(0xffffffffu, acc[e], off);

    if (lane == 0) {
        float mx = acc[0];
        #pragma unroll
        for (int e = 1; e < 8; e++) mx = fmaxf(mx, acc[e]);
        float p[8], s = 0.f;
        #pragma unroll
        for (int e = 0; e < 8; e++) { p[e] = expf(acc[e] - mx); s += p[e]; }
        float invs = 1.f / s;
        #pragma unroll
        for (int e = 0; e < 8; e++) { p[e] *= invs; probs_out[(long)warp * 8 + e] = p[e]; }
        int i1 = 0;
        #pragma unroll
        for (int e = 1; e < 8; e++) if (p[e] > p[i1]) i1 = e;
        int i2 = (i1 == 0) ? 1 : 0;
        #pragma unroll
        for (int e = 0; e < 8; e++) if (e != i1 && p[e] > p[i2]) i2 = e;
        float w1 = p[i1], w2 = p[i2];
        float inv2 = 1.f / (w1 + w2);
        w1 *= inv2; w2 *= inv2;
        int pos1 = atomicAdd(&g_cnt[i1], 1);
        g_idx[i1 * Tc + pos1] = warp;
        g_slot[warp * 2 + 0] = i1 * Tc + pos1;
        g_tw[warp * 2 + 0] = w1;
        int pos2 = atomicAdd(&g_cnt[i2], 1);
        g_idx[i2 * Tc + pos2] = warp;
        g_slot[warp * 2 + 1] = i2 * Tc + pos2;
        g_tw[warp * 2 + 1] = w2;
    }
}

// ---------------- final combine ----------------
__global__ void final_kernel(const float* __restrict__ h, const float* __restrict__ sh,
                             float* __restrict__ out) {
    long i4 = (long)blockIdx.x * blockDim.x + threadIdx.x;
    if (i4 >= (long)Tc * Dc / 4) return;
    int t = (int)(i4 / (Dc / 4));
    int d4 = (int)(i4 % (Dc / 4));
    int s0 = g_slot[t * 2 + 0], s1 = g_slot[t * 2 + 1];
    float w0 = g_tw[t * 2 + 0], w1 = g_tw[t * 2 + 1];
    float4 e0 = *(const float4*)(g_eo + (long)s0 * Dc + d4 * 4);
    float4 e1 = *(const float4*)(g_eo + (long)s1 * Dc + d4 * 4);
    float4 hv = ((const float4*)h)[i4];
    float4 sv = ((const float4*)sh)[i4];
    float4 r;
    r.x = hv.x + sv.x + w0 * e0.x + w1 * e1.x;
    r.y = hv.y + sv.y + w0 * e0.y + w1 * e1.y;
    r.z = hv.z + sv.z + w0 * e0.z + w1 * e1.z;
    r.w = hv.w + sv.w + w0 * e0.w + w1 * e1.w;
    ((float4*)out)[i4] = r;
}

// ---------------- launch ----------------
extern "C" void kernel_launch(void* const* d_in, const int* in_sizes, int n_in,
                              void* d_out, int out_size) {
    const float* x     = (const float*)d_in[0];
    const float* ln1_w = (const float*)d_in[1];
    const float* q_w   = (const float*)d_in[2];
    const float* kvd_w = (const float*)d_in[3];
    const float* kvn_w = (const float*)d_in[4];
    const float* kvu_w = (const float*)d_in[5];
    const float* o_w   = (const float*)d_in[6];
    const float* ln2_w = (const float*)d_in[7];
    const float* gate_w= (const float*)d_in[8];
    const float* sh_w1 = (const float*)d_in[9];
    const float* sh_w2 = (const float*)d_in[10];
    const float* sh_w3 = (const float*)d_in[11];
    const float* re_w1 = (const float*)d_in[12];
    const float* re_w2 = (const float*)d_in[13];
    const float* re_w3 = (const float*)d_in[14];

    float* outy = (float*)d_out;                 // [B,L,D]
    float* outp = outy + (long)Tc * Dc;          // [T,E]

    float *xn, *qb, *lat, *kvb, *attn, *hb, *hnb, *g1, *g3, *shb, *eh1, *eh3, *eo;
    cudaGetSymbolAddress((void**)&xn, g_xn);
    cudaGetSymbolAddress((void**)&qb, g_q);
    cudaGetSymbolAddress((void**)&lat, g_lat);
    cudaGetSymbolAddress((void**)&kvb, g_kv);
    cudaGetSymbolAddress((void**)&attn, g_attn);
    cudaGetSymbolAddress((void**)&hb, g_h);
    cudaGetSymbolAddress((void**)&hnb, g_hn);
    cudaGetSymbolAddress((void**)&g1, g_g1);
    cudaGetSymbolAddress((void**)&g3, g_g3);
    cudaGetSymbolAddress((void**)&shb, g_shared);
    cudaGetSymbolAddress((void**)&eh1, g_eh1);
    cudaGetSymbolAddress((void**)&eh3, g_eh3);
    cudaGetSymbolAddress((void**)&eo, g_eo);
    int* idxp; int* cntp;
    cudaGetSymbolAddress((void**)&idxp, g_idx);
    cudaGetSymbolAddress((void**)&cntp, g_cnt);

    // opt-in to 69KB dynamic smem for all gemm instantiations
    cudaFuncSetAttribute((const void*)gemm_tc<false, false, false>,
                         cudaFuncAttributeMaxDynamicSharedMemorySize, SMEM_BYTES);
    cudaFuncSetAttribute((const void*)gemm_tc<false, false, true>,
                         cudaFuncAttributeMaxDynamicSharedMemorySize, SMEM_BYTES);
    cudaFuncSetAttribute((const void*)gemm_tc<true, true, false>,
                         cudaFuncAttributeMaxDynamicSharedMemorySize, SMEM_BYTES);
    cudaFuncSetAttribute((const void*)gemm_tc<false, true, false>,
                         cudaFuncAttributeMaxDynamicSharedMemorySize, SMEM_BYTES);

    zero_cnt_k<<<1, 32>>>();

    rmsnorm_k<<<Tc, 256>>>(x, ln1_w, xn, Dc);
    gemm_tc<false, false, false><<<dim3(Hc * HDc / BN, Tc / BM, 1), 256, SMEM_BYTES>>>(
        xn, q_w, qb, nullptr, nullptr, nullptr, Tc, Hc * HDc, Dc, 0, 0, 0, 0);
    gemm_tc<false, false, false><<<dim3(Rc / BN, Tc / BM, 1), 256, SMEM_BYTES>>>(
        xn, kvd_w, lat, nullptr, nullptr, nullptr, Tc, Rc, Dc, 0, 0, 0, 0);
    rmsnorm_k<<<Tc, 256>>>(lat, kvn_w, lat, Rc);
    gemm_tc<false, false, false><<<dim3(2 * Hc * HDc / BN, Tc / BM, 1), 256, SMEM_BYTES>>>(
        lat, kvu_w, kvb, nullptr, nullptr, nullptr, Tc, 2 * Hc * HDc, Rc, 0, 0, 0, 0);
    attn_kernel<<<dim3(Lc / 128, Hc, Bc), 128>>>(qb, kvb, attn);
    gemm_tc<false, false, true><<<dim3(Dc / BN, Tc / BM, 1), 256, SMEM_BYTES>>>(
        attn, o_w, hb, x, nullptr, nullptr, Tc, Dc, Hc * HDc, 0, 0, 0, 0);

    rmsnorm_k<<<Tc, 256>>>(hb, ln2_w, hnb, Dc);
    gemm_tc<false, false, false><<<dim3(Fc / BN, Tc / BM, 1), 256, SMEM_BYTES>>>(
        hnb, sh_w1, g1, nullptr, nullptr, nullptr, Tc, Fc, Dc, 0, 0, 0, 0);
    gemm_tc<false, false, false><<<dim3(Fc / BN, Tc / BM, 1), 256, SMEM_BYTES>>>(
        hnb, sh_w3, g3, nullptr, nullptr, nullptr, Tc, Fc, Dc, 0, 0, 0, 0);
    silu_mul_k<<<(Tc * Fc / 4 + 255) / 256, 256>>>(g1, g3, g1, (long)Tc * Fc / 4);
    gemm_tc<false, false, false><<<dim3(Dc / BN, Tc / BM, 1), 256, SMEM_BYTES>>>(
        g1, sh_w2, shb, nullptr, nullptr, nullptr, Tc, Dc, Fc, 0, 0, 0, 0);

    router_kernel<<<Tc / 8, 256>>>(hnb, gate_w, outp);

    gemm_tc<true, true, false><<<dim3(Fc / BN, Tc / BM, Ec), 256, SMEM_BYTES>>>(
        hnb, re_w1, eh1, nullptr, idxp, cntp, Tc, Fc, Dc, 0, (long)Dc * Fc, (long)Tc * Fc, Tc);
    gemm_tc<true, true, false><<<dim3(Fc / BN, Tc / BM, Ec), 256, SMEM_BYTES>>>(
        hnb, re_w3, eh3, nullptr, idxp, cntp, Tc, Fc, Dc, 0, (long)Dc * Fc, (long)Tc * Fc, Tc);
    silu_mul_expert_k<<<dim3((Tc * Fc / 4 + 255) / 256, Ec), 256>>>();
    gemm_tc<false, true, false><<<dim3(Dc / BN, Tc / BM, Ec), 256, SMEM_BYTES>>>(
        eh1, re_w2, eo, nullptr, nullptr, cntp, Tc, Dc, Fc, (long)Tc * Fc, (long)Fc * Dc, (long)Tc * Dc, 0);

    final_kernel<<<(Tc * Dc / 4 + 255) / 256, 256>>>(hb, shb, outy);
}

// round 6
// speedup vs baseline: 1.5148x; 1.0296x over previous
#include <cuda_runtime.h>
#include <mma.h>
#include <math.h>

using namespace nvcuda;

#define Bc 2
#define Lc 2048
#define Dc 1024
#define Hc 16
#define HDc 64
#define Rc 256
#define Ec 8
#define Kc 2
#define Fc 1024
#define Tc (Bc*Lc)   // 4096

// ---------------- scratch ----------------
__device__ float g_xn[Tc*Dc];
__device__ float g_qlat[Tc*1280];                 // [q(1024) | lat_pre(256)]
__device__ float g_lat[Tc*Rc];
__device__ float g_kv[Tc*2*Hc*HDc];
__device__ float g_attn[Tc*Hc*HDc];
__device__ float g_h[Tc*Dc];
__device__ float g_hn[Tc*Dc];
__device__ float g_g13[Tc*2048];
__device__ float g_act[Tc*Fc];
__device__ float g_shared[Tc*Dc];
__device__ float g_wqkv[Dc*1280];
__device__ float g_w13[Dc*2048];
__device__ float g_rw13[(long)Ec*Dc*2048];
__device__ float g_eh13[(long)Ec*Tc*2048];
__device__ float g_ehact[(long)Ec*Tc*Fc];
__device__ float g_eo[(long)Ec*Tc*Dc];
__device__ int   g_cnt[Ec];
__device__ int   g_idx[Ec*Tc];
__device__ int   g_slot[Tc*Kc];
__device__ float g_tw[Tc*Kc];

// ---------------- small kernels ----------------
__global__ void zero_cnt_k() {
    if (threadIdx.x < Ec) g_cnt[threadIdx.x] = 0;
}

// strided float4 copy: src[rows][cols] -> dst rows with stride dstStride, column offset dstOff
__global__ void copy_strided_k(const float* __restrict__ src, float* __restrict__ dst,
                               long rows, int cols, int dstStride, int dstOff) {
    long i4 = (long)blockIdx.x * blockDim.x + threadIdx.x;
    long n4 = rows * (cols / 4);
    if (i4 >= n4) return;
    long r = i4 / (cols / 4);
    int c4 = (int)(i4 % (cols / 4));
    ((float4*)dst)[r * (dstStride / 4) + dstOff / 4 + c4] = ((const float4*)src)[i4];
}

__global__ void rmsnorm_k(const float* __restrict__ x, const float* __restrict__ w,
                          float* __restrict__ o, int dim, int xs, int os) {
    int row = blockIdx.x;
    int tid = threadIdx.x;
    const float* xr = x + (long)row * xs;
    float s = 0.f;
    for (int d = tid; d < dim; d += blockDim.x) { float v = xr[d]; s += v * v; }
    __shared__ float red[256];
    red[tid] = s;
    __syncthreads();
    for (int off = 128; off > 0; off >>= 1) {
        if (tid < off) red[tid] += red[tid + off];
        __syncthreads();
    }
    float inv = rsqrtf(red[0] / (float)dim + 1e-6f);
    float* orow = o + (long)row * os;
    for (int d = tid; d < dim; d += blockDim.x) orow[d] = w[d] * xr[d] * inv;
}

// shared expert silu: in g_g13 [T][2048] -> g_act [T][1024]
__global__ void silu_pack_k() {
    long i4 = (long)blockIdx.x * blockDim.x + threadIdx.x;
    if (i4 >= (long)Tc * Fc / 4) return;
    long t = i4 >> 8;          // Fc/4 = 256
    int f4 = (int)(i4 & 255);
    float4 av = ((const float4*)g_g13)[t * 512 + f4];
    float4 bv = ((const float4*)g_g13)[t * 512 + 256 + f4];
    float4 r;
    r.x = av.x / (1.f + expf(-av.x)) * bv.x;
    r.y = av.y / (1.f + expf(-av.y)) * bv.y;
    r.z = av.z / (1.f + expf(-av.z)) * bv.z;
    r.w = av.w / (1.f + expf(-av.w)) * bv.w;
    ((float4*)g_act)[t * 256 + f4] = r;
}

// routed experts silu: g_eh13 [e][T][2048] -> g_ehact [e][T][1024], rows < cnt only
__global__ void silu_expert_k() {
    int e = blockIdx.y;
    int cnt = g_cnt[e];
    long i4 = (long)blockIdx.x * blockDim.x + threadIdx.x;
    if (i4 >= (long)Tc * Fc / 4) return;
    int row = (int)(i4 >> 8);
    if (row >= cnt) return;
    int f4 = (int)(i4 & 255);
    long ibase = (long)e * Tc * 512;
    float4 av = ((const float4*)g_eh13)[ibase + (long)row * 512 + f4];
    float4 bv = ((const float4*)g_eh13)[ibase + (long)row * 512 + 256 + f4];
    float4 r;
    r.x = av.x / (1.f + expf(-av.x)) * bv.x;
    r.y = av.y / (1.f + expf(-av.y)) * bv.y;
    r.z = av.z / (1.f + expf(-av.z)) * bv.z;
    r.w = av.w / (1.f + expf(-av.w)) * bv.w;
    ((float4*)g_ehact)[(long)e * Tc * 256 + (long)row * 256 + f4] = r;
}

// ---------------- tf32 tensor-core GEMM: 128x256 block, 64x64 warp tiles, 3-stage cp.async ----------------
#define BM 128
#define BN 256
#define BK 32
#define AST 36                 // A stage row stride (floats)
#define BST 260                // B stage row stride
#define SM_A (BM*AST)          // 4608
#define SM_B (BK*BST)          // 8320
#define STAGE_F (SM_A+SM_B)    // 12928 floats
#define NSTAGE 3
#define SMEM_BYTES (NSTAGE*STAGE_F*4)   // 155136

__device__ __forceinline__ void cp_async16(float* sdst, const float* gsrc) {
    unsigned s = (unsigned)__cvta_generic_to_shared(sdst);
    asm volatile("cp.async.cg.shared.global [%0], [%1], 16;" :: "r"(s), "l"(gsrc));
}
#define CP_COMMIT() asm volatile("cp.async.commit_group;")
#define CP_WAIT2()  asm volatile("cp.async.wait_group 2;")

template<bool GATHER, bool HAS_CNT, bool RESID>
__global__ void __launch_bounds__(256)
gemm_tc(const float* __restrict__ A, const float* __restrict__ Bw,
        float* __restrict__ C, const float* __restrict__ resid,
        const int* __restrict__ gidx, const int* __restrict__ cntp,
        int M, int N, int Kd,
        long aEs, long bEs, long cEs, int iEs) {
    extern __shared__ float sm[];

    int e = blockIdx.z;
    A += (long)e * aEs;
    Bw += (long)e * bEs;
    C += (long)e * cEs;
    int Me = HAS_CNT ? cntp[e] : M;
    int bm = blockIdx.y * BM, bn = blockIdx.x * BN;
    if (bm >= Me) return;

    const int tid = threadIdx.x;
    const int warpId = tid >> 5;
    const int wm = warpId >> 2;        // 0..1 -> rows wm*64
    const int wn = warpId & 3;         // 0..3 -> cols wn*64

    const int arow0 = tid >> 3;        // 0..31
    const int acol  = (tid & 7) * 4;
    const int brow0 = tid >> 6;        // 0..3
    const int bcol  = (tid & 63) * 4;

    long aBase[4];
    #pragma unroll
    for (int i = 0; i < 4; i++) {
        int am = bm + arow0 + 32 * i;
        if (GATHER) {
            int g = gidx[e * iEs + am];
            if (g < 0 || g >= Tc) g = 0;
            aBase[i] = (long)g * Kd;
        } else {
            aBase[i] = (long)am * Kd;
        }
    }

    wmma::fragment<wmma::accumulator, 16, 16, 8, float> cf[4][4];
    if (RESID) {
        #pragma unroll
        for (int i = 0; i < 4; i++)
            #pragma unroll
            for (int j = 0; j < 4; j++)
                wmma::load_matrix_sync(cf[i][j],
                    resid + (long)(bm + wm * 64 + i * 16) * N + bn + wn * 64 + j * 16,
                    N, wmma::mem_row_major);
    } else {
        #pragma unroll
        for (int i = 0; i < 4; i++)
            #pragma unroll
            for (int j = 0; j < 4; j++)
                wmma::fill_fragment(cf[i][j], 0.f);
    }

    const int T = Kd / BK;

    // tile loader
    auto load_tile = [&](int t, int s) {
        float* As_ = sm + s * STAGE_F;
        float* Bs_ = sm + s * STAGE_F + SM_A;
        int k0 = t * BK;
        #pragma unroll
        for (int i = 0; i < 4; i++)
            cp_async16(&As_[(arow0 + 32 * i) * AST + acol], A + aBase[i] + k0 + acol);
        #pragma unroll
        for (int i = 0; i < 8; i++)
            cp_async16(&Bs_[(brow0 + 4 * i) * BST + bcol], Bw + (long)(k0 + brow0 + 4 * i) * N + bn + bcol);
    };

    load_tile(0, 0);
    CP_COMMIT();
    if (T > 1) load_tile(1, 1);
    CP_COMMIT();

    for (int t = 0; t < T; t++) {
        if (t + 2 < T) load_tile(t + 2, (t + 2) % NSTAGE);
        CP_COMMIT();
        CP_WAIT2();
        __syncthreads();

        int s = t % NSTAGE;
        const float* As_ = sm + s * STAGE_F;
        const float* Bs_ = sm + s * STAGE_F + SM_A;
        #pragma unroll
        for (int kk = 0; kk < BK / 8; kk++) {
            wmma::fragment<wmma::matrix_a, 16, 16, 8, wmma::precision::tf32, wmma::row_major> af[4];
            wmma::fragment<wmma::matrix_b, 16, 16, 8, wmma::precision::tf32, wmma::row_major> bf[4];
            #pragma unroll
            for (int i = 0; i < 4; i++)
                wmma::load_matrix_sync(af[i], &As_[(wm * 64 + i * 16) * AST + kk * 8], AST);
            #pragma unroll
            for (int j = 0; j < 4; j++)
                wmma::load_matrix_sync(bf[j], &Bs_[(kk * 8) * BST + wn * 64 + j * 16], BST);
            #pragma unroll
            for (int i = 0; i < 4; i++)
                #pragma unroll
                for (int j = 0; j < 4; j++)
                    wmma::mma_sync(cf[i][j], af[i], bf[j], cf[i][j]);
        }
        __syncthreads();
    }

    #pragma unroll
    for (int i = 0; i < 4; i++)
        #pragma unroll
        for (int j = 0; j < 4; j++)
            wmma::store_matrix_sync(
                C + (long)(bm + wm * 64 + i * 16) * N + bn + wn * 64 + j * 16,
                cf[i][j], N, wmma::mem_row_major);
}

// ---------------- causal flash attention (fp32), q strided ----------------
__global__ void attn_kernel(const float* __restrict__ q, const float* __restrict__ kv,
                            float* __restrict__ o) {
    const int b = blockIdx.z, h = blockIdx.y;
    const int q0 = blockIdx.x * 128;
    const int tid = threadIdx.x;
    const int ql = q0 + tid;

    __shared__ float Ks[64][64];
    __shared__ float Vs[64][64];

    float qreg[64];
    const long qbase = ((long)(b * Lc + ql)) * 1280 + h * HDc;   // packed qlat stride
    const long obase = ((long)(b * Lc + ql)) * (Hc * HDc) + h * HDc;
    #pragma unroll
    for (int d = 0; d < 64; d += 4) {
        float4 v = *(const float4*)(q + qbase + d);
        qreg[d] = v.x; qreg[d + 1] = v.y; qreg[d + 2] = v.z; qreg[d + 3] = v.w;
    }
    float acc[64];
    #pragma unroll
    for (int d = 0; d < 64; d++) acc[d] = 0.f;
    float mi = -INFINITY, li = 0.f;

    const int kend = q0 + 127;
    for (int kt = 0; kt <= kend; kt += 64) {
        int j = tid >> 1, d0 = (tid & 1) * 32;
        long kvbase = ((long)(b * Lc + kt + j)) * (2 * Hc * HDc) + h * HDc;
        #pragma unroll
        for (int dd = 0; dd < 32; dd += 4) {
            *(float4*)&Ks[j][d0 + dd] = *(const float4*)(kv + kvbase + d0 + dd);
            *(float4*)&Vs[j][d0 + dd] = *(const float4*)(kv + kvbase + Hc * HDc + d0 + dd);
        }
        __syncthreads();

        int jmax = ql - kt + 1;
        if (jmax > 64) jmax = 64;
        for (int jj = 0; jj < jmax; jj++) {
            float s0 = 0.f, s1 = 0.f, s2 = 0.f, s3 = 0.f;
            #pragma unroll
            for (int d = 0; d < 64; d += 4) {
                float4 k4 = *(const float4*)&Ks[jj][d];
                s0 += qreg[d] * k4.x;
                s1 += qreg[d + 1] * k4.y;
                s2 += qreg[d + 2] * k4.z;
                s3 += qreg[d + 3] * k4.w;
            }
            float s = 0.125f * ((s0 + s1) + (s2 + s3));
            if (s <= mi) {
                float p = __expf(s - mi);
                li += p;
                #pragma unroll
                for (int d = 0; d < 64; d += 4) {
                    float4 v4 = *(const float4*)&Vs[jj][d];
                    acc[d] += p * v4.x; acc[d + 1] += p * v4.y;
                    acc[d + 2] += p * v4.z; acc[d + 3] += p * v4.w;
                }
            } else {
                float corr = __expf(mi - s);
                mi = s;
                li = li * corr + 1.f;
                #pragma unroll
                for (int d = 0; d < 64; d += 4) {
                    float4 v4 = *(const float4*)&Vs[jj][d];
                    acc[d] = acc[d] * corr + v4.x; acc[d + 1] = acc[d + 1] * corr + v4.y;
                    acc[d + 2] = acc[d + 2] * corr + v4.z; acc[d + 3] = acc[d + 3] * corr + v4.w;
                }
            }
        }
        __syncthreads();
    }

    float inv = 1.f / li;
    #pragma unroll
    for (int d = 0; d < 64; d += 4) {
        float4 r = make_float4(acc[d] * inv, acc[d + 1] * inv, acc[d + 2] * inv, acc[d + 3] * inv);
        *(float4*)(o + obase + d) = r;
    }
}

// ---------------- router ----------------
__global__ void router_kernel(const float* __restrict__ hn, const float* __restrict__ gw,
                              float* __restrict__ probs_out) {
    int warp = (blockIdx.x * blockDim.x + threadIdx.x) >> 5;
    int lane = threadIdx.x & 31;
    if (warp >= Tc) return;
    const float* row = hn + (long)warp * Dc;
    float acc[8] = {0, 0, 0, 0, 0, 0, 0, 0};
    for (int d = lane; d < Dc; d += 32) {
        float xv = row[d];
        const float* g = gw + d * 8;
        #pragma unroll
        for (int e = 0; e < 8; e++) acc[e] += xv * g[e];
    }
    #pragma unroll
    for (int e = 0; e < 8; e++)
        #pragma unroll
        for (int off = 16; off > 0; off >>= 1)
            acc[e] += __shfl_xor_sync(0xffffffffu, acc[e], off);

    if (lane == 0) {
        float mx = acc[0];
        #pragma unroll
        for (int e = 1; e < 8; e++) mx = fmaxf(mx, acc[e]);
        float p[8], s = 0.f;
        #pragma unroll
        for (int e = 0; e < 8; e++) { p[e] = expf(acc[e] - mx); s += p[e]; }
        float invs = 1.f / s;
        #pragma unroll
        for (int e = 0; e < 8; e++) { p[e] *= invs; probs_out[(long)warp * 8 + e] = p[e]; }
        int i1 = 0;
        #pragma unroll
        for (int e = 1; e < 8; e++) if (p[e] > p[i1]) i1 = e;
        int i2 = (i1 == 0) ? 1 : 0;
        #pragma unroll
        for (int e = 0; e < 8; e++) if (e != i1 && p[e] > p[i2]) i2 = e;
        float w1 = p[i1], w2 = p[i2];
        float inv2 = 1.f / (w1 + w2);
        w1 *= inv2; w2 *= inv2;
        int pos1 = atomicAdd(&g_cnt[i1], 1);
        g_idx[i1 * Tc + pos1] = warp;
        g_slot[warp * 2 + 0] = i1 * Tc + pos1;
        g_tw[warp * 2 + 0] = w1;
        int pos2 = atomicAdd(&g_cnt[i2], 1);
        g_idx[i2 * Tc + pos2] = warp;
        g_slot[warp * 2 + 1] = i2 * Tc + pos2;
        g_tw[warp * 2 + 1] = w2;
    }
}

// ---------------- final combine ----------------
__global__ void final_kernel(const float* __restrict__ h, const float* __restrict__ sh,
                             float* __restrict__ out) {
    long i4 = (long)blockIdx.x * blockDim.x + threadIdx.x;
    if (i4 >= (long)Tc * Dc / 4) return;
    int t = (int)(i4 / (Dc / 4));
    int d4 = (int)(i4 % (Dc / 4));
    int s0 = g_slot[t * 2 + 0], s1 = g_slot[t * 2 + 1];
    float w0 = g_tw[t * 2 + 0], w1 = g_tw[t * 2 + 1];
    float4 e0 = *(const float4*)(g_eo + (long)s0 * Dc + d4 * 4);
    float4 e1 = *(const float4*)(g_eo + (long)s1 * Dc + d4 * 4);
    float4 hv = ((const float4*)h)[i4];
    float4 sv = ((const float4*)sh)[i4];
    float4 r;
    r.x = hv.x + sv.x + w0 * e0.x + w1 * e1.x;
    r.y = hv.y + sv.y + w0 * e0.y + w1 * e1.y;
    r.z = hv.z + sv.z + w0 * e0.z + w1 * e1.z;
    r.w = hv.w + sv.w + w0 * e0.w + w1 * e1.w;
    ((float4*)out)[i4] = r;
}

// ---------------- launch ----------------
extern "C" void kernel_launch(void* const* d_in, const int* in_sizes, int n_in,
                              void* d_out, int out_size) {
    const float* x     = (const float*)d_in[0];
    const float* ln1_w = (const float*)d_in[1];
    const float* q_w   = (const float*)d_in[2];
    const float* kvd_w = (const float*)d_in[3];
    const float* kvn_w = (const float*)d_in[4];
    const float* kvu_w = (const float*)d_in[5];
    const float* o_w   = (const float*)d_in[6];
    const float* ln2_w = (const float*)d_in[7];
    const float* gate_w= (const float*)d_in[8];
    const float* sh_w1 = (const float*)d_in[9];
    const float* sh_w2 = (const float*)d_in[10];
    const float* sh_w3 = (const float*)d_in[11];
    const float* re_w1 = (const float*)d_in[12];
    const float* re_w2 = (const float*)d_in[13];
    const float* re_w3 = (const float*)d_in[14];

    float* outy = (float*)d_out;                 // [B,L,D]
    float* outp = outy + (long)Tc * Dc;          // [T,E]

    float *xn, *qlat, *lat, *kvb, *attn, *hb, *hnb, *g13, *act, *shb;
    float *wqkv, *w13, *rw13, *eh13, *ehact, *eo;
    cudaGetSymbolAddress((void**)&xn, g_xn);
    cudaGetSymbolAddress((void**)&qlat, g_qlat);
    cudaGetSymbolAddress((void**)&lat, g_lat);
    cudaGetSymbolAddress((void**)&kvb, g_kv);
    cudaGetSymbolAddress((void**)&attn, g_attn);
    cudaGetSymbolAddress((void**)&hb, g_h);
    cudaGetSymbolAddress((void**)&hnb, g_hn);
    cudaGetSymbolAddress((void**)&g13, g_g13);
    cudaGetSymbolAddress((void**)&act, g_act);
    cudaGetSymbolAddress((void**)&shb, g_shared);
    cudaGetSymbolAddress((void**)&wqkv, g_wqkv);
    cudaGetSymbolAddress((void**)&w13, g_w13);
    cudaGetSymbolAddress((void**)&rw13, g_rw13);
    cudaGetSymbolAddress((void**)&eh13, g_eh13);
    cudaGetSymbolAddress((void**)&ehact, g_ehact);
    cudaGetSymbolAddress((void**)&eo, g_eo);
    int* idxp; int* cntp;
    cudaGetSymbolAddress((void**)&idxp, g_idx);
    cudaGetSymbolAddress((void**)&cntp, g_cnt);

    cudaFuncSetAttribute((const void*)gemm_tc<false, false, false>,
                         cudaFuncAttributeMaxDynamicSharedMemorySize, SMEM_BYTES);
    cudaFuncSetAttribute((const void*)gemm_tc<false, false, true>,
                         cudaFuncAttributeMaxDynamicSharedMemorySize, SMEM_BYTES);
    cudaFuncSetAttribute((const void*)gemm_tc<true, true, false>,
                         cudaFuncAttributeMaxDynamicSharedMemorySize, SMEM_BYTES);
    cudaFuncSetAttribute((const void*)gemm_tc<false, true, false>,
                         cudaFuncAttributeMaxDynamicSharedMemorySize, SMEM_BYTES);

    zero_cnt_k<<<1, 32>>>();

    // ---- weight packing ----
    {
        long n4;
        n4 = (long)Dc * Dc / 4;                       // q_w -> wqkv cols 0..1023
        copy_strided_k<<<(int)((n4 + 255) / 256), 256>>>(q_w, wqkv, Dc, Dc, 1280, 0);
        n4 = (long)Dc * Rc / 4;                       // kvd_w -> wqkv cols 1024..1279
        copy_strided_k<<<(int)((n4 + 255) / 256), 256>>>(kvd_w, wqkv, Dc, Rc, 1280, 1024);
        n4 = (long)Dc * Fc / 4;
        copy_strided_k<<<(int)((n4 + 255) / 256), 256>>>(sh_w1, w13, Dc, Fc, 2048, 0);
        copy_strided_k<<<(int)((n4 + 255) / 256), 256>>>(sh_w3, w13, Dc, Fc, 2048, 1024);
        n4 = (long)Ec * Dc * Fc / 4;
        copy_strided_k<<<(int)((n4 + 255) / 256), 256>>>(re_w1, rw13, (long)Ec * Dc, Fc, 2048, 0);
        copy_strided_k<<<(int)((n4 + 255) / 256), 256>>>(re_w3, rw13, (long)Ec * Dc, Fc, 2048, 1024);
    }

    // ---- attention path ----
    rmsnorm_k<<<Tc, 256>>>(x, ln1_w, xn, Dc, Dc, Dc);
    gemm_tc<false, false, false><<<dim3(1280 / BN, Tc / BM, 1), 256, SMEM_BYTES>>>(
        xn, wqkv, qlat, nullptr, nullptr, nullptr, Tc, 1280, Dc, 0, 0, 0, 0);
    rmsnorm_k<<<Tc, 256>>>(qlat + 1024, kvn_w, lat, Rc, 1280, Rc);
    gemm_tc<false, false, false><<<dim3(2048 / BN, Tc / BM, 1), 256, SMEM_BYTES>>>(
        lat, kvu_w, kvb, nullptr, nullptr, nullptr, Tc, 2048, Rc, 0, 0, 0, 0);
    attn_kernel<<<dim3(Lc / 128, Hc, Bc), 128>>>(qlat, kvb, attn);
    gemm_tc<false, false, true><<<dim3(Dc / BN, Tc / BM, 1), 256, SMEM_BYTES>>>(
        attn, o_w, hb, x, nullptr, nullptr, Tc, Dc, Hc * HDc, 0, 0, 0, 0);

    // ---- MoE path ----
    rmsnorm_k<<<Tc, 256>>>(hb, ln2_w, hnb, Dc, Dc, Dc);
    gemm_tc<false, false, false><<<dim3(2048 / BN, Tc / BM, 1), 256, SMEM_BYTES>>>(
        hnb, w13, g13, nullptr, nullptr, nullptr, Tc, 2048, Dc, 0, 0, 0, 0);
    silu_pack_k<<<(Tc * Fc / 4 + 255) / 256, 256>>>();
    gemm_tc<false, false, false><<<dim3(Dc / BN, Tc / BM, 1), 256, SMEM_BYTES>>>(
        act, sh_w2, shb, nullptr, nullptr, nullptr, Tc, Dc, Fc, 0, 0, 0, 0);

    router_kernel<<<Tc / 8, 256>>>(hnb, gate_w, outp);

    gemm_tc<true, true, false><<<dim3(2048 / BN, Tc / BM, Ec), 256, SMEM_BYTES>>>(
        hnb, rw13, eh13, nullptr, idxp, cntp, Tc, 2048, Dc, 0, (long)Dc * 2048, (long)Tc * 2048, Tc);
    silu_expert_k<<<dim3((Tc * Fc / 4 + 255) / 256, Ec), 256>>>();
    gemm_tc<false, true, false><<<dim3(Dc / BN, Tc / BM, Ec), 256, SMEM_BYTES>>>(
        ehact, re_w2, eo, nullptr, nullptr, cntp, Tc, Dc, Fc, (long)Tc * Fc, (long)Fc * Dc, (long)Tc * Dc, 0);

    final_kernel<<<(Tc * Dc / 4 + 255) / 256, 256>>>(hb, shb, outy);
}

// round 7
// speedup vs baseline: 1.7418x; 1.1499x over previous
#include <cuda_runtime.h>
#include <mma.h>
#include <math.h>

using namespace nvcuda;

#define Bc 2
#define Lc 2048
#define Dc 1024
#define Hc 16
#define HDc 64
#define Rc 256
#define Ec 8
#define Kc 2
#define Fc 1024
#define Tc (Bc*Lc)   // 4096

// ---------------- scratch ----------------
__device__ float g_xn[Tc*Dc];
__device__ float g_qlat[Tc*1280];                 // [q(1024) | lat_pre(256)]
__device__ float g_lat[Tc*Rc];
__device__ float g_kv[Tc*2*Hc*HDc];
__device__ float g_attn[Tc*Hc*HDc];
__device__ float g_h[Tc*Dc];
__device__ float g_hn[Tc*Dc];
__device__ float g_g13[Tc*2048];
__device__ float g_act[Tc*Fc];
__device__ float g_shared[Tc*Dc];
__device__ float g_wqkv[Dc*1280];
__device__ float g_w13[Dc*2048];
__device__ float g_rw13[(long)Ec*Dc*2048];
__device__ float g_eh13[(long)Ec*Tc*2048];
__device__ float g_ehact[(long)Ec*Tc*Fc];
__device__ float g_eo[(long)Ec*Tc*Dc];
__device__ int   g_cnt[Ec];
__device__ int   g_idx[Ec*Tc];
__device__ int   g_slot[Tc*Kc];
__device__ float g_tw[Tc*Kc];

// ---------------- small kernels ----------------
__global__ void zero_cnt_k() {
    if (threadIdx.x < Ec) g_cnt[threadIdx.x] = 0;
}

// fused weight packing: 6 segments selected by blockIdx.y
__global__ void pack_weights_k(const float* __restrict__ q_w, const float* __restrict__ kvd_w,
                               const float* __restrict__ sh_w1, const float* __restrict__ sh_w3,
                               const float* __restrict__ re_w1, const float* __restrict__ re_w3,
                               float* __restrict__ wqkv, float* __restrict__ w13,
                               float* __restrict__ rw13) {
    int seg = blockIdx.y;
    long i4 = (long)blockIdx.x * blockDim.x + threadIdx.x;
    const float* src; float* dst; long rows; int cols, stride, off;
    switch (seg) {
        case 0: src = q_w;   dst = wqkv; rows = Dc;           cols = Dc; stride = 1280; off = 0;    break;
        case 1: src = kvd_w; dst = wqkv; rows = Dc;           cols = Rc; stride = 1280; off = 1024; break;
        case 2: src = sh_w1; dst = w13;  rows = Dc;           cols = Fc; stride = 2048; off = 0;    break;
        case 3: src = sh_w3; dst = w13;  rows = Dc;           cols = Fc; stride = 2048; off = 1024; break;
        case 4: src = re_w1; dst = rw13; rows = (long)Ec*Dc;  cols = Fc; stride = 2048; off = 0;    break;
        default:src = re_w3; dst = rw13; rows = (long)Ec*Dc;  cols = Fc; stride = 2048; off = 1024; break;
    }
    long n4 = rows * (cols / 4);
    if (i4 >= n4) return;
    long r = i4 / (cols / 4);
    int c4 = (int)(i4 % (cols / 4));
    ((float4*)dst)[r * (stride / 4) + off / 4 + c4] = ((const float4*)src)[i4];
}

__global__ void rmsnorm_k(const float* __restrict__ x, const float* __restrict__ w,
                          float* __restrict__ o, int dim, int xs, int os) {
    int row = blockIdx.x;
    int tid = threadIdx.x;
    const float* xr = x + (long)row * xs;
    float s = 0.f;
    for (int d = tid; d < dim; d += blockDim.x) { float v = xr[d]; s += v * v; }
    __shared__ float red[256];
    red[tid] = s;
    __syncthreads();
    for (int off = 128; off > 0; off >>= 1) {
        if (tid < off) red[tid] += red[tid + off];
        __syncthreads();
    }
    float inv = rsqrtf(red[0] / (float)dim + 1e-6f);
    float* orow = o + (long)row * os;
    for (int d = tid; d < dim; d += blockDim.x) orow[d] = w[d] * xr[d] * inv;
}

__global__ void silu_pack_k() {
    long i4 = (long)blockIdx.x * blockDim.x + threadIdx.x;
    if (i4 >= (long)Tc * Fc / 4) return;
    long t = i4 >> 8;
    int f4 = (int)(i4 & 255);
    float4 av = ((const float4*)g_g13)[t * 512 + f4];
    float4 bv = ((const float4*)g_g13)[t * 512 + 256 + f4];
    float4 r;
    r.x = av.x / (1.f + expf(-av.x)) * bv.x;
    r.y = av.y / (1.f + expf(-av.y)) * bv.y;
    r.z = av.z / (1.f + expf(-av.z)) * bv.z;
    r.w = av.w / (1.f + expf(-av.w)) * bv.w;
    ((float4*)g_act)[t * 256 + f4] = r;
}

__global__ void silu_expert_k() {
    int e = blockIdx.y;
    int cnt = g_cnt[e];
    long i4 = (long)blockIdx.x * blockDim.x + threadIdx.x;
    if (i4 >= (long)Tc * Fc / 4) return;
    int row = (int)(i4 >> 8);
    if (row >= cnt) return;
    int f4 = (int)(i4 & 255);
    long ibase = (long)e * Tc * 512;
    float4 av = ((const float4*)g_eh13)[ibase + (long)row * 512 + f4];
    float4 bv = ((const float4*)g_eh13)[ibase + (long)row * 512 + 256 + f4];
    float4 r;
    r.x = av.x / (1.f + expf(-av.x)) * bv.x;
    r.y = av.y / (1.f + expf(-av.y)) * bv.y;
    r.z = av.z / (1.f + expf(-av.z)) * bv.z;
    r.w = av.w / (1.f + expf(-av.w)) * bv.w;
    ((float4*)g_ehact)[(long)e * Tc * 256 + (long)row * 256 + f4] = r;
}

// ---------------- tf32 tensor-core GEMM (unchanged from R6) ----------------
#define BM 128
#define BN 256
#define BK 32
#define AST 36
#define BST 260
#define SM_A (BM*AST)
#define SM_B (BK*BST)
#define STAGE_F (SM_A+SM_B)
#define NSTAGE 3
#define SMEM_BYTES (NSTAGE*STAGE_F*4)

__device__ __forceinline__ void cp_async16(float* sdst, const float* gsrc) {
    unsigned s = (unsigned)__cvta_generic_to_shared(sdst);
    asm volatile("cp.async.cg.shared.global [%0], [%1], 16;" :: "r"(s), "l"(gsrc));
}
#define CP_COMMIT() asm volatile("cp.async.commit_group;")
#define CP_WAIT2()  asm volatile("cp.async.wait_group 2;")

template<bool GATHER, bool HAS_CNT, bool RESID>
__global__ void __launch_bounds__(256)
gemm_tc(const float* __restrict__ A, const float* __restrict__ Bw,
        float* __restrict__ C, const float* __restrict__ resid,
        const int* __restrict__ gidx, const int* __restrict__ cntp,
        int M, int N, int Kd,
        long aEs, long bEs, long cEs, int iEs) {
    extern __shared__ float sm[];

    int e = blockIdx.z;
    A += (long)e * aEs;
    Bw += (long)e * bEs;
    C += (long)e * cEs;
    int Me = HAS_CNT ? cntp[e] : M;
    int bm = blockIdx.y * BM, bn = blockIdx.x * BN;
    if (bm >= Me) return;

    const int tid = threadIdx.x;
    const int warpId = tid >> 5;
    const int wm = warpId >> 2;
    const int wn = warpId & 3;

    const int arow0 = tid >> 3;
    const int acol  = (tid & 7) * 4;
    const int brow0 = tid >> 6;
    const int bcol  = (tid & 63) * 4;

    long aBase[4];
    #pragma unroll
    for (int i = 0; i < 4; i++) {
        int am = bm + arow0 + 32 * i;
        if (GATHER) {
            int g = gidx[e * iEs + am];
            if (g < 0 || g >= Tc) g = 0;
            aBase[i] = (long)g * Kd;
        } else {
            aBase[i] = (long)am * Kd;
        }
    }

    wmma::fragment<wmma::accumulator, 16, 16, 8, float> cf[4][4];
    if (RESID) {
        #pragma unroll
        for (int i = 0; i < 4; i++)
            #pragma unroll
            for (int j = 0; j < 4; j++)
                wmma::load_matrix_sync(cf[i][j],
                    resid + (long)(bm + wm * 64 + i * 16) * N + bn + wn * 64 + j * 16,
                    N, wmma::mem_row_major);
    } else {
        #pragma unroll
        for (int i = 0; i < 4; i++)
            #pragma unroll
            for (int j = 0; j < 4; j++)
                wmma::fill_fragment(cf[i][j], 0.f);
    }

    const int T = Kd / BK;

    auto load_tile = [&](int t, int s) {
        float* As_ = sm + s * STAGE_F;
        float* Bs_ = sm + s * STAGE_F + SM_A;
        int k0 = t * BK;
        #pragma unroll
        for (int i = 0; i < 4; i++)
            cp_async16(&As_[(arow0 + 32 * i) * AST + acol], A + aBase[i] + k0 + acol);
        #pragma unroll
        for (int i = 0; i < 8; i++)
            cp_async16(&Bs_[(brow0 + 4 * i) * BST + bcol], Bw + (long)(k0 + brow0 + 4 * i) * N + bn + bcol);
    };

    load_tile(0, 0);
    CP_COMMIT();
    if (T > 1) load_tile(1, 1);
    CP_COMMIT();

    for (int t = 0; t < T; t++) {
        if (t + 2 < T) load_tile(t + 2, (t + 2) % NSTAGE);
        CP_COMMIT();
        CP_WAIT2();
        __syncthreads();

        int s = t % NSTAGE;
        const float* As_ = sm + s * STAGE_F;
        const float* Bs_ = sm + s * STAGE_F + SM_A;
        #pragma unroll
        for (int kk = 0; kk < BK / 8; kk++) {
            wmma::fragment<wmma::matrix_a, 16, 16, 8, wmma::precision::tf32, wmma::row_major> af[4];
            wmma::fragment<wmma::matrix_b, 16, 16, 8, wmma::precision::tf32, wmma::row_major> bf[4];
            #pragma unroll
            for (int i = 0; i < 4; i++)
                wmma::load_matrix_sync(af[i], &As_[(wm * 64 + i * 16) * AST + kk * 8], AST);
            #pragma unroll
            for (int j = 0; j < 4; j++)
                wmma::load_matrix_sync(bf[j], &Bs_[(kk * 8) * BST + wn * 64 + j * 16], BST);
            #pragma unroll
            for (int i = 0; i < 4; i++)
                #pragma unroll
                for (int j = 0; j < 4; j++)
                    wmma::mma_sync(cf[i][j], af[i], bf[j], cf[i][j]);
        }
        __syncthreads();
    }

    #pragma unroll
    for (int i = 0; i < 4; i++)
        #pragma unroll
        for (int j = 0; j < 4; j++)
            wmma::store_matrix_sync(
                C + (long)(bm + wm * 64 + i * 16) * N + bn + wn * 64 + j * 16,
                cf[i][j], N, wmma::mem_row_major);
}

// ---------------- tensor-core causal flash attention ----------------
// block: 128 threads (4 warps), 64 queries, one (b,h). K-tiles of 64.
// S = Q@K^T via tf32 wmma; online softmax in smem; O += P@V via wmma with
// accumulator held in smem (rescaled per tile).
#define ATSTR 72
#define ATT_SMEM ((5*64*ATSTR + 3*64)*4)   // 92928 B

__global__ void __launch_bounds__(128)
attn_tc_kernel(const float* __restrict__ q, const float* __restrict__ kv,
               float* __restrict__ o) {
    extern __shared__ float smema[];
    float* Qs = smema;                  // 64 x 72
    float* Ks = Qs + 64 * ATSTR;
    float* Vs = Ks + 64 * ATSTR;
    float* Ss = Vs + 64 * ATSTR;
    float* Os = Ss + 64 * ATSTR;
    float* mrow = Os + 64 * ATSTR;      // 64
    float* lrow = mrow + 64;
    float* crow = lrow + 64;

    const int b = blockIdx.z, h = blockIdx.y, iq = blockIdx.x;
    const int q0 = iq * 64;
    const int tid = threadIdx.x;
    const int warpId = tid >> 5;

    // load Q (pre-scaled by 1/sqrt(HD)), zero O, init m/l
    {
        int j = tid >> 1, d0 = (tid & 1) * 32;
        long qb = ((long)(b * Lc + q0 + j)) * 1280 + h * HDc;
        #pragma unroll
        for (int dd = 0; dd < 32; dd += 4) {
            float4 v = *(const float4*)(q + qb + d0 + dd);
            Qs[j * ATSTR + d0 + dd + 0] = v.x * 0.125f;
            Qs[j * ATSTR + d0 + dd + 1] = v.y * 0.125f;
            Qs[j * ATSTR + d0 + dd + 2] = v.z * 0.125f;
            Qs[j * ATSTR + d0 + dd + 3] = v.w * 0.125f;
            Os[j * ATSTR + d0 + dd + 0] = 0.f;
            Os[j * ATSTR + d0 + dd + 1] = 0.f;
            Os[j * ATSTR + d0 + dd + 2] = 0.f;
            Os[j * ATSTR + d0 + dd + 3] = 0.f;
        }
        if (tid < 64) { mrow[tid] = -INFINITY; lrow[tid] = 0.f; }
    }
    __syncthreads();

    for (int kt = 0; kt <= q0; kt += 64) {
        // load K/V tile
        {
            int j = tid >> 1, d0 = (tid & 1) * 32;
            long kvb = ((long)(b * Lc + kt + j)) * (2 * Hc * HDc) + h * HDc;
            #pragma unroll
            for (int dd = 0; dd < 32; dd += 4) {
                *(float4*)&Ks[j * ATSTR + d0 + dd] = *(const float4*)(kv + kvb + d0 + dd);
                *(float4*)&Vs[j * ATSTR + d0 + dd] = *(const float4*)(kv + kvb + Hc * HDc + d0 + dd);
            }
        }
        __syncthreads();

        // S = Q @ K^T   (warp computes rows warpId*16..+16 x all 64 cols)
        {
            wmma::fragment<wmma::accumulator, 16, 16, 8, float> sf[4];
            #pragma unroll
            for (int n = 0; n < 4; n++) wmma::fill_fragment(sf[n], 0.f);
            #pragma unroll
            for (int kk = 0; kk < 8; kk++) {
                wmma::fragment<wmma::matrix_a, 16, 16, 8, wmma::precision::tf32, wmma::row_major> aq;
                wmma::load_matrix_sync(aq, &Qs[(warpId * 16) * ATSTR + kk * 8], ATSTR);
                #pragma unroll
                for (int n = 0; n < 4; n++) {
                    wmma::fragment<wmma::matrix_b, 16, 16, 8, wmma::precision::tf32, wmma::col_major> bk;
                    wmma::load_matrix_sync(bk, &Ks[(n * 16) * ATSTR + kk * 8], ATSTR);
                    wmma::mma_sync(sf[n], aq, bk, sf[n]);
                }
            }
            #pragma unroll
            for (int n = 0; n < 4; n++)
                wmma::store_matrix_sync(&Ss[(warpId * 16) * ATSTR + n * 16], sf[n], ATSTR, wmma::mem_row_major);
        }
        __syncthreads();

        // online softmax (one thread per row)
        if (tid < 64) {
            int r = tid;
            int vmax = (kt == q0) ? (r + 1) : 64;
            float mx = -INFINITY;
            for (int c = 0; c < vmax; c++) mx = fmaxf(mx, Ss[r * ATSTR + c]);
            float nm = fmaxf(mrow[r], mx);
            float corr = __expf(mrow[r] - nm);
            float sum = 0.f;
            for (int c = 0; c < vmax; c++) {
                float p = __expf(Ss[r * ATSTR + c] - nm);
                Ss[r * ATSTR + c] = p;
                sum += p;
            }
            for (int c = vmax; c < 64; c++) Ss[r * ATSTR + c] = 0.f;
            lrow[r] = lrow[r] * corr + sum;
            mrow[r] = nm;
            crow[r] = corr;
        }
        __syncthreads();

        // rescale O by corr
        {
            int r = tid >> 1, c0 = (tid & 1) * 32;
            float corr = crow[r];
            #pragma unroll
            for (int c = 0; c < 32; c++) Os[r * ATSTR + c0 + c] *= corr;
        }
        __syncthreads();

        // O += P @ V
        {
            wmma::fragment<wmma::accumulator, 16, 16, 8, float> of[4];
            #pragma unroll
            for (int n = 0; n < 4; n++)
                wmma::load_matrix_sync(of[n], &Os[(warpId * 16) * ATSTR + n * 16], ATSTR, wmma::mem_row_major);
            #pragma unroll
            for (int kk = 0; kk < 8; kk++) {
                wmma::fragment<wmma::matrix_a, 16, 16, 8, wmma::precision::tf32, wmma::row_major> ap;
                wmma::load_matrix_sync(ap, &Ss[(warpId * 16) * ATSTR + kk * 8], ATSTR);
                #pragma unroll
                for (int n = 0; n < 4; n++) {
                    wmma::fragment<wmma::matrix_b, 16, 16, 8, wmma::precision::tf32, wmma::row_major> bv;
                    wmma::load_matrix_sync(bv, &Vs[(kk * 8) * ATSTR + n * 16], ATSTR);
                    wmma::mma_sync(of[n], ap, bv, of[n]);
                }
            }
            #pragma unroll
            for (int n = 0; n < 4; n++)
                wmma::store_matrix_sync(&Os[(warpId * 16) * ATSTR + n * 16], of[n], ATSTR, wmma::mem_row_major);
        }
        __syncthreads();
    }

    // write out normalized O
    {
        int r = tid >> 1, c0 = (tid & 1) * 32;
        float inv = 1.f / lrow[r];
        long ob = ((long)(b * Lc + q0 + r)) * (Hc * HDc) + h * HDc + c0;
        #pragma unroll
        for (int c = 0; c < 32; c += 4) {
            float4 w;
            w.x = Os[r * ATSTR + c0 + c + 0] * inv;
            w.y = Os[r * ATSTR + c0 + c + 1] * inv;
            w.z = Os[r * ATSTR + c0 + c + 2] * inv;
            w.w = Os[r * ATSTR + c0 + c + 3] * inv;
            *(float4*)(o + ob + c) = w;
        }
    }
}

// ---------------- router ----------------
__global__ void router_kernel(const float* __restrict__ hn, const float* __restrict__ gw,
                              float* __restrict__ probs_out) {
    int warp = (blockIdx.x * blockDim.x + threadIdx.x) >> 5;
    int lane = threadIdx.x & 31;
    if (warp >= Tc) return;
    const float* row = hn + (long)warp * Dc;
    float acc[8] = {0, 0, 0, 0, 0, 0, 0, 0};
    for (int d = lane; d < Dc; d += 32) {
        float xv = row[d];
        const float* g = gw + d * 8;
        #pragma unroll
        for (int e = 0; e < 8; e++) acc[e] += xv * g[e];
    }
    #pragma unroll
    for (int e = 0; e < 8; e++)
        #pragma unroll
        for (int off = 16; off > 0; off >>= 1)
            acc[e] += __shfl_xor_sync(0xffffffffu, acc[e], off);

    if (lane == 0) {
        float mx = acc[0];
        #pragma unroll
        for (int e = 1; e < 8; e++) mx = fmaxf(mx, acc[e]);
        float p[8], s = 0.f;
        #pragma unroll
        for (int e = 0; e < 8; e++) { p[e] = expf(acc[e] - mx); s += p[e]; }
        float invs = 1.f / s;
        #pragma unroll
        for (int e = 0; e < 8; e++) { p[e] *= invs; probs_out[(long)warp * 8 + e] = p[e]; }
        int i1 = 0;
        #pragma unroll
        for (int e = 1; e < 8; e++) if (p[e] > p[i1]) i1 = e;
        int i2 = (i1 == 0) ? 1 : 0;
        #pragma unroll
        for (int e = 0; e < 8; e++) if (e != i1 && p[e] > p[i2]) i2 = e;
        float w1 = p[i1], w2 = p[i2];
        float inv2 = 1.f / (w1 + w2);
        w1 *= inv2; w2 *= inv2;
        int pos1 = atomicAdd(&g_cnt[i1], 1);
        g_idx[i1 * Tc + pos1] = warp;
        g_slot[warp * 2 + 0] = i1 * Tc + pos1;
        g_tw[warp * 2 + 0] = w1;
        int pos2 = atomicAdd(&g_cnt[i2], 1);
        g_idx[i2 * Tc + pos2] = warp;
        g_slot[warp * 2 + 1] = i2 * Tc + pos2;
        g_tw[warp * 2 + 1] = w2;
    }
}

// ---------------- final combine ----------------
__global__ void final_kernel(const float* __restrict__ h, const float* __restrict__ sh,
                             float* __restrict__ out) {
    long i4 = (long)blockIdx.x * blockDim.x + threadIdx.x;
    if (i4 >= (long)Tc * Dc / 4) return;
    int t = (int)(i4 / (Dc / 4));
    int d4 = (int)(i4 % (Dc / 4));
    int s0 = g_slot[t * 2 + 0], s1 = g_slot[t * 2 + 1];
    float w0 = g_tw[t * 2 + 0], w1 = g_tw[t * 2 + 1];
    float4 e0 = *(const float4*)(g_eo + (long)s0 * Dc + d4 * 4);
    float4 e1 = *(const float4*)(g_eo + (long)s1 * Dc + d4 * 4);
    float4 hv = ((const float4*)h)[i4];
    float4 sv = ((const float4*)sh)[i4];
    float4 r;
    r.x = hv.x + sv.x + w0 * e0.x + w1 * e1.x;
    r.y = hv.y + sv.y + w0 * e0.y + w1 * e1.y;
    r.z = hv.z + sv.z + w0 * e0.z + w1 * e1.z;
    r.w = hv.w + sv.w + w0 * e0.w + w1 * e1.w;
    ((float4*)out)[i4] = r;
}

// ---------------- launch ----------------
extern "C" void kernel_launch(void* const* d_in, const int* in_sizes, int n_in,
                              void* d_out, int out_size) {
    const float* x     = (const float*)d_in[0];
    const float* ln1_w = (const float*)d_in[1];
    const float* q_w   = (const float*)d_in[2];
    const float* kvd_w = (const float*)d_in[3];
    const float* kvn_w = (const float*)d_in[4];
    const float* kvu_w = (const float*)d_in[5];
    const float* o_w   = (const float*)d_in[6];
    const float* ln2_w = (const float*)d_in[7];
    const float* gate_w= (const float*)d_in[8];
    const float* sh_w1 = (const float*)d_in[9];
    const float* sh_w2 = (const float*)d_in[10];
    const float* sh_w3 = (const float*)d_in[11];
    const float* re_w1 = (const float*)d_in[12];
    const float* re_w2 = (const float*)d_in[13];
    const float* re_w3 = (const float*)d_in[14];

    float* outy = (float*)d_out;
    float* outp = outy + (long)Tc * Dc;

    float *xn, *qlat, *lat, *kvb, *attn, *hb, *hnb, *g13, *act, *shb;
    float *wqkv, *w13, *rw13, *eh13, *ehact, *eo;
    cudaGetSymbolAddress((void**)&xn, g_xn);
    cudaGetSymbolAddress((void**)&qlat, g_qlat);
    cudaGetSymbolAddress((void**)&lat, g_lat);
    cudaGetSymbolAddress((void**)&kvb, g_kv);
    cudaGetSymbolAddress((void**)&attn, g_attn);
    cudaGetSymbolAddress((void**)&hb, g_h);
    cudaGetSymbolAddress((void**)&hnb, g_hn);
    cudaGetSymbolAddress((void**)&g13, g_g13);
    cudaGetSymbolAddress((void**)&act, g_act);
    cudaGetSymbolAddress((void**)&shb, g_shared);
    cudaGetSymbolAddress((void**)&wqkv, g_wqkv);
    cudaGetSymbolAddress((void**)&w13, g_w13);
    cudaGetSymbolAddress((void**)&rw13, g_rw13);
    cudaGetSymbolAddress((void**)&eh13, g_eh13);
    cudaGetSymbolAddress((void**)&ehact, g_ehact);
    cudaGetSymbolAddress((void**)&eo, g_eo);
    int* idxp; int* cntp;
    cudaGetSymbolAddress((void**)&idxp, g_idx);
    cudaGetSymbolAddress((void**)&cntp, g_cnt);

    cudaFuncSetAttribute((const void*)gemm_tc<false, false, false>,
                         cudaFuncAttributeMaxDynamicSharedMemorySize, SMEM_BYTES);
    cudaFuncSetAttribute((const void*)gemm_tc<false, false, true>,
                         cudaFuncAttributeMaxDynamicSharedMemorySize, SMEM_BYTES);
    cudaFuncSetAttribute((const void*)gemm_tc<true, true, false>,
                         cudaFuncAttributeMaxDynamicSharedMemorySize, SMEM_BYTES);
    cudaFuncSetAttribute((const void*)gemm_tc<false, true, false>,
                         cudaFuncAttributeMaxDynamicSharedMemorySize, SMEM_BYTES);
    cudaFuncSetAttribute((const void*)attn_tc_kernel,
                         cudaFuncAttributeMaxDynamicSharedMemorySize, ATT_SMEM);

    // launch #0: fused weight packing (6 segments)
    pack_weights_k<<<dim3(8192, 6), 256>>>(q_w, kvd_w, sh_w1, sh_w3, re_w1, re_w3,
                                           wqkv, w13, rw13);

    // ---- attention path ----
    rmsnorm_k<<<Tc, 256>>>(x, ln1_w, xn, Dc, Dc, Dc);                              // 1
    gemm_tc<false, false, false><<<dim3(1280 / BN, Tc / BM, 1), 256, SMEM_BYTES>>>(// 2
        xn, wqkv, qlat, nullptr, nullptr, nullptr, Tc, 1280, Dc, 0, 0, 0, 0);
    rmsnorm_k<<<Tc, 256>>>(qlat + 1024, kvn_w, lat, Rc, 1280, Rc);                 // 3
    gemm_tc<false, false, false><<<dim3(2048 / BN, Tc / BM, 1), 256, SMEM_BYTES>>>(// 4
        lat, kvu_w, kvb, nullptr, nullptr, nullptr, Tc, 2048, Rc, 0, 0, 0, 0);
    attn_tc_kernel<<<dim3(Lc / 64, Hc, Bc), 128, ATT_SMEM>>>(qlat, kvb, attn);     // 5 <- profiled
    gemm_tc<false, false, true><<<dim3(Dc / BN, Tc / BM, 1), 256, SMEM_BYTES>>>(
        attn, o_w, hb, x, nullptr, nullptr, Tc, Dc, Hc * HDc, 0, 0, 0, 0);

    // ---- MoE path ----
    rmsnorm_k<<<Tc, 256>>>(hb, ln2_w, hnb, Dc, Dc, Dc);
    gemm_tc<false, false, false><<<dim3(2048 / BN, Tc / BM, 1), 256, SMEM_BYTES>>>(
        hnb, w13, g13, nullptr, nullptr, nullptr, Tc, 2048, Dc, 0, 0, 0, 0);
    silu_pack_k<<<(Tc * Fc / 4 + 255) / 256, 256>>>();
    gemm_tc<false, false, false><<<dim3(Dc / BN, Tc / BM, 1), 256, SMEM_BYTES>>>(
        act, sh_w2, shb, nullptr, nullptr, nullptr, Tc, Dc, Fc, 0, 0, 0, 0);

    zero_cnt_k<<<1, 32>>>();
    router_kernel<<<Tc / 8, 256>>>(hnb, gate_w, outp);

    gemm_tc<true, true, false><<<dim3(2048 / BN, Tc / BM, Ec), 256, SMEM_BYTES>>>(
        hnb, rw13, eh13, nullptr, idxp, cntp, Tc, 2048, Dc, 0, (long)Dc * 2048, (long)Tc * 2048, Tc);
    silu_expert_k<<<dim3((Tc * Fc / 4 + 255) / 256, Ec), 256>>>();
    gemm_tc<false, true, false><<<dim3(Dc / BN, Tc / BM, Ec), 256, SMEM_BYTES>>>(
        ehact, re_w2, eo, nullptr, nullptr, cntp, Tc, Dc, Fc, (long)Tc * Fc, (long)Fc * Dc, (long)Tc * Dc, 0);

    final_kernel<<<(Tc * Dc / 4 + 255) / 256, 256>>>(hb, shb, outy);
}

// round 10
// speedup vs baseline: 1.7987x; 1.0327x over previous
#include <cuda_runtime.h>
#include <mma.h>
#include <math.h>

using namespace nvcuda;

#define Bc 2
#define Lc 2048
#define Dc 1024
#define Hc 16
#define HDc 64
#define Rc 256
#define Ec 8
#define Kc 2
#define Fc 1024
#define Tc (Bc*Lc)   // 4096

// ---------------- scratch ----------------
__device__ float g_xn[Tc*Dc];
__device__ float g_qlat[Tc*1280];                 // [q(1024) | lat_pre(256)]
__device__ float g_lat[Tc*Rc];
__device__ float g_kv[Tc*2*Hc*HDc];
__device__ float g_attn[Tc*Hc*HDc];
__device__ float g_h[Tc*Dc];
__device__ float g_hn[Tc*Dc];
__device__ float g_act[Tc*Fc];
__device__ float g_shared[Tc*Dc];
__device__ float g_wqkv[Dc*1280];
__device__ float g_w13[Dc*2048];                  // interleaved w1/w3
__device__ float g_rw13[(long)Ec*Dc*2048];        // interleaved
__device__ float g_ehact[(long)Ec*Tc*Fc];
__device__ float g_eo[(long)Ec*Tc*Dc];
__device__ int   g_cnt[Ec];
__device__ int   g_idx[Ec*Tc];
__device__ int   g_slot[Tc*Kc];
__device__ float g_tw[Tc*Kc];

// ---------------- small kernels ----------------
__global__ void zero_cnt_k() {
    if (threadIdx.x < Ec) g_cnt[threadIdx.x] = 0;
}

// weight packing: seg 0/1 concat into wqkv; seg 2/3 pair-interleave w1/w3
__global__ void pack_weights_k(const float* __restrict__ q_w, const float* __restrict__ kvd_w,
                               const float* __restrict__ sh_w1, const float* __restrict__ sh_w3,
                               const float* __restrict__ re_w1, const float* __restrict__ re_w3,
                               float* __restrict__ wqkv, float* __restrict__ w13,
                               float* __restrict__ rw13) {
    int seg = blockIdx.y;
    long i = (long)blockIdx.x * blockDim.x + threadIdx.x;
    if (seg == 0) {           // q_w [Dc][Dc] -> wqkv cols 0..1023
        long n4 = (long)Dc * Dc / 4;
        if (i >= n4) return;
        long r = i / (Dc / 4); int c4 = (int)(i % (Dc / 4));
        ((float4*)wqkv)[r * 320 + c4] = ((const float4*)q_w)[i];
    } else if (seg == 1) {    // kvd_w [Dc][Rc] -> wqkv cols 1024..1279
        long n4 = (long)Dc * Rc / 4;
        if (i >= n4) return;
        long r = i / (Rc / 4); int c4 = (int)(i % (Rc / 4));
        ((float4*)wqkv)[r * 320 + 256 + c4] = ((const float4*)kvd_w)[i];
    } else if (seg == 2) {    // sh_w1/sh_w3 interleave -> w13
        long n2 = (long)Dc * Fc / 2;
        if (i >= n2) return;
        long r = i / (Fc / 2); int j2 = (int)(i % (Fc / 2));
        float2 a = ((const float2*)sh_w1)[r * (Fc / 2) + j2];
        float2 b = ((const float2*)sh_w3)[r * (Fc / 2) + j2];
        float4 o = make_float4(a.x, b.x, a.y, b.y);
        ((float4*)w13)[r * 512 + j2] = o;
    } else {                  // re_w1/re_w3 interleave -> rw13
        long n2 = (long)Ec * Dc * Fc / 2;
        if (i >= n2) return;
        long r = i / (Fc / 2); int j2 = (int)(i % (Fc / 2));
        float2 a = ((const float2*)re_w1)[r * (Fc / 2) + j2];
        float2 b = ((const float2*)re_w3)[r * (Fc / 2) + j2];
        float4 o = make_float4(a.x, b.x, a.y, b.y);
        ((float4*)rw13)[r * 512 + j2] = o;
    }
}

__global__ void rmsnorm_k(const float* __restrict__ x, const float* __restrict__ w,
                          float* __restrict__ o, int dim, int xs, int os) {
    int row = blockIdx.x;
    int tid = threadIdx.x;
    const float* xr = x + (long)row * xs;
    float s = 0.f;
    for (int d = tid; d < dim; d += blockDim.x) { float v = xr[d]; s += v * v; }
    __shared__ float red[256];
    red[tid] = s;
    __syncthreads();
    for (int off = 128; off > 0; off >>= 1) {
        if (tid < off) red[tid] += red[tid + off];
        __syncthreads();
    }
    float inv = rsqrtf(red[0] / (float)dim + 1e-6f);
    float* orow = o + (long)row * os;
    for (int d = tid; d < dim; d += blockDim.x) orow[d] = w[d] * xr[d] * inv;
}

// ---------------- tf32 TC GEMM: 128x256 tile, 4-stage cp.async, 1 sync/tile, fused SiLU ----------------
#define BM 128
#define BN 256
#define BK 32
#define AST 36
#define BST 260
#define SM_A (BM*AST)
#define SM_B (BK*BST)
#define STAGE_F (SM_A+SM_B)
#define NSTAGE 4
#define SMEM_BYTES (NSTAGE*STAGE_F*4)   // 206848
#define EPST 68

__device__ __forceinline__ void cp_async16(float* sdst, const float* gsrc) {
    unsigned s = (unsigned)__cvta_generic_to_shared(sdst);
    asm volatile("cp.async.cg.shared.global [%0], [%1], 16;" :: "r"(s), "l"(gsrc));
}
#define CP_COMMIT() asm volatile("cp.async.commit_group;")
#define CP_WAIT2()  asm volatile("cp.async.wait_group 2;")

template<bool GATHER, bool HAS_CNT, bool RESID, bool SILU>
__global__ void __launch_bounds__(256)
gemm_tc(const float* __restrict__ A, const float* __restrict__ Bw,
        float* __restrict__ C, const float* __restrict__ resid,
        float* __restrict__ actOut,
        const int* __restrict__ gidx, const int* __restrict__ cntp,
        int M, int N, int Kd,
        long aEs, long bEs, long cEs, long actEs, int iEs) {
    extern __shared__ float sm[];

    int e = blockIdx.z;
    A += (long)e * aEs;
    Bw += (long)e * bEs;
    int Me = HAS_CNT ? cntp[e] : M;
    int bm = blockIdx.y * BM, bn = blockIdx.x * BN;
    if (bm >= Me) return;

    const int tid = threadIdx.x;
    const int warpId = tid >> 5;
    const int wm = warpId >> 2;        // 0..1
    const int wn = warpId & 3;         // 0..3

    const int arow0 = tid >> 3;
    const int acol  = (tid & 7) * 4;
    const int brow0 = tid >> 6;
    const int bcol  = (tid & 63) * 4;

    long aBase[4];
    #pragma unroll
    for (int i = 0; i < 4; i++) {
        int am = bm + arow0 + 32 * i;
        if (GATHER) {
            int g = gidx[e * iEs + am];
            if (g < 0 || g >= Tc) g = 0;
            aBase[i] = (long)g * Kd;
        } else {
            aBase[i] = (long)am * Kd;
        }
    }

    wmma::fragment<wmma::accumulator, 16, 16, 8, float> cf[4][4];
    if (RESID) {
        #pragma unroll
        for (int i = 0; i < 4; i++)
            #pragma unroll
            for (int j = 0; j < 4; j++)
                wmma::load_matrix_sync(cf[i][j],
                    resid + (long)(bm + wm * 64 + i * 16) * N + bn + wn * 64 + j * 16,
                    N, wmma::mem_row_major);
    } else {
        #pragma unroll
        for (int i = 0; i < 4; i++)
            #pragma unroll
            for (int j = 0; j < 4; j++)
                wmma::fill_fragment(cf[i][j], 0.f);
    }

    const int T = Kd / BK;

    auto load_tile = [&](int t, int s) {
        float* As_ = sm + s * STAGE_F;
        float* Bs_ = sm + s * STAGE_F + SM_A;
        int k0 = t * BK;
        #pragma unroll
        for (int i = 0; i < 4; i++)
            cp_async16(&As_[(arow0 + 32 * i) * AST + acol], A + aBase[i] + k0 + acol);
        #pragma unroll
        for (int i = 0; i < 8; i++)
            cp_async16(&Bs_[(brow0 + 4 * i) * BST + bcol], Bw + (long)(k0 + brow0 + 4 * i) * N + bn + bcol);
    };

    load_tile(0, 0);
    CP_COMMIT();
    if (T > 1) load_tile(1, 1);
    CP_COMMIT();

    for (int t = 0; t < T; t++) {
        if (t + 2 < T) load_tile(t + 2, (t + 2) & 3);
        CP_COMMIT();
        CP_WAIT2();
        __syncthreads();

        int s = t & 3;
        const float* As_ = sm + s * STAGE_F;
        const float* Bs_ = sm + s * STAGE_F + SM_A;

        wmma::fragment<wmma::matrix_a, 16, 16, 8, wmma::precision::tf32, wmma::row_major> af[2][4];
        wmma::fragment<wmma::matrix_b, 16, 16, 8, wmma::precision::tf32, wmma::row_major> bf[2][4];
        #pragma unroll
        for (int i = 0; i < 4; i++)
            wmma::load_matrix_sync(af[0][i], &As_[(wm * 64 + i * 16) * AST], AST);
        #pragma unroll
        for (int j = 0; j < 4; j++)
            wmma::load_matrix_sync(bf[0][j], &Bs_[wn * 64 + j * 16], BST);

        #pragma unroll
        for (int kk = 0; kk < BK / 8; kk++) {
            int cur = kk & 1, nxt = cur ^ 1;
            if (kk < BK / 8 - 1) {
                #pragma unroll
                for (int i = 0; i < 4; i++)
                    wmma::load_matrix_sync(af[nxt][i], &As_[(wm * 64 + i * 16) * AST + (kk + 1) * 8], AST);
                #pragma unroll
                for (int j = 0; j < 4; j++)
                    wmma::load_matrix_sync(bf[nxt][j], &Bs_[((kk + 1) * 8) * BST + wn * 64 + j * 16], BST);
            }
            #pragma unroll
            for (int i = 0; i < 4; i++)
                #pragma unroll
                for (int j = 0; j < 4; j++)
                    wmma::mma_sync(cf[i][j], af[cur][i], bf[cur][j], cf[i][j]);
        }
        // no trailing sync: 4 stages, prefetch distance 2 -> no WAR hazard
    }

    if (SILU) {
        // stage accumulators to smem, then silu pairs -> actOut
        __syncthreads();
        float* St = sm;
        #pragma unroll
        for (int i = 0; i < 4; i++)
            #pragma unroll
            for (int j = 0; j < 4; j++)
                wmma::store_matrix_sync(&St[((warpId * 64) + i * 16) * EPST + j * 16],
                                        cf[i][j], EPST, wmma::mem_row_major);
        __syncthreads();
        int r = tid >> 1;               // 0..127
        int co0 = (tid & 1) * 64;       // act col offset within CTA half
        int wmr = r >> 6, wr = r & 63;
        long obase = (long)e * actEs + (long)(bm + r) * (N >> 1) + (bn >> 1) + co0;
        #pragma unroll 4
        for (int c = 0; c < 64; c += 4) {
            int bc0 = 2 * (co0 + c);
            int wnn = bc0 >> 6, wc = bc0 & 63;
            const float* p = &St[((wmr * 4 + wnn) * 64 + wr) * EPST + wc];
            float4 p0 = *(const float4*)(p);
            float4 p1 = *(const float4*)(p + 4);
            float4 o;
            o.x = p0.x / (1.f + expf(-p0.x)) * p0.y;
            o.y = p0.z / (1.f + expf(-p0.z)) * p0.w;
            o.z = p1.x / (1.f + expf(-p1.x)) * p1.y;
            o.w = p1.z / (1.f + expf(-p1.z)) * p1.w;
            *(float4*)(actOut + obase + c) = o;
        }
    } else {
        C += (long)e * cEs;
        #pragma unroll
        for (int i = 0; i < 4; i++)
            #pragma unroll
            for (int j = 0; j < 4; j++)
                wmma::store_matrix_sync(
                    C + (long)(bm + wm * 64 + i * 16) * N + bn + wn * 64 + j * 16,
                    cf[i][j], N, wmma::mem_row_major);
    }
}

// ---------------- tensor-core causal flash attention (unchanged) ----------------
#define ATSTR 72
#define ATT_SMEM ((5*64*ATSTR + 3*64)*4)

__global__ void __launch_bounds__(128)
attn_tc_kernel(const float* __restrict__ q, const float* __restrict__ kv,
               float* __restrict__ o) {
    extern __shared__ float smema[];
    float* Qs = smema;
    float* Ks = Qs + 64 * ATSTR;
    float* Vs = Ks + 64 * ATSTR;
    float* Ss = Vs + 64 * ATSTR;
    float* Os = Ss + 64 * ATSTR;
    float* mrow = Os + 64 * ATSTR;
    float* lrow = mrow + 64;
    float* crow = lrow + 64;

    const int b = blockIdx.z, h = blockIdx.y, iq = blockIdx.x;
    const int q0 = iq * 64;
    const int tid = threadIdx.x;
    const int warpId = tid >> 5;

    {
        int j = tid >> 1, d0 = (tid & 1) * 32;
        long qb = ((long)(b * Lc + q0 + j)) * 1280 + h * HDc;
        #pragma unroll
        for (int dd = 0; dd < 32; dd += 4) {
            float4 v = *(const float4*)(q + qb + d0 + dd);
            Qs[j * ATSTR + d0 + dd + 0] = v.x * 0.125f;
            Qs[j * ATSTR + d0 + dd + 1] = v.y * 0.125f;
            Qs[j * ATSTR + d0 + dd + 2] = v.z * 0.125f;
            Qs[j * ATSTR + d0 + dd + 3] = v.w * 0.125f;
            Os[j * ATSTR + d0 + dd + 0] = 0.f;
            Os[j * ATSTR + d0 + dd + 1] = 0.f;
            Os[j * ATSTR + d0 + dd + 2] = 0.f;
            Os[j * ATSTR + d0 + dd + 3] = 0.f;
        }
        if (tid < 64) { mrow[tid] = -INFINITY; lrow[tid] = 0.f; }
    }
    __syncthreads();

    for (int kt = 0; kt <= q0; kt += 64) {
        {
            int j = tid >> 1, d0 = (tid & 1) * 32;
            long kvb = ((long)(b * Lc + kt + j)) * (2 * Hc * HDc) + h * HDc;
            #pragma unroll
            for (int dd = 0; dd < 32; dd += 4) {
                *(float4*)&Ks[j * ATSTR + d0 + dd] = *(const float4*)(kv + kvb + d0 + dd);
                *(float4*)&Vs[j * ATSTR + d0 + dd] = *(const float4*)(kv + kvb + Hc * HDc + d0 + dd);
            }
        }
        __syncthreads();

        {
            wmma::fragment<wmma::accumulator, 16, 16, 8, float> sf[4];
            #pragma unroll
            for (int n = 0; n < 4; n++) wmma::fill_fragment(sf[n], 0.f);
            #pragma unroll
            for (int kk = 0; kk < 8; kk++) {
                wmma::fragment<wmma::matrix_a, 16, 16, 8, wmma::precision::tf32, wmma::row_major> aq;
                wmma::load_matrix_sync(aq, &Qs[(warpId * 16) * ATSTR + kk * 8], ATSTR);
                #pragma unroll
                for (int n = 0; n < 4; n++) {
                    wmma::fragment<wmma::matrix_b, 16, 16, 8, wmma::precision::tf32, wmma::col_major> bk;
                    wmma::load_matrix_sync(bk, &Ks[(n * 16) * ATSTR + kk * 8], ATSTR);
                    wmma::mma_sync(sf[n], aq, bk, sf[n]);
                }
            }
            #pragma unroll
            for (int n = 0; n < 4; n++)
                wmma::store_matrix_sync(&Ss[(warpId * 16) * ATSTR + n * 16], sf[n], ATSTR, wmma::mem_row_major);
        }
        __syncthreads();

        if (tid < 64) {
            int r = tid;
            int vmax = (kt == q0) ? (r + 1) : 64;
            float mx = -INFINITY;
            for (int c = 0; c < vmax; c++) mx = fmaxf(mx, Ss[r * ATSTR + c]);
            float nm = fmaxf(mrow[r], mx);
            float corr = __expf(mrow[r] - nm);
            float sum = 0.f;
            for (int c = 0; c < vmax; c++) {
                float p = __expf(Ss[r * ATSTR + c] - nm);
                Ss[r * ATSTR + c] = p;
                sum += p;
            }
            for (int c = vmax; c < 64; c++) Ss[r * ATSTR + c] = 0.f;
            lrow[r] = lrow[r] * corr + sum;
            mrow[r] = nm;
            crow[r] = corr;
        }
        __syncthreads();

        {
            int r = tid >> 1, c0 = (tid & 1) * 32;
            float corr = crow[r];
            #pragma unroll
            for (int c = 0; c < 32; c++) Os[r * ATSTR + c0 + c] *= corr;
        }
        __syncthreads();

        {
            wmma::fragment<wmma::accumulator, 16, 16, 8, float> of[4];
            #pragma unroll
            for (int n = 0; n < 4; n++)
                wmma::load_matrix_sync(of[n], &Os[(warpId * 16) * ATSTR + n * 16], ATSTR, wmma::mem_row_major);
            #pragma unroll
            for (int kk = 0; kk < 8; kk++) {
                wmma::fragment<wmma::matrix_a, 16, 16, 8, wmma::precision::tf32, wmma::row_major> ap;
                wmma::load_matrix_sync(ap, &Ss[(warpId * 16) * ATSTR + kk * 8], ATSTR);
                #pragma unroll
                for (int n = 0; n < 4; n++) {
                    wmma::fragment<wmma::matrix_b, 16, 16, 8, wmma::precision::tf32, wmma::row_major> bv;
                    wmma::load_matrix_sync(bv, &Vs[(kk * 8) * ATSTR + n * 16], ATSTR);
                    wmma::mma_sync(of[n], ap, bv, of[n]);
                }
            }
            #pragma unroll
            for (int n = 0; n < 4; n++)
                wmma::store_matrix_sync(&Os[(warpId * 16) * ATSTR + n * 16], of[n], ATSTR, wmma::mem_row_major);
        }
        __syncthreads();
    }

    {
        int r = tid >> 1, c0 = (tid & 1) * 32;
        float inv = 1.f / lrow[r];
        long ob = ((long)(b * Lc + q0 + r)) * (Hc * HDc) + h * HDc + c0;
        #pragma unroll
        for (int c = 0; c < 32; c += 4) {
            float4 w;
            w.x = Os[r * ATSTR + c0 + c + 0] * inv;
            w.y = Os[r * ATSTR + c0 + c + 1] * inv;
            w.z = Os[r * ATSTR + c0 + c + 2] * inv;
            w.w = Os[r * ATSTR + c0 + c + 3] * inv;
            *(float4*)(o + ob + c) = w;
        }
    }
}

// ---------------- router ----------------
__global__ void router_kernel(const float* __restrict__ hn, const float* __restrict__ gw,
                              float* __restrict__ probs_out) {
    int warp = (blockIdx.x * blockDim.x + threadIdx.x) >> 5;
    int lane = threadIdx.x & 31;
    if (warp >= Tc) return;
    const float* row = hn + (long)warp * Dc;
    float acc[8] = {0, 0, 0, 0, 0, 0, 0, 0};
    for (int d = lane; d < Dc; d += 32) {
        float xv = row[d];
        const float* g = gw + d * 8;
        #pragma unroll
        for (int e = 0; e < 8; e++) acc[e] += xv * g[e];
    }
    #pragma unroll
    for (int e = 0; e < 8; e++)
        #pragma unroll
        for (int off = 16; off > 0; off >>= 1)
            acc[e] += __shfl_xor_sync(0xffffffffu, acc[e], off);

    if (lane == 0) {
        float mx = acc[0];
        #pragma unroll
        for (int e = 1; e < 8; e++) mx = fmaxf(mx, acc[e]);
        float p[8], s = 0.f;
        #pragma unroll
        for (int e = 0; e < 8; e++) { p[e] = expf(acc[e] - mx); s += p[e]; }
        float invs = 1.f / s;
        #pragma unroll
        for (int e = 0; e < 8; e++) { p[e] *= invs; probs_out[(long)warp * 8 + e] = p[e]; }
        int i1 = 0;
        #pragma unroll
        for (int e = 1; e < 8; e++) if (p[e] > p[i1]) i1 = e;
        int i2 = (i1 == 0) ? 1 : 0;
        #pragma unroll
        for (int e = 0; e < 8; e++) if (e != i1 && p[e] > p[i2]) i2 = e;
        float w1 = p[i1], w2 = p[i2];
        float inv2 = 1.f / (w1 + w2);
        w1 *= inv2; w2 *= inv2;
        int pos1 = atomicAdd(&g_cnt[i1], 1);
        g_idx[i1 * Tc + pos1] = warp;
        g_slot[warp * 2 + 0] = i1 * Tc + pos1;
        g_tw[warp * 2 + 0] = w1;
        int pos2 = atomicAdd(&g_cnt[i2], 1);
        g_idx[i2 * Tc + pos2] = warp;
        g_slot[warp * 2 + 1] = i2 * Tc + pos2;
        g_tw[warp * 2 + 1] = w2;
    }
}

// ---------------- final combine ----------------
__global__ void final_kernel(const float* __restrict__ h, const float* __restrict__ sh,
                             float* __restrict__ out) {
    long i4 = (long)blockIdx.x * blockDim.x + threadIdx.x;
    if (i4 >= (long)Tc * Dc / 4) return;
    int t = (int)(i4 / (Dc / 4));
    int d4 = (int)(i4 % (Dc / 4));
    int s0 = g_slot[t * 2 + 0], s1 = g_slot[t * 2 + 1];
    float w0 = g_tw[t * 2 + 0], w1 = g_tw[t * 2 + 1];
    float4 e0 = *(const float4*)(g_eo + (long)s0 * Dc + d4 * 4);
    float4 e1 = *(const float4*)(g_eo + (long)s1 * Dc + d4 * 4);
    float4 hv = ((const float4*)h)[i4];
    float4 sv = ((const float4*)sh)[i4];
    float4 r;
    r.x = hv.x + sv.x + w0 * e0.x + w1 * e1.x;
    r.y = hv.y + sv.y + w0 * e0.y + w1 * e1.y;
    r.z = hv.z + sv.z + w0 * e0.z + w1 * e1.z;
    r.w = hv.w + sv.w + w0 * e0.w + w1 * e1.w;
    ((float4*)out)[i4] = r;
}

// ---------------- launch ----------------
extern "C" void kernel_launch(void* const* d_in, const int* in_sizes, int n_in,
                              void* d_out, int out_size) {
    const float* x     = (const float*)d_in[0];
    const float* ln1_w = (const float*)d_in[1];
    const float* q_w   = (const float*)d_in[2];
    const float* kvd_w = (const float*)d_in[3];
    const float* kvn_w = (const float*)d_in[4];
    const float* kvu_w = (const float*)d_in[5];
    const float* o_w   = (const float*)d_in[6];
    const float* ln2_w = (const float*)d_in[7];
    const float* gate_w= (const float*)d_in[8];
    const float* sh_w1 = (const float*)d_in[9];
    const float* sh_w2 = (const float*)d_in[10];
    const float* sh_w3 = (const float*)d_in[11];
    const float* re_w1 = (const float*)d_in[12];
    const float* re_w2 = (const float*)d_in[13];
    const float* re_w3 = (const float*)d_in[14];

    float* outy = (float*)d_out;
    float* outp = outy + (long)Tc * Dc;

    float *xn, *qlat, *lat, *kvb, *attn, *hb, *hnb, *act, *shb;
    float *wqkv, *w13, *rw13, *ehact, *eo;
    cudaGetSymbolAddress((void**)&xn, g_xn);
    cudaGetSymbolAddress((void**)&qlat, g_qlat);
    cudaGetSymbolAddress((void**)&lat, g_lat);
    cudaGetSymbolAddress((void**)&kvb, g_kv);
    cudaGetSymbolAddress((void**)&attn, g_attn);
    cudaGetSymbolAddress((void**)&hb, g_h);
    cudaGetSymbolAddress((void**)&hnb, g_hn);
    cudaGetSymbolAddress((void**)&act, g_act);
    cudaGetSymbolAddress((void**)&shb, g_shared);
    cudaGetSymbolAddress((void**)&wqkv, g_wqkv);
    cudaGetSymbolAddress((void**)&w13, g_w13);
    cudaGetSymbolAddress((void**)&rw13, g_rw13);
    cudaGetSymbolAddress((void**)&ehact, g_ehact);
    cudaGetSymbolAddress((void**)&eo, g_eo);
    int* idxp; int* cntp;
    cudaGetSymbolAddress((void**)&idxp, g_idx);
    cudaGetSymbolAddress((void**)&cntp, g_cnt);

    cudaFuncSetAttribute((const void*)gemm_tc<false, false, false, false>,
                         cudaFuncAttributeMaxDynamicSharedMemorySize, SMEM_BYTES);
    cudaFuncSetAttribute((const void*)gemm_tc<false, false, true, false>,
                         cudaFuncAttributeMaxDynamicSharedMemorySize, SMEM_BYTES);
    cudaFuncSetAttribute((const void*)gemm_tc<false, false, false, true>,
                         cudaFuncAttributeMaxDynamicSharedMemorySize, SMEM_BYTES);
    cudaFuncSetAttribute((const void*)gemm_tc<true, true, false, true>,
                         cudaFuncAttributeMaxDynamicSharedMemorySize, SMEM_BYTES);
    cudaFuncSetAttribute((const void*)gemm_tc<false, true, false, false>,
                         cudaFuncAttributeMaxDynamicSharedMemorySize, SMEM_BYTES);
    cudaFuncSetAttribute((const void*)attn_tc_kernel,
                         cudaFuncAttributeMaxDynamicSharedMemorySize, ATT_SMEM);

    pack_weights_k<<<dim3(16384, 4), 256>>>(q_w, kvd_w, sh_w1, sh_w3, re_w1, re_w3,
                                            wqkv, w13, rw13);

    // ---- attention path ----
    rmsnorm_k<<<Tc, 256>>>(x, ln1_w, xn, Dc, Dc, Dc);
    gemm_tc<false, false, false, false><<<dim3(1280 / BN, Tc / BM, 1), 256, SMEM_BYTES>>>(
        xn, wqkv, qlat, nullptr, nullptr, nullptr, nullptr, Tc, 1280, Dc, 0, 0, 0, 0, 0);
    rmsnorm_k<<<Tc, 256>>>(qlat + 1024, kvn_w, lat, Rc, 1280, Rc);
    gemm_tc<false, false, false, false><<<dim3(2048 / BN, Tc / BM, 1), 256, SMEM_BYTES>>>(
        lat, kvu_w, kvb, nullptr, nullptr, nullptr, nullptr, Tc, 2048, Rc, 0, 0, 0, 0, 0);
    attn_tc_kernel<<<dim3(Lc / 64, Hc, Bc), 128, ATT_SMEM>>>(qlat, kvb, attn);
    gemm_tc<false, false, true, false><<<dim3(Dc / BN, Tc / BM, 1), 256, SMEM_BYTES>>>(
        attn, o_w, hb, x, nullptr, nullptr, nullptr, Tc, Dc, Hc * HDc, 0, 0, 0, 0, 0);

    // ---- MoE path ----
    rmsnorm_k<<<Tc, 256>>>(hb, ln2_w, hnb, Dc, Dc, Dc);
    // shared expert: fused w1/w3 GEMM + silu -> act
    gemm_tc<false, false, false, true><<<dim3(2048 / BN, Tc / BM, 1), 256, SMEM_BYTES>>>(
        hnb, w13, nullptr, nullptr, act, nullptr, nullptr, Tc, 2048, Dc, 0, 0, 0, 0, 0);
    gemm_tc<false, false, false, false><<<dim3(Dc / BN, Tc / BM, 1), 256, SMEM_BYTES>>>(
        act, sh_w2, shb, nullptr, nullptr, nullptr, nullptr, Tc, Dc, Fc, 0, 0, 0, 0, 0);

    zero_cnt_k<<<1, 32>>>();
    router_kernel<<<Tc / 8, 256>>>(hnb, gate_w, outp);

    // routed experts: fused gathered w1/w3 GEMM + silu -> ehact
    gemm_tc<true, true, false, true><<<dim3(2048 / BN, Tc / BM, Ec), 256, SMEM_BYTES>>>(
        hnb, rw13, nullptr, nullptr, ehact, idxp, cntp,
        Tc, 2048, Dc, 0, (long)Dc * 2048, 0, (long)Tc * Fc, Tc);
    gemm_tc<false, true, false, false><<<dim3(Dc / BN, Tc / BM, Ec), 256, SMEM_BYTES>>>(
        ehact, re_w2, eo, nullptr, nullptr, nullptr, cntp,
        Tc, Dc, Fc, (long)Tc * Fc, (long)Fc * Dc, (long)Tc * Dc, 0, 0);

    final_kernel<<<(Tc * Dc / 4 + 255) / 256, 256>>>(hb, shb, outy);
}

// round 12
// speedup vs baseline: 3.2245x; 1.7927x over previous
#include <cuda_runtime.h>
#include <mma.h>
#include <cuda_fp16.h>
#include <math.h>
#include <stdint.h>

using namespace nvcuda;

#define Bc 2
#define Lc 2048
#define Dc 1024
#define Hc 16
#define HDc 64
#define Rc 256
#define Ec 8
#define Kc 2
#define Fc 1024
#define Tc (Bc*Lc)   // 4096

// ---------------- scratch ----------------
__device__ __half g_xn_h[Tc*Dc];
__device__ float  g_qlat[Tc*1280];
__device__ __half g_lat_h[Tc*Rc];
__device__ float  g_kv[Tc*2*Hc*HDc];
__device__ __half g_attn_h[Tc*Hc*HDc];
__device__ float  g_h[Tc*Dc];
__device__ float  g_hn[Tc*Dc];
__device__ __half g_hn_h[Tc*Dc];
__device__ __half g_act_h[Tc*Fc];
__device__ float  g_shared[Tc*Dc];
__device__ __half g_wqkv_h[Dc*1280];
__device__ __half g_kvu_h[Rc*2048];
__device__ __half g_ow_h[Dc*Dc];
__device__ __half g_w13_h[Dc*2048];              // pair-interleaved w1/w3
__device__ __half g_w2_h[Dc*Dc];
__device__ __half g_rw13_h[(long)Ec*Dc*2048];    // pair-interleaved
__device__ __half g_rw2_h[(long)Ec*Dc*Dc];
__device__ __half g_ehact_h[(long)Ec*Tc*Fc];
__device__ float  g_eo[(long)Ec*Tc*Dc];
__device__ int    g_cnt[Ec];
__device__ int    g_idx[Ec*Tc];
__device__ int    g_slot[Tc*Kc];
__device__ float  g_tw[Tc*Kc];

// ---------------- helpers ----------------
__device__ __forceinline__ void st_half4(__half* p, float a, float b, float c, float d) {
    *(__half2*)p       = __floats2half2_rn(a, b);
    *(__half2*)(p + 2) = __floats2half2_rn(c, d);
}
__device__ __forceinline__ void cp16(void* sdst, const void* g) {
    unsigned s = (unsigned)__cvta_generic_to_shared(sdst);
    asm volatile("cp.async.cg.shared.global [%0], [%1], 16;" :: "r"(s), "l"(g));
}
#define CP_COMMIT() asm volatile("cp.async.commit_group;")
#define CP_WAIT2()  asm volatile("cp.async.wait_group 2;")

// ---------------- small kernels ----------------
__global__ void zero_cnt_k() {
    if (threadIdx.x < Ec) g_cnt[threadIdx.x] = 0;
}

// convert + pack all weights to half (8 segments)
__global__ void cvt_weights_k(const float* __restrict__ q_w, const float* __restrict__ kvd_w,
                              const float* __restrict__ kvu_w, const float* __restrict__ o_w,
                              const float* __restrict__ sh_w1, const float* __restrict__ sh_w2,
                              const float* __restrict__ sh_w3,
                              const float* __restrict__ re_w1, const float* __restrict__ re_w2,
                              const float* __restrict__ re_w3) {
    int seg = blockIdx.y;
    long i = (long)blockIdx.x * blockDim.x + threadIdx.x;
    switch (seg) {
    case 0: {   // q_w -> wqkv cols 0..1023
        if (i >= (long)Dc * Dc / 4) return;
        long r = i / 256; int c4 = (int)(i % 256);
        float4 v = ((const float4*)q_w)[i];
        st_half4(g_wqkv_h + r * 1280 + c4 * 4, v.x, v.y, v.z, v.w);
        break; }
    case 1: {   // kvd_w -> wqkv cols 1024..1279
        if (i >= (long)Dc * Rc / 4) return;
        long r = i / 64; int c4 = (int)(i % 64);
        float4 v = ((const float4*)kvd_w)[i];
        st_half4(g_wqkv_h + r * 1280 + 1024 + c4 * 4, v.x, v.y, v.z, v.w);
        break; }
    case 2: {   // kvu_w plain
        if (i >= (long)Rc * 2048 / 4) return;
        float4 v = ((const float4*)kvu_w)[i];
        st_half4(g_kvu_h + i * 4, v.x, v.y, v.z, v.w);
        break; }
    case 3: {   // o_w plain
        if (i >= (long)Dc * Dc / 4) return;
        float4 v = ((const float4*)o_w)[i];
        st_half4(g_ow_h + i * 4, v.x, v.y, v.z, v.w);
        break; }
    case 4: {   // sh_w2 plain
        if (i >= (long)Dc * Dc / 4) return;
        float4 v = ((const float4*)sh_w2)[i];
        st_half4(g_w2_h + i * 4, v.x, v.y, v.z, v.w);
        break; }
    case 5: {   // re_w2 plain (x8)
        if (i >= (long)Ec * Dc * Dc / 4) return;
        float4 v = ((const float4*)re_w2)[i];
        st_half4(g_rw2_h + i * 4, v.x, v.y, v.z, v.w);
        break; }
    case 6: {   // sh_w1/sh_w3 interleave
        if (i >= (long)Dc * Fc / 2) return;
        long r = i / 512; int j2 = (int)(i % 512);
        float2 a = ((const float2*)sh_w1)[r * 512 + j2];
        float2 b = ((const float2*)sh_w3)[r * 512 + j2];
        st_half4(g_w13_h + r * 2048 + j2 * 4, a.x, b.x, a.y, b.y);
        break; }
    default: {  // re_w1/re_w3 interleave (x8)
        if (i >= (long)Ec * Dc * Fc / 2) return;
        long r = i / 512; int j2 = (int)(i % 512);
        float2 a = ((const float2*)re_w1)[r * 512 + j2];
        float2 b = ((const float2*)re_w3)[r * 512 + j2];
        st_half4(g_rw13_h + r * 2048 + j2 * 4, a.x, b.x, a.y, b.y);
        break; }
    }
}

// rmsnorm: always writes half output (stride = dim); optionally fp32 too
__global__ void rmsnorm_k(const float* __restrict__ x, const float* __restrict__ w,
                          __half* __restrict__ oh, float* __restrict__ of,
                          int dim, int xs) {
    int row = blockIdx.x;
    int tid = threadIdx.x;
    const float* xr = x + (long)row * xs;
    float s = 0.f;
    for (int d = tid; d < dim; d += blockDim.x) { float v = xr[d]; s += v * v; }
    __shared__ float red[256];
    red[tid] = s;
    __syncthreads();
    for (int off = 128; off > 0; off >>= 1) {
        if (tid < off) red[tid] += red[tid + off];
        __syncthreads();
    }
    float inv = rsqrtf(red[0] / (float)dim + 1e-6f);
    __half* ohr = oh + (long)row * dim;
    float* ofr = of ? of + (long)row * dim : nullptr;
    for (int d = tid; d < dim; d += blockDim.x) {
        float v = w[d] * xr[d] * inv;
        ohr[d] = __float2half_rn(v);
        if (of) ofr[d] = v;
    }
}

// ---------------- fp16 TC GEMM: 128x256 tile, m16n16k16, 4-stage cp.async, fused SiLU ----------------
#define BM 128
#define BN 256
#define BK 32
#define ASTH 40                 // halfs
#define BSTH 264
#define SMAH (BM*ASTH)          // 5120 halfs
#define SMBH (BK*BSTH)          // 8448 halfs
#define STGH (SMAH+SMBH)        // 13568 halfs = 27136 B
#define NSTAGE 4
#define EPST 68
#define GSMEM 139264            // max(4*27136=108544, 512*68*4=139264)

template<bool GATHER, bool HAS_CNT, bool RESID, bool SILU>
__global__ void __launch_bounds__(256)
gemm_h(const __half* __restrict__ A, const __half* __restrict__ Bw,
       float* __restrict__ C, const float* __restrict__ resid,
       __half* __restrict__ actOut,
       const int* __restrict__ gidx, const int* __restrict__ cntp,
       int M, int N, int Kd,
       long aEs, long bEs, long cEs, long actEs, int iEs) {
    extern __shared__ char smx[];

    int e = blockIdx.z;
    A += (long)e * aEs;
    Bw += (long)e * bEs;
    int Me = HAS_CNT ? cntp[e] : M;
    int bm = blockIdx.y * BM, bn = blockIdx.x * BN;
    if (bm >= Me) return;

    const int tid = threadIdx.x;
    const int warpId = tid >> 5;
    const int wm = warpId >> 2;        // 0..1
    const int wn = warpId & 3;         // 0..3

    // A: 128 rows x 32 halfs = 512 16B-chunks; 2 per thread (rows r, r+64)
    const int ar0 = tid >> 2;          // 0..63
    const int ac8 = (tid & 3) * 8;
    // B: 32 rows x 256 halfs = 1024 chunks; 4 per thread
    const int br0 = tid >> 5;          // 0..7
    const int bc8 = (tid & 31) * 8;

    long aBase[2];
    int aS[2];
    #pragma unroll
    for (int i = 0; i < 2; i++) {
        int row = ar0 + 64 * i;
        int am = bm + row;
        long ar;
        if (GATHER) {
            int g = gidx[e * iEs + am];
            if (g < 0 || g >= Tc) g = 0;
            ar = (long)g * Kd;
        } else ar = (long)am * Kd;
        aBase[i] = ar + ac8;
        aS[i] = row * ASTH + ac8;
    }
    long bOff[4];
    int bS[4];
    #pragma unroll
    for (int i = 0; i < 4; i++) {
        int row = br0 + 8 * i;
        bOff[i] = (long)row * N + bn + bc8;
        bS[i] = row * BSTH + bc8;
    }

    wmma::fragment<wmma::accumulator, 16, 16, 16, float> cf[4][4];
    if (RESID) {
        #pragma unroll
        for (int i = 0; i < 4; i++)
            #pragma unroll
            for (int j = 0; j < 4; j++)
                wmma::load_matrix_sync(cf[i][j],
                    resid + (long)(bm + wm * 64 + i * 16) * N + bn + wn * 64 + j * 16,
                    N, wmma::mem_row_major);
    } else {
        #pragma unroll
        for (int i = 0; i < 4; i++)
            #pragma unroll
            for (int j = 0; j < 4; j++)
                wmma::fill_fragment(cf[i][j], 0.f);
    }

    const int T = Kd / BK;

    auto load_tile = [&](int t, int s) {
        __half* As_ = (__half*)smx + s * STGH;
        __half* Bs_ = As_ + SMAH;
        int k0 = t * BK;
        #pragma unroll
        for (int i = 0; i < 2; i++)
            cp16(As_ + aS[i], A + aBase[i] + k0);
        #pragma unroll
        for (int i = 0; i < 4; i++)
            cp16(Bs_ + bS[i], Bw + (long)k0 * N + bOff[i]);
    };

    load_tile(0, 0);
    CP_COMMIT();
    if (T > 1) load_tile(1, 1);
    CP_COMMIT();

    for (int t = 0; t < T; t++) {
        if (t + 2 < T) load_tile(t + 2, (t + 2) & 3);
        CP_COMMIT();
        CP_WAIT2();
        __syncthreads();

        int s = t & 3;
        const __half* As_ = (const __half*)smx + s * STGH;
        const __half* Bs_ = As_ + SMAH;
        #pragma unroll
        for (int kk = 0; kk < 2; kk++) {
            wmma::fragment<wmma::matrix_a, 16, 16, 16, __half, wmma::row_major> af[4];
            wmma::fragment<wmma::matrix_b, 16, 16, 16, __half, wmma::row_major> bf[4];
            #pragma unroll
            for (int i = 0; i < 4; i++)
                wmma::load_matrix_sync(af[i], &As_[(wm * 64 + i * 16) * ASTH + kk * 16], ASTH);
            #pragma unroll
            for (int j = 0; j < 4; j++)
                wmma::load_matrix_sync(bf[j], &Bs_[(kk * 16) * BSTH + wn * 64 + j * 16], BSTH);
            #pragma unroll
            for (int i = 0; i < 4; i++)
                #pragma unroll
                for (int j = 0; j < 4; j++)
                    wmma::mma_sync(cf[i][j], af[i], bf[j], cf[i][j]);
        }
        // no trailing sync: 4 stages, prefetch distance 2 -> no WAR hazard
    }

    if (SILU) {
        __syncthreads();
        float* St = (float*)smx;
        #pragma unroll
        for (int i = 0; i < 4; i++)
            #pragma unroll
            for (int j = 0; j < 4; j++)
                wmma::store_matrix_sync(&St[((warpId * 64) + i * 16) * EPST + j * 16],
                                        cf[i][j], EPST, wmma::mem_row_major);
        __syncthreads();
        int r = tid >> 1;
        int co0 = (tid & 1) * 64;
        int wmr = r >> 6, wr = r & 63;
        long obase = (long)e * actEs + (long)(bm + r) * (N >> 1) + (bn >> 1) + co0;
        #pragma unroll 4
        for (int c = 0; c < 64; c += 4) {
            int bc0 = 2 * (co0 + c);
            int wnn = bc0 >> 6, wc = bc0 & 63;
            const float* p = &St[((wmr * 4 + wnn) * 64 + wr) * EPST + wc];
            float4 p0 = *(const float4*)(p);
            float4 p1 = *(const float4*)(p + 4);
            st_half4(actOut + obase + c,
                     p0.x / (1.f + expf(-p0.x)) * p0.y,
                     p0.z / (1.f + expf(-p0.z)) * p0.w,
                     p1.x / (1.f + expf(-p1.x)) * p1.y,
                     p1.z / (1.f + expf(-p1.z)) * p1.w);
        }
    } else {
        C += (long)e * cEs;
        #pragma unroll
        for (int i = 0; i < 4; i++)
            #pragma unroll
            for (int j = 0; j < 4; j++)
                wmma::store_matrix_sync(
                    C + (long)(bm + wm * 64 + i * 16) * N + bn + wn * 64 + j * 16,
                    cf[i][j], N, wmma::mem_row_major);
    }
}

// ---------------- tensor-core causal flash attention (tf32 wmma; half output) ----------------
#define ATSTR 72
#define ATT_SMEM ((5*64*ATSTR + 3*64)*4)

__global__ void __launch_bounds__(128)
attn_tc_kernel(const float* __restrict__ q, const float* __restrict__ kv,
               __half* __restrict__ o) {
    extern __shared__ float smema[];
    float* Qs = smema;
    float* Ks = Qs + 64 * ATSTR;
    float* Vs = Ks + 64 * ATSTR;
    float* Ss = Vs + 64 * ATSTR;
    float* Os = Ss + 64 * ATSTR;
    float* mrow = Os + 64 * ATSTR;
    float* lrow = mrow + 64;
    float* crow = lrow + 64;

    const int b = blockIdx.z, h = blockIdx.y, iq = blockIdx.x;
    const int q0 = iq * 64;
    const int tid = threadIdx.x;
    const int warpId = tid >> 5;

    {
        int j = tid >> 1, d0 = (tid & 1) * 32;
        long qb = ((long)(b * Lc + q0 + j)) * 1280 + h * HDc;
        #pragma unroll
        for (int dd = 0; dd < 32; dd += 4) {
            float4 v = *(const float4*)(q + qb + d0 + dd);
            Qs[j * ATSTR + d0 + dd + 0] = v.x * 0.125f;
            Qs[j * ATSTR + d0 + dd + 1] = v.y * 0.125f;
            Qs[j * ATSTR + d0 + dd + 2] = v.z * 0.125f;
            Qs[j * ATSTR + d0 + dd + 3] = v.w * 0.125f;
            Os[j * ATSTR + d0 + dd + 0] = 0.f;
            Os[j * ATSTR + d0 + dd + 1] = 0.f;
            Os[j * ATSTR + d0 + dd + 2] = 0.f;
            Os[j * ATSTR + d0 + dd + 3] = 0.f;
        }
        if (tid < 64) { mrow[tid] = -INFINITY; lrow[tid] = 0.f; }
    }
    __syncthreads();

    for (int kt = 0; kt <= q0; kt += 64) {
        {
            int j = tid >> 1, d0 = (tid & 1) * 32;
            long kvb = ((long)(b * Lc + kt + j)) * (2 * Hc * HDc) + h * HDc;
            #pragma unroll
            for (int dd = 0; dd < 32; dd += 4) {
                *(float4*)&Ks[j * ATSTR + d0 + dd] = *(const float4*)(kv + kvb + d0 + dd);
                *(float4*)&Vs[j * ATSTR + d0 + dd] = *(const float4*)(kv + kvb + Hc * HDc + d0 + dd);
            }
        }
        __syncthreads();

        {
            wmma::fragment<wmma::accumulator, 16, 16, 8, float> sf[4];
            #pragma unroll
            for (int n = 0; n < 4; n++) wmma::fill_fragment(sf[n], 0.f);
            #pragma unroll
            for (int kk = 0; kk < 8; kk++) {
                wmma::fragment<wmma::matrix_a, 16, 16, 8, wmma::precision::tf32, wmma::row_major> aq;
                wmma::load_matrix_sync(aq, &Qs[(warpId * 16) * ATSTR + kk * 8], ATSTR);
                #pragma unroll
                for (int n = 0; n < 4; n++) {
                    wmma::fragment<wmma::matrix_b, 16, 16, 8, wmma::precision::tf32, wmma::col_major> bk;
                    wmma::load_matrix_sync(bk, &Ks[(n * 16) * ATSTR + kk * 8], ATSTR);
                    wmma::mma_sync(sf[n], aq, bk, sf[n]);
                }
            }
            #pragma unroll
            for (int n = 0; n < 4; n++)
                wmma::store_matrix_sync(&Ss[(warpId * 16) * ATSTR + n * 16], sf[n], ATSTR, wmma::mem_row_major);
        }
        __syncthreads();

        if (tid < 64) {
            int r = tid;
            int vmax = (kt == q0) ? (r + 1) : 64;
            float mx = -INFINITY;
            for (int c = 0; c < vmax; c++) mx = fmaxf(mx, Ss[r * ATSTR + c]);
            float nm = fmaxf(mrow[r], mx);
            float corr = __expf(mrow[r] - nm);
            float sum = 0.f;
            for (int c = 0; c < vmax; c++) {
                float p = __expf(Ss[r * ATSTR + c] - nm);
                Ss[r * ATSTR + c] = p;
                sum += p;
            }
            for (int c = vmax; c < 64; c++) Ss[r * ATSTR + c] = 0.f;
            lrow[r] = lrow[r] * corr + sum;
            mrow[r] = nm;
            crow[r] = corr;
        }
        __syncthreads();

        {
            int r = tid >> 1, c0 = (tid & 1) * 32;
            float corr = crow[r];
            #pragma unroll
            for (int c = 0; c < 32; c++) Os[r * ATSTR + c0 + c] *= corr;
        }
        __syncthreads();

        {
            wmma::fragment<wmma::accumulator, 16, 16, 8, float> of[4];
            #pragma unroll
            for (int n = 0; n < 4; n++)
                wmma::load_matrix_sync(of[n], &Os[(warpId * 16) * ATSTR + n * 16], ATSTR, wmma::mem_row_major);
            #pragma unroll
            for (int kk = 0; kk < 8; kk++) {
                wmma::fragment<wmma::matrix_a, 16, 16, 8, wmma::precision::tf32, wmma::row_major> ap;
                wmma::load_matrix_sync(ap, &Ss[(warpId * 16) * ATSTR + kk * 8], ATSTR);
                #pragma unroll
                for (int n = 0; n < 4; n++) {
                    wmma::fragment<wmma::matrix_b, 16, 16, 8, wmma::precision::tf32, wmma::row_major> bv;
                    wmma::load_matrix_sync(bv, &Vs[(kk * 8) * ATSTR + n * 16], ATSTR);
                    wmma::mma_sync(of[n], ap, bv, of[n]);
                }
            }
            #pragma unroll
            for (int n = 0; n < 4; n++)
                wmma::store_matrix_sync(&Os[(warpId * 16) * ATSTR + n * 16], of[n], ATSTR, wmma::mem_row_major);
        }
        __syncthreads();
    }

    {
        int r = tid >> 1, c0 = (tid & 1) * 32;
        float inv = 1.f / lrow[r];
        long ob = ((long)(b * Lc + q0 + r)) * (Hc * HDc) + h * HDc + c0;
        #pragma unroll
        for (int c = 0; c < 32; c += 4) {
            st_half4(o + ob + c,
                     Os[r * ATSTR + c0 + c + 0] * inv,
                     Os[r * ATSTR + c0 + c + 1] * inv,
                     Os[r * ATSTR + c0 + c + 2] * inv,
                     Os[r * ATSTR + c0 + c + 3] * inv);
        }
    }
}

// ---------------- router (fp32 hn) ----------------
__global__ void router_kernel(const float* __restrict__ hn, const float* __restrict__ gw,
                              float* __restrict__ probs_out) {
    int warp = (blockIdx.x * blockDim.x + threadIdx.x) >> 5;
    int lane = threadIdx.x & 31;
    if (warp >= Tc) return;
    const float* row = hn + (long)warp * Dc;
    float acc[8] = {0, 0, 0, 0, 0, 0, 0, 0};
    for (int d = lane; d < Dc; d += 32) {
        float xv = row[d];
        const float* g = gw + d * 8;
        #pragma unroll
        for (int e = 0; e < 8; e++) acc[e] += xv * g[e];
    }
    #pragma unroll
    for (int e = 0; e < 8; e++)
        #pragma unroll
        for (int off = 16; off > 0; off >>= 1)
            acc[e] += __shfl_xor_sync(0xffffffffu, acc[e], off);

    if (lane == 0) {
        float mx = acc[0];
        #pragma unroll
        for (int e = 1; e < 8; e++) mx = fmaxf(mx, acc[e]);
        float p[8], s = 0.f;
        #pragma unroll
        for (int e = 0; e < 8; e++) { p[e] = expf(acc[e] - mx); s += p[e]; }
        float invs = 1.f / s;
        #pragma unroll
        for (int e = 0; e < 8; e++) { p[e] *= invs; probs_out[(long)warp * 8 + e] = p[e]; }
        int i1 = 0;
        #pragma unroll
        for (int e = 1; e < 8; e++) if (p[e] > p[i1]) i1 = e;
        int i2 = (i1 == 0) ? 1 : 0;
        #pragma unroll
        for (int e = 0; e < 8; e++) if (e != i1 && p[e] > p[i2]) i2 = e;
        float w1 = p[i1], w2 = p[i2];
        float inv2 = 1.f / (w1 + w2);
        w1 *= inv2; w2 *= inv2;
        int pos1 = atomicAdd(&g_cnt[i1], 1);
        g_idx[i1 * Tc + pos1] = warp;
        g_slot[warp * 2 + 0] = i1 * Tc + pos1;
        g_tw[warp * 2 + 0] = w1;
        int pos2 = atomicAdd(&g_cnt[i2], 1);
        g_idx[i2 * Tc + pos2] = warp;
        g_slot[warp * 2 + 1] = i2 * Tc + pos2;
        g_tw[warp * 2 + 1] = w2;
    }
}

// ---------------- final combine ----------------
__global__ void final_kernel(const float* __restrict__ h, const float* __restrict__ sh,
                             float* __restrict__ out) {
    long i4 = (long)blockIdx.x * blockDim.x + threadIdx.x;
    if (i4 >= (long)Tc * Dc / 4) return;
    int t = (int)(i4 / (Dc / 4));
    int d4 = (int)(i4 % (Dc / 4));
    int s0 = g_slot[t * 2 + 0], s1 = g_slot[t * 2 + 1];
    float w0 = g_tw[t * 2 + 0], w1 = g_tw[t * 2 + 1];
    float4 e0 = *(const float4*)(g_eo + (long)s0 * Dc + d4 * 4);
    float4 e1 = *(const float4*)(g_eo + (long)s1 * Dc + d4 * 4);
    float4 hv = ((const float4*)h)[i4];
    float4 sv = ((const float4*)sh)[i4];
    float4 r;
    r.x = hv.x + sv.x + w0 * e0.x + w1 * e1.x;
    r.y = hv.y + sv.y + w0 * e0.y + w1 * e1.y;
    r.z = hv.z + sv.z + w0 * e0.z + w1 * e1.z;
    r.w = hv.w + sv.w + w0 * e0.w + w1 * e1.w;
    ((float4*)out)[i4] = r;
}

// ---------------- launch ----------------
extern "C" void kernel_launch(void* const* d_in, const int* in_sizes, int n_in,
                              void* d_out, int out_size) {
    const float* x     = (const float*)d_in[0];
    const float* ln1_w = (const float*)d_in[1];
    const float* q_w   = (const float*)d_in[2];
    const float* kvd_w = (const float*)d_in[3];
    const float* kvn_w = (const float*)d_in[4];
    const float* kvu_w = (const float*)d_in[5];
    const float* o_w   = (const float*)d_in[6];
    const float* ln2_w = (const float*)d_in[7];
    const float* gate_w= (const float*)d_in[8];
    const float* sh_w1 = (const float*)d_in[9];
    const float* sh_w2 = (const float*)d_in[10];
    const float* sh_w3 = (const float*)d_in[11];
    const float* re_w1 = (const float*)d_in[12];
    const float* re_w2 = (const float*)d_in[13];
    const float* re_w3 = (const float*)d_in[14];

    float* outy = (float*)d_out;
    float* outp = outy + (long)Tc * Dc;

    __half *xnh, *lath, *attnh, *hnh, *acth, *ehacth;
    __half *wqkvh, *kvuh, *owh, *w13h, *w2h, *rw13h, *rw2h;
    float *qlat, *kvb, *hb, *hnb, *shb, *eo;
    cudaGetSymbolAddress((void**)&xnh, g_xn_h);
    cudaGetSymbolAddress((void**)&lath, g_lat_h);
    cudaGetSymbolAddress((void**)&attnh, g_attn_h);
    cudaGetSymbolAddress((void**)&hnh, g_hn_h);
    cudaGetSymbolAddress((void**)&acth, g_act_h);
    cudaGetSymbolAddress((void**)&ehacth, g_ehact_h);
    cudaGetSymbolAddress((void**)&wqkvh, g_wqkv_h);
    cudaGetSymbolAddress((void**)&kvuh, g_kvu_h);
    cudaGetSymbolAddress((void**)&owh, g_ow_h);
    cudaGetSymbolAddress((void**)&w13h, g_w13_h);
    cudaGetSymbolAddress((void**)&w2h, g_w2_h);
    cudaGetSymbolAddress((void**)&rw13h, g_rw13_h);
    cudaGetSymbolAddress((void**)&rw2h, g_rw2_h);
    cudaGetSymbolAddress((void**)&qlat, g_qlat);
    cudaGetSymbolAddress((void**)&kvb, g_kv);
    cudaGetSymbolAddress((void**)&hb, g_h);
    cudaGetSymbolAddress((void**)&hnb, g_hn);
    cudaGetSymbolAddress((void**)&shb, g_shared);
    cudaGetSymbolAddress((void**)&eo, g_eo);
    int* idxp; int* cntp;
    cudaGetSymbolAddress((void**)&idxp, g_idx);
    cudaGetSymbolAddress((void**)&cntp, g_cnt);

    cudaFuncSetAttribute((const void*)gemm_h<false, false, false, false>,
                         cudaFuncAttributeMaxDynamicSharedMemorySize, GSMEM);
    cudaFuncSetAttribute((const void*)gemm_h<false, false, true, false>,
                         cudaFuncAttributeMaxDynamicSharedMemorySize, GSMEM);
    cudaFuncSetAttribute((const void*)gemm_h<false, false, false, true>,
                         cudaFuncAttributeMaxDynamicSharedMemorySize, GSMEM);
    cudaFuncSetAttribute((const void*)gemm_h<true, true, false, true>,
                         cudaFuncAttributeMaxDynamicSharedMemorySize, GSMEM);
    cudaFuncSetAttribute((const void*)gemm_h<false, true, false, false>,
                         cudaFuncAttributeMaxDynamicSharedMemorySize, GSMEM);
    cudaFuncSetAttribute((const void*)attn_tc_kernel,
                         cudaFuncAttributeMaxDynamicSharedMemorySize, ATT_SMEM);

    // weight conversion/packing to half (8 segments)
    cvt_weights_k<<<dim3(16384, 8), 256>>>(q_w, kvd_w, kvu_w, o_w, sh_w1, sh_w2, sh_w3,
                                           re_w1, re_w2, re_w3);

    // ---- attention path ----
    rmsnorm_k<<<Tc, 256>>>(x, ln1_w, xnh, nullptr, Dc, Dc);
    gemm_h<false, false, false, false><<<dim3(5, 32, 1), 256, GSMEM>>>(
        xnh, wqkvh, qlat, nullptr, nullptr, nullptr, nullptr, Tc, 1280, 1024, 0, 0, 0, 0, 0);
    rmsnorm_k<<<Tc, 256>>>(qlat + 1024, kvn_w, lath, nullptr, Rc, 1280);
    gemm_h<false, false, false, false><<<dim3(8, 32, 1), 256, GSMEM>>>(
        lath, kvuh, kvb, nullptr, nullptr, nullptr, nullptr, Tc, 2048, 256, 0, 0, 0, 0, 0);
    attn_tc_kernel<<<dim3(Lc / 64, Hc, Bc), 128, ATT_SMEM>>>(qlat, kvb, attnh);
    gemm_h<false, false, true, false><<<dim3(4, 32, 1), 256, GSMEM>>>(
        attnh, owh, hb, x, nullptr, nullptr, nullptr, Tc, 1024, 1024, 0, 0, 0, 0, 0);

    // ---- MoE path ----
    rmsnorm_k<<<Tc, 256>>>(hb, ln2_w, hnh, hnb, Dc, Dc);
    gemm_h<false, false, false, true><<<dim3(8, 32, 1), 256, GSMEM>>>(
        hnh, w13h, nullptr, nullptr, acth, nullptr, nullptr, Tc, 2048, 1024, 0, 0, 0, 0, 0);
    gemm_h<false, false, false, false><<<dim3(4, 32, 1), 256, GSMEM>>>(
        acth, w2h, shb, nullptr, nullptr, nullptr, nullptr, Tc, 1024, 1024, 0, 0, 0, 0, 0);

    zero_cnt_k<<<1, 32>>>();
    router_kernel<<<Tc / 8, 256>>>(hnb, gate_w, outp);

    gemm_h<true, true, false, true><<<dim3(8, 32, Ec), 256, GSMEM>>>(
        hnh, rw13h, nullptr, nullptr, ehacth, idxp, cntp,
        Tc, 2048, 1024, 0, (long)1024 * 2048, 0, (long)Tc * Fc, Tc);
    gemm_h<false, true, false, false><<<dim3(4, 32, Ec), 256, GSMEM>>>(
        ehacth, rw2h, eo, nullptr, nullptr, nullptr, cntp,
        Tc, 1024, 1024, (long)Tc * Fc, (long)1024 * 1024, (long)Tc * Dc, 0, 0);

    final_kernel<<<(Tc * Dc / 4 + 255) / 256, 256>>>(hb, shb, outy);
}

// round 13
// speedup vs baseline: 3.2254x; 1.0003x over previous
#include <cuda_runtime.h>
#include <mma.h>
#include <cuda_fp16.h>
#include <math.h>
#include <stdint.h>

using namespace nvcuda;

#define Bc 2
#define Lc 2048
#define Dc 1024
#define Hc 16
#define HDc 64
#define Rc 256
#define Ec 8
#define Kc 2
#define Fc 1024
#define Tc (Bc*Lc)   // 4096

// ---------------- scratch ----------------
__device__ __half g_xn_h[Tc*Dc];
__device__ float  g_qlat[Tc*1280];
__device__ __half g_lat_h[Tc*Rc];
__device__ float  g_kv[Tc*2*Hc*HDc];
__device__ __half g_attn_h[Tc*Hc*HDc];
__device__ float  g_h[Tc*Dc];
__device__ float  g_hn[Tc*Dc];
__device__ __half g_hn_h[Tc*Dc];
__device__ __half g_act_h[Tc*Fc];
__device__ float  g_shared[Tc*Dc];
__device__ __half g_wqkv_h[Dc*1280];
__device__ __half g_kvu_h[Rc*2048];
__device__ __half g_ow_h[Dc*Dc];
__device__ __half g_w13_h[Dc*2048];              // pair-interleaved w1/w3
__device__ __half g_w2_h[Dc*Dc];
__device__ __half g_rw13_h[(long)Ec*Dc*2048];    // pair-interleaved
__device__ __half g_rw2_h[(long)Ec*Dc*Dc];
__device__ __half g_ehact_h[(long)Ec*Tc*Fc];
__device__ float  g_eo[(long)Ec*Tc*Dc];
__device__ int    g_cnt[Ec];
__device__ int    g_idx[Ec*Tc];
__device__ int    g_slot[Tc*Kc];
__device__ float  g_tw[Tc*Kc];

// ---------------- helpers ----------------
__device__ __forceinline__ void st_half4(__half* p, float a, float b, float c, float d) {
    *(__half2*)p       = __floats2half2_rn(a, b);
    *(__half2*)(p + 2) = __floats2half2_rn(c, d);
}
__device__ __forceinline__ void cp16(void* sdst, const void* g) {
    unsigned s = (unsigned)__cvta_generic_to_shared(sdst);
    asm volatile("cp.async.cg.shared.global [%0], [%1], 16;" :: "r"(s), "l"(g));
}
#define CP_COMMIT() asm volatile("cp.async.commit_group;")
#define CP_WAIT2()  asm volatile("cp.async.wait_group 2;")

// ---------------- small kernels ----------------
__global__ void zero_cnt_k() {
    if (threadIdx.x < Ec) g_cnt[threadIdx.x] = 0;
}

// convert + pack all weights to half (8 segments)
__global__ void cvt_weights_k(const float* __restrict__ q_w, const float* __restrict__ kvd_w,
                              const float* __restrict__ kvu_w, const float* __restrict__ o_w,
                              const float* __restrict__ sh_w1, const float* __restrict__ sh_w2,
                              const float* __restrict__ sh_w3,
                              const float* __restrict__ re_w1, const float* __restrict__ re_w2,
                              const float* __restrict__ re_w3) {
    int seg = blockIdx.y;
    long i = (long)blockIdx.x * blockDim.x + threadIdx.x;
    switch (seg) {
    case 0: {   // q_w -> wqkv cols 0..1023
        if (i >= (long)Dc * Dc / 4) return;
        long r = i / 256; int c4 = (int)(i % 256);
        float4 v = ((const float4*)q_w)[i];
        st_half4(g_wqkv_h + r * 1280 + c4 * 4, v.x, v.y, v.z, v.w);
        break; }
    case 1: {   // kvd_w -> wqkv cols 1024..1279
        if (i >= (long)Dc * Rc / 4) return;
        long r = i / 64; int c4 = (int)(i % 64);
        float4 v = ((const float4*)kvd_w)[i];
        st_half4(g_wqkv_h + r * 1280 + 1024 + c4 * 4, v.x, v.y, v.z, v.w);
        break; }
    case 2: {   // kvu_w plain
        if (i >= (long)Rc * 2048 / 4) return;
        float4 v = ((const float4*)kvu_w)[i];
        st_half4(g_kvu_h + i * 4, v.x, v.y, v.z, v.w);
        break; }
    case 3: {   // o_w plain
        if (i >= (long)Dc * Dc / 4) return;
        float4 v = ((const float4*)o_w)[i];
        st_half4(g_ow_h + i * 4, v.x, v.y, v.z, v.w);
        break; }
    case 4: {   // sh_w2 plain
        if (i >= (long)Dc * Dc / 4) return;
        float4 v = ((const float4*)sh_w2)[i];
        st_half4(g_w2_h + i * 4, v.x, v.y, v.z, v.w);
        break; }
    case 5: {   // re_w2 plain (x8)
        if (i >= (long)Ec * Dc * Dc / 4) return;
        float4 v = ((const float4*)re_w2)[i];
        st_half4(g_rw2_h + i * 4, v.x, v.y, v.z, v.w);
        break; }
    case 6: {   // sh_w1/sh_w3 interleave
        if (i >= (long)Dc * Fc / 2) return;
        long r = i / 512; int j2 = (int)(i % 512);
        float2 a = ((const float2*)sh_w1)[r * 512 + j2];
        float2 b = ((const float2*)sh_w3)[r * 512 + j2];
        st_half4(g_w13_h + r * 2048 + j2 * 4, a.x, b.x, a.y, b.y);
        break; }
    default: {  // re_w1/re_w3 interleave (x8)
        if (i >= (long)Ec * Dc * Fc / 2) return;
        long r = i / 512; int j2 = (int)(i % 512);
        float2 a = ((const float2*)re_w1)[r * 512 + j2];
        float2 b = ((const float2*)re_w3)[r * 512 + j2];
        st_half4(g_rw13_h + r * 2048 + j2 * 4, a.x, b.x, a.y, b.y);
        break; }
    }
}

// rmsnorm: always writes half output (stride = dim); optionally fp32 too
__global__ void rmsnorm_k(const float* __restrict__ x, const float* __restrict__ w,
                          __half* __restrict__ oh, float* __restrict__ of,
                          int dim, int xs) {
    int row = blockIdx.x;
    int tid = threadIdx.x;
    const float* xr = x + (long)row * xs;
    float s = 0.f;
    for (int d = tid; d < dim; d += blockDim.x) { float v = xr[d]; s += v * v; }
    __shared__ float red[256];
    red[tid] = s;
    __syncthreads();
    for (int off = 128; off > 0; off >>= 1) {
        if (tid < off) red[tid] += red[tid + off];
        __syncthreads();
    }
    float inv = rsqrtf(red[0] / (float)dim + 1e-6f);
    __half* ohr = oh + (long)row * dim;
    float* ofr = of ? of + (long)row * dim : nullptr;
    for (int d = tid; d < dim; d += blockDim.x) {
        float v = w[d] * xr[d] * inv;
        ohr[d] = __float2half_rn(v);
        if (of) ofr[d] = v;
    }
}

// ---------------- fp16 TC GEMM: 128x256 tile, m16n16k16, 4-stage cp.async, fused SiLU ----------------
#define BM 128
#define BN 256
#define BK 32
#define ASTH 40                 // halfs
#define BSTH 264
#define SMAH (BM*ASTH)          // 5120 halfs
#define SMBH (BK*BSTH)          // 8448 halfs
#define STGH (SMAH+SMBH)        // 13568 halfs = 27136 B
#define NSTAGE 4
#define EPST 68
#define GSMEM 139264            // max(4*27136=108544, 512*68*4=139264)

template<bool GATHER, bool HAS_CNT, bool RESID, bool SILU>
__global__ void __launch_bounds__(256)
gemm_h(const __half* __restrict__ A, const __half* __restrict__ Bw,
       float* __restrict__ C, const float* __restrict__ resid,
       __half* __restrict__ actOut,
       const int* __restrict__ gidx, const int* __restrict__ cntp,
       int M, int N, int Kd,
       long aEs, long bEs, long cEs, long actEs, int iEs) {
    extern __shared__ char smx[];

    int e = blockIdx.z;
    A += (long)e * aEs;
    Bw += (long)e * bEs;
    int Me = HAS_CNT ? cntp[e] : M;
    int bm = blockIdx.y * BM, bn = blockIdx.x * BN;
    if (bm >= Me) return;

    const int tid = threadIdx.x;
    const int warpId = tid >> 5;
    const int wm = warpId >> 2;        // 0..1
    const int wn = warpId & 3;         // 0..3

    // A: 128 rows x 32 halfs = 512 16B-chunks; 2 per thread (rows r, r+64)
    const int ar0 = tid >> 2;          // 0..63
    const int ac8 = (tid & 3) * 8;
    // B: 32 rows x 256 halfs = 1024 chunks; 4 per thread
    const int br0 = tid >> 5;          // 0..7
    const int bc8 = (tid & 31) * 8;

    long aBase[2];
    int aS[2];
    #pragma unroll
    for (int i = 0; i < 2; i++) {
        int row = ar0 + 64 * i;
        int am = bm + row;
        long ar;
        if (GATHER) {
            int g = gidx[e * iEs + am];
            if (g < 0 || g >= Tc) g = 0;
            ar = (long)g * Kd;
        } else ar = (long)am * Kd;
        aBase[i] = ar + ac8;
        aS[i] = row * ASTH + ac8;
    }
    long bOff[4];
    int bS[4];
    #pragma unroll
    for (int i = 0; i < 4; i++) {
        int row = br0 + 8 * i;
        bOff[i] = (long)row * N + bn + bc8;
        bS[i] = row * BSTH + bc8;
    }

    wmma::fragment<wmma::accumulator, 16, 16, 16, float> cf[4][4];
    if (RESID) {
        #pragma unroll
        for (int i = 0; i < 4; i++)
            #pragma unroll
            for (int j = 0; j < 4; j++)
                wmma::load_matrix_sync(cf[i][j],
                    resid + (long)(bm + wm * 64 + i * 16) * N + bn + wn * 64 + j * 16,
                    N, wmma::mem_row_major);
    } else {
        #pragma unroll
        for (int i = 0; i < 4; i++)
            #pragma unroll
            for (int j = 0; j < 4; j++)
                wmma::fill_fragment(cf[i][j], 0.f);
    }

    const int T = Kd / BK;

    auto load_tile = [&](int t, int s) {
        __half* As_ = (__half*)smx + s * STGH;
        __half* Bs_ = As_ + SMAH;
        int k0 = t * BK;
        #pragma unroll
        for (int i = 0; i < 2; i++)
            cp16(As_ + aS[i], A + aBase[i] + k0);
        #pragma unroll
        for (int i = 0; i < 4; i++)
            cp16(Bs_ + bS[i], Bw + (long)k0 * N + bOff[i]);
    };

    load_tile(0, 0);
    CP_COMMIT();
    if (T > 1) load_tile(1, 1);
    CP_COMMIT();

    for (int t = 0; t < T; t++) {
        if (t + 2 < T) load_tile(t + 2, (t + 2) & 3);
        CP_COMMIT();
        CP_WAIT2();
        __syncthreads();

        int s = t & 3;
        const __half* As_ = (const __half*)smx + s * STGH;
        const __half* Bs_ = As_ + SMAH;
        #pragma unroll
        for (int kk = 0; kk < 2; kk++) {
            wmma::fragment<wmma::matrix_a, 16, 16, 16, __half, wmma::row_major> af[4];
            wmma::fragment<wmma::matrix_b, 16, 16, 16, __half, wmma::row_major> bf[4];
            #pragma unroll
            for (int i = 0; i < 4; i++)
                wmma::load_matrix_sync(af[i], &As_[(wm * 64 + i * 16) * ASTH + kk * 16], ASTH);
            #pragma unroll
            for (int j = 0; j < 4; j++)
                wmma::load_matrix_sync(bf[j], &Bs_[(kk * 16) * BSTH + wn * 64 + j * 16], BSTH);
            #pragma unroll
            for (int i = 0; i < 4; i++)
                #pragma unroll
                for (int j = 0; j < 4; j++)
                    wmma::mma_sync(cf[i][j], af[i], bf[j], cf[i][j]);
        }
        // no trailing sync: 4 stages, prefetch distance 2 -> no WAR hazard
    }

    if (SILU) {
        __syncthreads();
        float* St = (float*)smx;
        #pragma unroll
        for (int i = 0; i < 4; i++)
            #pragma unroll
            for (int j = 0; j < 4; j++)
                wmma::store_matrix_sync(&St[((warpId * 64) + i * 16) * EPST + j * 16],
                                        cf[i][j], EPST, wmma::mem_row_major);
        __syncthreads();
        int r = tid >> 1;
        int co0 = (tid & 1) * 64;
        int wmr = r >> 6, wr = r & 63;
        long obase = (long)e * actEs + (long)(bm + r) * (N >> 1) + (bn >> 1) + co0;
        #pragma unroll 4
        for (int c = 0; c < 64; c += 4) {
            int bc0 = 2 * (co0 + c);
            int wnn = bc0 >> 6, wc = bc0 & 63;
            const float* p = &St[((wmr * 4 + wnn) * 64 + wr) * EPST + wc];
            float4 p0 = *(const float4*)(p);
            float4 p1 = *(const float4*)(p + 4);
            st_half4(actOut + obase + c,
                     p0.x / (1.f + expf(-p0.x)) * p0.y,
                     p0.z / (1.f + expf(-p0.z)) * p0.w,
                     p1.x / (1.f + expf(-p1.x)) * p1.y,
                     p1.z / (1.f + expf(-p1.z)) * p1.w);
        }
    } else {
        C += (long)e * cEs;
        #pragma unroll
        for (int i = 0; i < 4; i++)
            #pragma unroll
            for (int j = 0; j < 4; j++)
                wmma::store_matrix_sync(
                    C + (long)(bm + wm * 64 + i * 16) * N + bn + wn * 64 + j * 16,
                    cf[i][j], N, wmma::mem_row_major);
    }
}

// ---------------- tensor-core causal flash attention (tf32 wmma; half output) ----------------
#define ATSTR 72
#define ATT_SMEM ((5*64*ATSTR + 3*64)*4)

__global__ void __launch_bounds__(128)
attn_tc_kernel(const float* __restrict__ q, const float* __restrict__ kv,
               __half* __restrict__ o) {
    extern __shared__ float smema[];
    float* Qs = smema;
    float* Ks = Qs + 64 * ATSTR;
    float* Vs = Ks + 64 * ATSTR;
    float* Ss = Vs + 64 * ATSTR;
    float* Os = Ss + 64 * ATSTR;
    float* mrow = Os + 64 * ATSTR;
    float* lrow = mrow + 64;
    float* crow = lrow + 64;

    const int b = blockIdx.z, h = blockIdx.y, iq = blockIdx.x;
    const int q0 = iq * 64;
    const int tid = threadIdx.x;
    const int warpId = tid >> 5;

    {
        int j = tid >> 1, d0 = (tid & 1) * 32;
        long qb = ((long)(b * Lc + q0 + j)) * 1280 + h * HDc;
        #pragma unroll
        for (int dd = 0; dd < 32; dd += 4) {
            float4 v = *(const float4*)(q + qb + d0 + dd);
            Qs[j * ATSTR + d0 + dd + 0] = v.x * 0.125f;
            Qs[j * ATSTR + d0 + dd + 1] = v.y * 0.125f;
            Qs[j * ATSTR + d0 + dd + 2] = v.z * 0.125f;
            Qs[j * ATSTR + d0 + dd + 3] = v.w * 0.125f;
            Os[j * ATSTR + d0 + dd + 0] = 0.f;
            Os[j * ATSTR + d0 + dd + 1] = 0.f;
            Os[j * ATSTR + d0 + dd + 2] = 0.f;
            Os[j * ATSTR + d0 + dd + 3] = 0.f;
        }
        if (tid < 64) { mrow[tid] = -INFINITY; lrow[tid] = 0.f; }
    }
    __syncthreads();

    for (int kt = 0; kt <= q0; kt += 64) {
        {
            int j = tid >> 1, d0 = (tid & 1) * 32;
            long kvb = ((long)(b * Lc + kt + j)) * (2 * Hc * HDc) + h * HDc;
            #pragma unroll
            for (int dd = 0; dd < 32; dd += 4) {
                *(float4*)&Ks[j * ATSTR + d0 + dd] = *(const float4*)(kv + kvb + d0 + dd);
                *(float4*)&Vs[j * ATSTR + d0 + dd] = *(const float4*)(kv + kvb + Hc * HDc + d0 + dd);
            }
        }
        __syncthreads();

        {
            wmma::fragment<wmma::accumulator, 16, 16, 8, float> sf[4];
            #pragma unroll
            for (int n = 0; n < 4; n++) wmma::fill_fragment(sf[n], 0.f);
            #pragma unroll
            for (int kk = 0; kk < 8; kk++) {
                wmma::fragment<wmma::matrix_a, 16, 16, 8, wmma::precision::tf32, wmma::row_major> aq;
                wmma::load_matrix_sync(aq, &Qs[(warpId * 16) * ATSTR + kk * 8], ATSTR);
                #pragma unroll
                for (int n = 0; n < 4; n++) {
                    wmma::fragment<wmma::matrix_b, 16, 16, 8, wmma::precision::tf32, wmma::col_major> bk;
                    wmma::load_matrix_sync(bk, &Ks[(n * 16) * ATSTR + kk * 8], ATSTR);
                    wmma::mma_sync(sf[n], aq, bk, sf[n]);
                }
            }
            #pragma unroll
            for (int n = 0; n < 4; n++)
                wmma::store_matrix_sync(&Ss[(warpId * 16) * ATSTR + n * 16], sf[n], ATSTR, wmma::mem_row_major);
        }
        __syncthreads();

        if (tid < 64) {
            int r = tid;
            int vmax = (kt == q0) ? (r + 1) : 64;
            float mx = -INFINITY;
            for (int c = 0; c < vmax; c++) mx = fmaxf(mx, Ss[r * ATSTR + c]);
            float nm = fmaxf(mrow[r], mx);
            float corr = __expf(mrow[r] - nm);
            float sum = 0.f;
            for (int c = 0; c < vmax; c++) {
                float p = __expf(Ss[r * ATSTR + c] - nm);
                Ss[r * ATSTR + c] = p;
                sum += p;
            }
            for (int c = vmax; c < 64; c++) Ss[r * ATSTR + c] = 0.f;
            lrow[r] = lrow[r] * corr + sum;
            mrow[r] = nm;
            crow[r] = corr;
        }
        __syncthreads();

        {
            int r = tid >> 1, c0 = (tid & 1) * 32;
            float corr = crow[r];
            #pragma unroll
            for (int c = 0; c < 32; c++) Os[r * ATSTR + c0 + c] *= corr;
        }
        __syncthreads();

        {
            wmma::fragment<wmma::accumulator, 16, 16, 8, float> of[4];
            #pragma unroll
            for (int n = 0; n < 4; n++)
                wmma::load_matrix_sync(of[n], &Os[(warpId * 16) * ATSTR + n * 16], ATSTR, wmma::mem_row_major);
            #pragma unroll
            for (int kk = 0; kk < 8; kk++) {
                wmma::fragment<wmma::matrix_a, 16, 16, 8, wmma::precision::tf32, wmma::row_major> ap;
                wmma::load_matrix_sync(ap, &Ss[(warpId * 16) * ATSTR + kk * 8], ATSTR);
                #pragma unroll
                for (int n = 0; n < 4; n++) {
                    wmma::fragment<wmma::matrix_b, 16, 16, 8, wmma::precision::tf32, wmma::row_major> bv;
                    wmma::load_matrix_sync(bv, &Vs[(kk * 8) * ATSTR + n * 16], ATSTR);
                    wmma::mma_sync(of[n], ap, bv, of[n]);
                }
            }
            #pragma unroll
            for (int n = 0; n < 4; n++)
                wmma::store_matrix_sync(&Os[(warpId * 16) * ATSTR + n * 16], of[n], ATSTR, wmma::mem_row_major);
        }
        __syncthreads();
    }

    {
        int r = tid >> 1, c0 = (tid & 1) * 32;
        float inv = 1.f / lrow[r];
        long ob = ((long)(b * Lc + q0 + r)) * (Hc * HDc) + h * HDc + c0;
        #pragma unroll
        for (int c = 0; c < 32; c += 4) {
            st_half4(o + ob + c,
                     Os[r * ATSTR + c0 + c + 0] * inv,
                     Os[r * ATSTR + c0 + c + 1] * inv,
                     Os[r * ATSTR + c0 + c + 2] * inv,
                     Os[r * ATSTR + c0 + c + 3] * inv);
        }
    }
}

// ---------------- router (fp32 hn) ----------------
__global__ void router_kernel(const float* __restrict__ hn, const float* __restrict__ gw,
                              float* __restrict__ probs_out) {
    int warp = (blockIdx.x * blockDim.x + threadIdx.x) >> 5;
    int lane = threadIdx.x & 31;
    if (warp >= Tc) return;
    const float* row = hn + (long)warp * Dc;
    float acc[8] = {0, 0, 0, 0, 0, 0, 0, 0};
    for (int d = lane; d < Dc; d += 32) {
        float xv = row[d];
        const float* g = gw + d * 8;
        #pragma unroll
        for (int e = 0; e < 8; e++) acc[e] += xv * g[e];
    }
    #pragma unroll
    for (int e = 0; e < 8; e++)
        #pragma unroll
        for (int off = 16; off > 0; off >>= 1)
            acc[e] += __shfl_xor_sync(0xffffffffu, acc[e], off);

    if (lane == 0) {
        float mx = acc[0];
        #pragma unroll
        for (int e = 1; e < 8; e++) mx = fmaxf(mx, acc[e]);
        float p[8], s = 0.f;
        #pragma unroll
        for (int e = 0; e < 8; e++) { p[e] = expf(acc[e] - mx); s += p[e]; }
        float invs = 1.f / s;
        #pragma unroll
        for (int e = 0; e < 8; e++) { p[e] *= invs; probs_out[(long)warp * 8 + e] = p[e]; }
        int i1 = 0;
        #pragma unroll
        for (int e = 1; e < 8; e++) if (p[e] > p[i1]) i1 = e;
        int i2 = (i1 == 0) ? 1 : 0;
        #pragma unroll
        for (int e = 0; e < 8; e++) if (e != i1 && p[e] > p[i2]) i2 = e;
        float w1 = p[i1], w2 = p[i2];
        float inv2 = 1.f / (w1 + w2);
        w1 *= inv2; w2 *= inv2;
        int pos1 = atomicAdd(&g_cnt[i1], 1);
        g_idx[i1 * Tc + pos1] = warp;
        g_slot[warp * 2 + 0] = i1 * Tc + pos1;
        g_tw[warp * 2 + 0] = w1;
        int pos2 = atomicAdd(&g_cnt[i2], 1);
        g_idx[i2 * Tc + pos2] = warp;
        g_slot[warp * 2 + 1] = i2 * Tc + pos2;
        g_tw[warp * 2 + 1] = w2;
    }
}

// ---------------- final combine ----------------
__global__ void final_kernel(const float* __restrict__ h, const float* __restrict__ sh,
                             float* __restrict__ out) {
    long i4 = (long)blockIdx.x * blockDim.x + threadIdx.x;
    if (i4 >= (long)Tc * Dc / 4) return;
    int t = (int)(i4 / (Dc / 4));
    int d4 = (int)(i4 % (Dc / 4));
    int s0 = g_slot[t * 2 + 0], s1 = g_slot[t * 2 + 1];
    float w0 = g_tw[t * 2 + 0], w1 = g_tw[t * 2 + 1];
    float4 e0 = *(const float4*)(g_eo + (long)s0 * Dc + d4 * 4);
    float4 e1 = *(const float4*)(g_eo + (long)s1 * Dc + d4 * 4);
    float4 hv = ((const float4*)h)[i4];
    float4 sv = ((const float4*)sh)[i4];
    float4 r;
    r.x = hv.x + sv.x + w0 * e0.x + w1 * e1.x;
    r.y = hv.y + sv.y + w0 * e0.y + w1 * e1.y;
    r.z = hv.z + sv.z + w0 * e0.z + w1 * e1.z;
    r.w = hv.w + sv.w + w0 * e0.w + w1 * e1.w;
    ((float4*)out)[i4] = r;
}

// ---------------- launch ----------------
extern "C" void kernel_launch(void* const* d_in, const int* in_sizes, int n_in,
                              void* d_out, int out_size) {
    const float* x     = (const float*)d_in[0];
    const float* ln1_w = (const float*)d_in[1];
    const float* q_w   = (const float*)d_in[2];
    const float* kvd_w = (const float*)d_in[3];
    const float* kvn_w = (const float*)d_in[4];
    const float* kvu_w = (const float*)d_in[5];
    const float* o_w   = (const float*)d_in[6];
    const float* ln2_w = (const float*)d_in[7];
    const float* gate_w= (const float*)d_in[8];
    const float* sh_w1 = (const float*)d_in[9];
    const float* sh_w2 = (const float*)d_in[10];
    const float* sh_w3 = (const float*)d_in[11];
    const float* re_w1 = (const float*)d_in[12];
    const float* re_w2 = (const float*)d_in[13];
    const float* re_w3 = (const float*)d_in[14];

    float* outy = (float*)d_out;
    float* outp = outy + (long)Tc * Dc;

    __half *xnh, *lath, *attnh, *hnh, *acth, *ehacth;
    __half *wqkvh, *kvuh, *owh, *w13h, *w2h, *rw13h, *rw2h;
    float *qlat, *kvb, *hb, *hnb, *shb, *eo;
    cudaGetSymbolAddress((void**)&xnh, g_xn_h);
    cudaGetSymbolAddress((void**)&lath, g_lat_h);
    cudaGetSymbolAddress((void**)&attnh, g_attn_h);
    cudaGetSymbolAddress((void**)&hnh, g_hn_h);
    cudaGetSymbolAddress((void**)&acth, g_act_h);
    cudaGetSymbolAddress((void**)&ehacth, g_ehact_h);
    cudaGetSymbolAddress((void**)&wqkvh, g_wqkv_h);
    cudaGetSymbolAddress((void**)&kvuh, g_kvu_h);
    cudaGetSymbolAddress((void**)&owh, g_ow_h);
    cudaGetSymbolAddress((void**)&w13h, g_w13_h);
    cudaGetSymbolAddress((void**)&w2h, g_w2_h);
    cudaGetSymbolAddress((void**)&rw13h, g_rw13_h);
    cudaGetSymbolAddress((void**)&rw2h, g_rw2_h);
    cudaGetSymbolAddress((void**)&qlat, g_qlat);
    cudaGetSymbolAddress((void**)&kvb, g_kv);
    cudaGetSymbolAddress((void**)&hb, g_h);
    cudaGetSymbolAddress((void**)&hnb, g_hn);
    cudaGetSymbolAddress((void**)&shb, g_shared);
    cudaGetSymbolAddress((void**)&eo, g_eo);
    int* idxp; int* cntp;
    cudaGetSymbolAddress((void**)&idxp, g_idx);
    cudaGetSymbolAddress((void**)&cntp, g_cnt);

    cudaFuncSetAttribute((const void*)gemm_h<false, false, false, false>,
                         cudaFuncAttributeMaxDynamicSharedMemorySize, GSMEM);
    cudaFuncSetAttribute((const void*)gemm_h<false, false, true, false>,
                         cudaFuncAttributeMaxDynamicSharedMemorySize, GSMEM);
    cudaFuncSetAttribute((const void*)gemm_h<false, false, false, true>,
                         cudaFuncAttributeMaxDynamicSharedMemorySize, GSMEM);
    cudaFuncSetAttribute((const void*)gemm_h<true, true, false, true>,
                         cudaFuncAttributeMaxDynamicSharedMemorySize, GSMEM);
    cudaFuncSetAttribute((const void*)gemm_h<false, true, false, false>,
                         cudaFuncAttributeMaxDynamicSharedMemorySize, GSMEM);
    cudaFuncSetAttribute((const void*)attn_tc_kernel,
                         cudaFuncAttributeMaxDynamicSharedMemorySize, ATT_SMEM);

    // weight conversion/packing to half (8 segments)
    cvt_weights_k<<<dim3(16384, 8), 256>>>(q_w, kvd_w, kvu_w, o_w, sh_w1, sh_w2, sh_w3,
                                           re_w1, re_w2, re_w3);

    // ---- attention path ----
    rmsnorm_k<<<Tc, 256>>>(x, ln1_w, xnh, nullptr, Dc, Dc);
    gemm_h<false, false, false, false><<<dim3(5, 32, 1), 256, GSMEM>>>(
        xnh, wqkvh, qlat, nullptr, nullptr, nullptr, nullptr, Tc, 1280, 1024, 0, 0, 0, 0, 0);
    rmsnorm_k<<<Tc, 256>>>(qlat + 1024, kvn_w, lath, nullptr, Rc, 1280);
    gemm_h<false, false, false, false><<<dim3(8, 32, 1), 256, GSMEM>>>(
        lath, kvuh, kvb, nullptr, nullptr, nullptr, nullptr, Tc, 2048, 256, 0, 0, 0, 0, 0);
    attn_tc_kernel<<<dim3(Lc / 64, Hc, Bc), 128, ATT_SMEM>>>(qlat, kvb, attnh);
    gemm_h<false, false, true, false><<<dim3(4, 32, 1), 256, GSMEM>>>(
        attnh, owh, hb, x, nullptr, nullptr, nullptr, Tc, 1024, 1024, 0, 0, 0, 0, 0);

    // ---- MoE path ----
    rmsnorm_k<<<Tc, 256>>>(hb, ln2_w, hnh, hnb, Dc, Dc);
    gemm_h<false, false, false, true><<<dim3(8, 32, 1), 256, GSMEM>>>(
        hnh, w13h, nullptr, nullptr, acth, nullptr, nullptr, Tc, 2048, 1024, 0, 0, 0, 0, 0);
    gemm_h<false, false, false, false><<<dim3(4, 32, 1), 256, GSMEM>>>(
        acth, w2h, shb, nullptr, nullptr, nullptr, nullptr, Tc, 1024, 1024, 0, 0, 0, 0, 0);

    zero_cnt_k<<<1, 32>>>();
    router_kernel<<<Tc / 8, 256>>>(hnb, gate_w, outp);

    gemm_h<true, true, false, true><<<dim3(8, 32, Ec), 256, GSMEM>>>(
        hnh, rw13h, nullptr, nullptr, ehacth, idxp, cntp,
        Tc, 2048, 1024, 0, (long)1024 * 2048, 0, (long)Tc * Fc, Tc);
    gemm_h<false, true, false, false><<<dim3(4, 32, Ec), 256, GSMEM>>>(
        ehacth, rw2h, eo, nullptr, nullptr, nullptr, cntp,
        Tc, 1024, 1024, (long)Tc * Fc, (long)1024 * 1024, (long)Tc * Dc, 0, 0);

    final_kernel<<<(Tc * Dc / 4 + 255) / 256, 256>>>(hb, shb, outy);
}

// round 14
// speedup vs baseline: 4.1922x; 1.2998x over previous
#include <cuda_runtime.h>
#include <mma.h>
#include <cuda_fp16.h>
#include <math.h>
#include <stdint.h>

using namespace nvcuda;

#define Bc 2
#define Lc 2048
#define Dc 1024
#define Hc 16
#define HDc 64
#define Rc 256
#define Ec 8
#define Kc 2
#define Fc 1024
#define Tc (Bc*Lc)   // 4096

// ---------------- scratch ----------------
__device__ __half g_xn_h[Tc*Dc];
__device__ float  g_qlat[Tc*1280];
__device__ __half g_lat_h[Tc*Rc];
__device__ __half g_kv_h[Tc*2*Hc*HDc];
__device__ __half g_attn_h[Tc*Hc*HDc];
__device__ float  g_h[Tc*Dc];
__device__ float  g_hn[Tc*Dc];
__device__ __half g_hn_h[Tc*Dc];
__device__ __half g_act_h[Tc*Fc];
__device__ float  g_shared[Tc*Dc];
__device__ __half g_wqkv_h[Dc*1280];
__device__ __half g_kvu_h[Rc*2048];
__device__ __half g_ow_h[Dc*Dc];
__device__ __half g_w13_h[Dc*2048];              // pair-interleaved w1/w3
__device__ __half g_w2_h[Dc*Dc];
__device__ __half g_rw13_h[(long)Ec*Dc*2048];    // pair-interleaved
__device__ __half g_rw2_h[(long)Ec*Dc*Dc];
__device__ __half g_ehact_h[(long)Ec*Tc*Fc];
__device__ float  g_eo[(long)Ec*Tc*Dc];
__device__ int    g_cnt[Ec];
__device__ int    g_idx[Ec*Tc];
__device__ int    g_slot[Tc*Kc];
__device__ float  g_tw[Tc*Kc];

// ---------------- helpers ----------------
__device__ __forceinline__ void st_half4(__half* p, float a, float b, float c, float d) {
    *(__half2*)p       = __floats2half2_rn(a, b);
    *(__half2*)(p + 2) = __floats2half2_rn(c, d);
}
__device__ __forceinline__ void cp16(void* sdst, const void* g) {
    unsigned s = (unsigned)__cvta_generic_to_shared(sdst);
    asm volatile("cp.async.cg.shared.global [%0], [%1], 16;" :: "r"(s), "l"(g));
}
#define CP_COMMIT() asm volatile("cp.async.commit_group;")
#define CP_WAIT2()  asm volatile("cp.async.wait_group 2;")

// ---------------- small kernels ----------------
__global__ void zero_cnt_k() {
    if (threadIdx.x < Ec) g_cnt[threadIdx.x] = 0;
}

// convert + pack all weights to half (8 segments)
__global__ void cvt_weights_k(const float* __restrict__ q_w, const float* __restrict__ kvd_w,
                              const float* __restrict__ kvu_w, const float* __restrict__ o_w,
                              const float* __restrict__ sh_w1, const float* __restrict__ sh_w2,
                              const float* __restrict__ sh_w3,
                              const float* __restrict__ re_w1, const float* __restrict__ re_w2,
                              const float* __restrict__ re_w3) {
    int seg = blockIdx.y;
    long i = (long)blockIdx.x * blockDim.x + threadIdx.x;
    switch (seg) {
    case 0: {
        if (i >= (long)Dc * Dc / 4) return;
        long r = i / 256; int c4 = (int)(i % 256);
        float4 v = ((const float4*)q_w)[i];
        st_half4(g_wqkv_h + r * 1280 + c4 * 4, v.x, v.y, v.z, v.w);
        break; }
    case 1: {
        if (i >= (long)Dc * Rc / 4) return;
        long r = i / 64; int c4 = (int)(i % 64);
        float4 v = ((const float4*)kvd_w)[i];
        st_half4(g_wqkv_h + r * 1280 + 1024 + c4 * 4, v.x, v.y, v.z, v.w);
        break; }
    case 2: {
        if (i >= (long)Rc * 2048 / 4) return;
        float4 v = ((const float4*)kvu_w)[i];
        st_half4(g_kvu_h + i * 4, v.x, v.y, v.z, v.w);
        break; }
    case 3: {
        if (i >= (long)Dc * Dc / 4) return;
        float4 v = ((const float4*)o_w)[i];
        st_half4(g_ow_h + i * 4, v.x, v.y, v.z, v.w);
        break; }
    case 4: {
        if (i >= (long)Dc * Dc / 4) return;
        float4 v = ((const float4*)sh_w2)[i];
        st_half4(g_w2_h + i * 4, v.x, v.y, v.z, v.w);
        break; }
    case 5: {
        if (i >= (long)Ec * Dc * Dc / 4) return;
        float4 v = ((const float4*)re_w2)[i];
        st_half4(g_rw2_h + i * 4, v.x, v.y, v.z, v.w);
        break; }
    case 6: {
        if (i >= (long)Dc * Fc / 2) return;
        long r = i / 512; int j2 = (int)(i % 512);
        float2 a = ((const float2*)sh_w1)[r * 512 + j2];
        float2 b = ((const float2*)sh_w3)[r * 512 + j2];
        st_half4(g_w13_h + r * 2048 + j2 * 4, a.x, b.x, a.y, b.y);
        break; }
    default: {
        if (i >= (long)Ec * Dc * Fc / 2) return;
        long r = i / 512; int j2 = (int)(i % 512);
        float2 a = ((const float2*)re_w1)[r * 512 + j2];
        float2 b = ((const float2*)re_w3)[r * 512 + j2];
        st_half4(g_rw13_h + r * 2048 + j2 * 4, a.x, b.x, a.y, b.y);
        break; }
    }
}

// rmsnorm: half output always, fp32 optional
__global__ void rmsnorm_k(const float* __restrict__ x, const float* __restrict__ w,
                          __half* __restrict__ oh, float* __restrict__ of,
                          int dim, int xs) {
    int row = blockIdx.x;
    int tid = threadIdx.x;
    const float* xr = x + (long)row * xs;
    float s = 0.f;
    for (int d = tid; d < dim; d += blockDim.x) { float v = xr[d]; s += v * v; }
    __shared__ float red[256];
    red[tid] = s;
    __syncthreads();
    for (int off = 128; off > 0; off >>= 1) {
        if (tid < off) red[tid] += red[tid + off];
        __syncthreads();
    }
    float inv = rsqrtf(red[0] / (float)dim + 1e-6f);
    __half* ohr = oh + (long)row * dim;
    float* ofr = of ? of + (long)row * dim : nullptr;
    for (int d = tid; d < dim; d += blockDim.x) {
        float v = w[d] * xr[d] * inv;
        ohr[d] = __float2half_rn(v);
        if (of) ofr[d] = v;
    }
}

// ---------------- fp16 TC GEMM: 128x256 tile, m16n16k16, 4-stage cp.async ----------------
// EPI: 0 = fp32 C (+opt resid), 1 = silu-pair -> half, 2 = plain -> half
#define BM 128
#define BN 256
#define BK 32
#define ASTH 40
#define BSTH 264
#define SMAH (BM*ASTH)
#define SMBH (BK*BSTH)
#define STGH (SMAH+SMBH)
#define EPST 68
#define GSMEM 139264

template<bool GATHER, bool HAS_CNT, bool RESID, int EPI>
__global__ void __launch_bounds__(256)
gemm_h(const __half* __restrict__ A, const __half* __restrict__ Bw,
       float* __restrict__ C, const float* __restrict__ resid,
       __half* __restrict__ actOut,
       const int* __restrict__ gidx, const int* __restrict__ cntp,
       int M, int N, int Kd,
       long aEs, long bEs, long cEs, long actEs, int iEs) {
    extern __shared__ char smx[];

    int e = blockIdx.z;
    A += (long)e * aEs;
    Bw += (long)e * bEs;
    int Me = HAS_CNT ? cntp[e] : M;
    int bm = blockIdx.y * BM, bn = blockIdx.x * BN;
    if (bm >= Me) return;

    const int tid = threadIdx.x;
    const int warpId = tid >> 5;
    const int wm = warpId >> 2;
    const int wn = warpId & 3;

    const int ar0 = tid >> 2;
    const int ac8 = (tid & 3) * 8;
    const int br0 = tid >> 5;
    const int bc8 = (tid & 31) * 8;

    long aBase[2];
    int aS[2];
    #pragma unroll
    for (int i = 0; i < 2; i++) {
        int row = ar0 + 64 * i;
        int am = bm + row;
        long ar;
        if (GATHER) {
            int g = gidx[e * iEs + am];
            if (g < 0 || g >= Tc) g = 0;
            ar = (long)g * Kd;
        } else ar = (long)am * Kd;
        aBase[i] = ar + ac8;
        aS[i] = row * ASTH + ac8;
    }
    long bOff[4];
    int bS[4];
    #pragma unroll
    for (int i = 0; i < 4; i++) {
        int row = br0 + 8 * i;
        bOff[i] = (long)row * N + bn + bc8;
        bS[i] = row * BSTH + bc8;
    }

    wmma::fragment<wmma::accumulator, 16, 16, 16, float> cf[4][4];
    if (RESID) {
        #pragma unroll
        for (int i = 0; i < 4; i++)
            #pragma unroll
            for (int j = 0; j < 4; j++)
                wmma::load_matrix_sync(cf[i][j],
                    resid + (long)(bm + wm * 64 + i * 16) * N + bn + wn * 64 + j * 16,
                    N, wmma::mem_row_major);
    } else {
        #pragma unroll
        for (int i = 0; i < 4; i++)
            #pragma unroll
            for (int j = 0; j < 4; j++)
                wmma::fill_fragment(cf[i][j], 0.f);
    }

    const int T = Kd / BK;

    auto load_tile = [&](int t, int s) {
        __half* As_ = (__half*)smx + s * STGH;
        __half* Bs_ = As_ + SMAH;
        int k0 = t * BK;
        #pragma unroll
        for (int i = 0; i < 2; i++)
            cp16(As_ + aS[i], A + aBase[i] + k0);
        #pragma unroll
        for (int i = 0; i < 4; i++)
            cp16(Bs_ + bS[i], Bw + (long)k0 * N + bOff[i]);
    };

    load_tile(0, 0);
    CP_COMMIT();
    if (T > 1) load_tile(1, 1);
    CP_COMMIT();

    for (int t = 0; t < T; t++) {
        if (t + 2 < T) load_tile(t + 2, (t + 2) & 3);
        CP_COMMIT();
        CP_WAIT2();
        __syncthreads();

        int s = t & 3;
        const __half* As_ = (const __half*)smx + s * STGH;
        const __half* Bs_ = As_ + SMAH;
        #pragma unroll
        for (int kk = 0; kk < 2; kk++) {
            wmma::fragment<wmma::matrix_a, 16, 16, 16, __half, wmma::row_major> af[4];
            wmma::fragment<wmma::matrix_b, 16, 16, 16, __half, wmma::row_major> bf[4];
            #pragma unroll
            for (int i = 0; i < 4; i++)
                wmma::load_matrix_sync(af[i], &As_[(wm * 64 + i * 16) * ASTH + kk * 16], ASTH);
            #pragma unroll
            for (int j = 0; j < 4; j++)
                wmma::load_matrix_sync(bf[j], &Bs_[(kk * 16) * BSTH + wn * 64 + j * 16], BSTH);
            #pragma unroll
            for (int i = 0; i < 4; i++)
                #pragma unroll
                for (int j = 0; j < 4; j++)
                    wmma::mma_sync(cf[i][j], af[i], bf[j], cf[i][j]);
        }
    }

    if (EPI >= 1) {
        __syncthreads();
        float* St = (float*)smx;
        #pragma unroll
        for (int i = 0; i < 4; i++)
            #pragma unroll
            for (int j = 0; j < 4; j++)
                wmma::store_matrix_sync(&St[((warpId * 64) + i * 16) * EPST + j * 16],
                                        cf[i][j], EPST, wmma::mem_row_major);
        __syncthreads();
        int r = tid >> 1;
        int wmr = r >> 6, wr = r & 63;
        if (EPI == 1) {
            int co0 = (tid & 1) * 64;
            long obase = (long)e * actEs + (long)(bm + r) * (N >> 1) + (bn >> 1) + co0;
            #pragma unroll 4
            for (int c = 0; c < 64; c += 4) {
                int bc0 = 2 * (co0 + c);
                int wnn = bc0 >> 6, wc = bc0 & 63;
                const float* p = &St[((wmr * 4 + wnn) * 64 + wr) * EPST + wc];
                float4 p0 = *(const float4*)(p);
                float4 p1 = *(const float4*)(p + 4);
                st_half4(actOut + obase + c,
                         p0.x / (1.f + expf(-p0.x)) * p0.y,
                         p0.z / (1.f + expf(-p0.z)) * p0.w,
                         p1.x / (1.f + expf(-p1.x)) * p1.y,
                         p1.z / (1.f + expf(-p1.z)) * p1.w);
            }
        } else {
            int co0 = (tid & 1) * 128;
            long obase = (long)e * actEs + (long)(bm + r) * N + bn + co0;
            #pragma unroll 4
            for (int c = 0; c < 128; c += 4) {
                int bc = co0 + c;
                int wnn = bc >> 6, wc = bc & 63;
                const float* p = &St[((wmr * 4 + wnn) * 64 + wr) * EPST + wc];
                float4 v = *(const float4*)p;
                st_half4(actOut + obase + c, v.x, v.y, v.z, v.w);
            }
        }
    } else {
        C += (long)e * cEs;
        #pragma unroll
        for (int i = 0; i < 4; i++)
            #pragma unroll
            for (int j = 0; j < 4; j++)
                wmma::store_matrix_sync(
                    C + (long)(bm + wm * 64 + i * 16) * N + bn + wn * 64 + j * 16,
                    cf[i][j], N, wmma::mem_row_major);
    }
}

// ---------------- fp16 tensor-core causal flash attention ----------------
// 64 queries/block, 128 threads (4 warps). Half Q/K/V/P, fp32 scores/O.
#define HSTR 72
#define FSTR 68
#define ATT_SMEM (4*64*HSTR*2 + 2*64*FSTR*4 + 3*64*4)   // 72448 B

__global__ void __launch_bounds__(128)
attn_h_kernel(const float* __restrict__ q, const __half* __restrict__ kv,
              __half* __restrict__ o) {
    extern __shared__ char smema[];
    __half* Qs = (__half*)smema;
    __half* Ks = Qs + 64 * HSTR;
    __half* Vs = Ks + 64 * HSTR;
    __half* Ph = Vs + 64 * HSTR;
    float* Sf = (float*)(Ph + 64 * HSTR);
    float* Os = Sf + 64 * FSTR;
    float* mrow = Os + 64 * FSTR;
    float* lrow = mrow + 64;
    float* crow = lrow + 64;

    const int b = blockIdx.z, h = blockIdx.y, iq = blockIdx.x;
    const int q0 = iq * 64;
    const int tid = threadIdx.x;
    const int warpId = tid >> 5;
    const int r = tid >> 1;              // 0..63 (row)
    const int hf = tid & 1;              // half-row selector
    const int c0 = hf * 32;

    // load Q (scaled), zero O
    {
        long qb = ((long)(b * Lc + q0 + r)) * 1280 + h * HDc + c0;
        #pragma unroll
        for (int dd = 0; dd < 32; dd += 4) {
            float4 v = *(const float4*)(q + qb + dd);
            st_half4(Qs + r * HSTR + c0 + dd, v.x * 0.125f, v.y * 0.125f,
                     v.z * 0.125f, v.w * 0.125f);
            Os[r * FSTR + c0 + dd + 0] = 0.f;
            Os[r * FSTR + c0 + dd + 1] = 0.f;
            Os[r * FSTR + c0 + dd + 2] = 0.f;
            Os[r * FSTR + c0 + dd + 3] = 0.f;
        }
        if (tid < 64) { mrow[tid] = -INFINITY; lrow[tid] = 0.f; }
    }
    __syncthreads();

    for (int kt = 0; kt <= q0; kt += 64) {
        // load K/V tile (half)
        {
            long kvb = ((long)(b * Lc + kt + r)) * (2 * Hc * HDc) + h * HDc + c0;
            #pragma unroll
            for (int dd = 0; dd < 32; dd += 8) {
                *(int4*)&Ks[r * HSTR + c0 + dd] = *(const int4*)(kv + kvb + dd);
                *(int4*)&Vs[r * HSTR + c0 + dd] = *(const int4*)(kv + kvb + Hc * HDc + dd);
            }
        }
        __syncthreads();

        // S = Q @ K^T (fp16 MMA, fp32 accum)
        {
            wmma::fragment<wmma::accumulator, 16, 16, 16, float> sf[4];
            #pragma unroll
            for (int n = 0; n < 4; n++) wmma::fill_fragment(sf[n], 0.f);
            #pragma unroll
            for (int kk = 0; kk < 4; kk++) {
                wmma::fragment<wmma::matrix_a, 16, 16, 16, __half, wmma::row_major> aq;
                wmma::load_matrix_sync(aq, &Qs[(warpId * 16) * HSTR + kk * 16], HSTR);
                #pragma unroll
                for (int n = 0; n < 4; n++) {
                    wmma::fragment<wmma::matrix_b, 16, 16, 16, __half, wmma::col_major> bk;
                    wmma::load_matrix_sync(bk, &Ks[(n * 16) * HSTR + kk * 16], HSTR);
                    wmma::mma_sync(sf[n], aq, bk, sf[n]);
                }
            }
            #pragma unroll
            for (int n = 0; n < 4; n++)
                wmma::store_matrix_sync(&Sf[(warpId * 16) * FSTR + n * 16], sf[n], FSTR, wmma::mem_row_major);
        }
        __syncthreads();

        // online softmax: 2 threads per row (32 cols each), shfl combine
        {
            int limit = (kt == q0) ? (r + 1) : 64;     // valid cols in [0, limit)
            int vend = limit - c0;                      // valid within this half
            if (vend > 32) vend = 32;
            float mx = -INFINITY;
            for (int c = 0; c < vend; c++) mx = fmaxf(mx, Sf[r * FSTR + c0 + c]);
            mx = fmaxf(mx, __shfl_xor_sync(0xffffffffu, mx, 1));
            float mold = mrow[r];
            float nm = fmaxf(mold, mx);
            float corr = __expf(mold - nm);
            float sum = 0.f;
            for (int c = 0; c < vend; c++) {
                float p = __expf(Sf[r * FSTR + c0 + c] - nm);
                Ph[r * HSTR + c0 + c] = __float2half_rn(p);
                sum += p;
            }
            for (int c = (vend < 0 ? 0 : vend); c < 32; c++)
                Ph[r * HSTR + c0 + c] = __float2half_rn(0.f);
            sum += __shfl_xor_sync(0xffffffffu, sum, 1);
            if (hf == 0) {
                lrow[r] = lrow[r] * corr + sum;
                mrow[r] = nm;
                crow[r] = corr;
            }
        }
        __syncthreads();

        // rescale O
        {
            float corr = crow[r];
            #pragma unroll
            for (int c = 0; c < 32; c++) Os[r * FSTR + c0 + c] *= corr;
        }
        __syncthreads();

        // O += P @ V (fp16 MMA, fp32 accum via smem)
        {
            wmma::fragment<wmma::accumulator, 16, 16, 16, float> of[4];
            #pragma unroll
            for (int n = 0; n < 4; n++)
                wmma::load_matrix_sync(of[n], &Os[(warpId * 16) * FSTR + n * 16], FSTR, wmma::mem_row_major);
            #pragma unroll
            for (int kk = 0; kk < 4; kk++) {
                wmma::fragment<wmma::matrix_a, 16, 16, 16, __half, wmma::row_major> ap;
                wmma::load_matrix_sync(ap, &Ph[(warpId * 16) * HSTR + kk * 16], HSTR);
                #pragma unroll
                for (int n = 0; n < 4; n++) {
                    wmma::fragment<wmma::matrix_b, 16, 16, 16, __half, wmma::row_major> bv;
                    wmma::load_matrix_sync(bv, &Vs[(kk * 16) * HSTR + n * 16], HSTR);
                    wmma::mma_sync(of[n], ap, bv, of[n]);
                }
            }
            #pragma unroll
            for (int n = 0; n < 4; n++)
                wmma::store_matrix_sync(&Os[(warpId * 16) * FSTR + n * 16], of[n], FSTR, wmma::mem_row_major);
        }
        __syncthreads();
    }

    // write normalized O (half)
    {
        float inv = 1.f / lrow[r];
        long ob = ((long)(b * Lc + q0 + r)) * (Hc * HDc) + h * HDc + c0;
        #pragma unroll
        for (int c = 0; c < 32; c += 4) {
            st_half4(o + ob + c,
                     Os[r * FSTR + c0 + c + 0] * inv,
                     Os[r * FSTR + c0 + c + 1] * inv,
                     Os[r * FSTR + c0 + c + 2] * inv,
                     Os[r * FSTR + c0 + c + 3] * inv);
        }
    }
}

// ---------------- router (fp32 hn) ----------------
__global__ void router_kernel(const float* __restrict__ hn, const float* __restrict__ gw,
                              float* __restrict__ probs_out) {
    int warp = (blockIdx.x * blockDim.x + threadIdx.x) >> 5;
    int lane = threadIdx.x & 31;
    if (warp >= Tc) return;
    const float* row = hn + (long)warp * Dc;
    float acc[8] = {0, 0, 0, 0, 0, 0, 0, 0};
    for (int d = lane; d < Dc; d += 32) {
        float xv = row[d];
        const float* g = gw + d * 8;
        #pragma unroll
        for (int e = 0; e < 8; e++) acc[e] += xv * g[e];
    }
    #pragma unroll
    for (int e = 0; e < 8; e++)
        #pragma unroll
        for (int off = 16; off > 0; off >>= 1)
            acc[e] += __shfl_xor_sync(0xffffffffu, acc[e], off);

    if (lane == 0) {
        float mx = acc[0];
        #pragma unroll
        for (int e = 1; e < 8; e++) mx = fmaxf(mx, acc[e]);
        float p[8], s = 0.f;
        #pragma unroll
        for (int e = 0; e < 8; e++) { p[e] = expf(acc[e] - mx); s += p[e]; }
        float invs = 1.f / s;
        #pragma unroll
        for (int e = 0; e < 8; e++) { p[e] *= invs; probs_out[(long)warp * 8 + e] = p[e]; }
        int i1 = 0;
        #pragma unroll
        for (int e = 1; e < 8; e++) if (p[e] > p[i1]) i1 = e;
        int i2 = (i1 == 0) ? 1 : 0;
        #pragma unroll
        for (int e = 0; e < 8; e++) if (e != i1 && p[e] > p[i2]) i2 = e;
        float w1 = p[i1], w2 = p[i2];
        float inv2 = 1.f / (w1 + w2);
        w1 *= inv2; w2 *= inv2;
        int pos1 = atomicAdd(&g_cnt[i1], 1);
        g_idx[i1 * Tc + pos1] = warp;
        g_slot[warp * 2 + 0] = i1 * Tc + pos1;
        g_tw[warp * 2 + 0] = w1;
        int pos2 = atomicAdd(&g_cnt[i2], 1);
        g_idx[i2 * Tc + pos2] = warp;
        g_slot[warp * 2 + 1] = i2 * Tc + pos2;
        g_tw[warp * 2 + 1] = w2;
    }
}

// ---------------- final combine ----------------
__global__ void final_kernel(const float* __restrict__ h, const float* __restrict__ sh,
                             float* __restrict__ out) {
    long i4 = (long)blockIdx.x * blockDim.x + threadIdx.x;
    if (i4 >= (long)Tc * Dc / 4) return;
    int t = (int)(i4 / (Dc / 4));
    int d4 = (int)(i4 % (Dc / 4));
    int s0 = g_slot[t * 2 + 0], s1 = g_slot[t * 2 + 1];
    float w0 = g_tw[t * 2 + 0], w1 = g_tw[t * 2 + 1];
    float4 e0 = *(const float4*)(g_eo + (long)s0 * Dc + d4 * 4);
    float4 e1 = *(const float4*)(g_eo + (long)s1 * Dc + d4 * 4);
    float4 hv = ((const float4*)h)[i4];
    float4 sv = ((const float4*)sh)[i4];
    float4 r;
    r.x = hv.x + sv.x + w0 * e0.x + w1 * e1.x;
    r.y = hv.y + sv.y + w0 * e0.y + w1 * e1.y;
    r.z = hv.z + sv.z + w0 * e0.z + w1 * e1.z;
    r.w = hv.w + sv.w + w0 * e0.w + w1 * e1.w;
    ((float4*)out)[i4] = r;
}

// ---------------- launch ----------------
extern "C" void kernel_launch(void* const* d_in, const int* in_sizes, int n_in,
                              void* d_out, int out_size) {
    const float* x     = (const float*)d_in[0];
    const float* ln1_w = (const float*)d_in[1];
    const float* q_w   = (const float*)d_in[2];
    const float* kvd_w = (const float*)d_in[3];
    const float* kvn_w = (const float*)d_in[4];
    const float* kvu_w = (const float*)d_in[5];
    const float* o_w   = (const float*)d_in[6];
    const float* ln2_w = (const float*)d_in[7];
    const float* gate_w= (const float*)d_in[8];
    const float* sh_w1 = (const float*)d_in[9];
    const float* sh_w2 = (const float*)d_in[10];
    const float* sh_w3 = (const float*)d_in[11];
    const float* re_w1 = (const float*)d_in[12];
    const float* re_w2 = (const float*)d_in[13];
    const float* re_w3 = (const float*)d_in[14];

    float* outy = (float*)d_out;
    float* outp = outy + (long)Tc * Dc;

    __half *xnh, *lath, *kvh, *attnh, *hnh, *acth, *ehacth;
    __half *wqkvh, *kvuh, *owh, *w13h, *w2h, *rw13h, *rw2h;
    float *qlat, *hb, *hnb, *shb, *eo;
    cudaGetSymbolAddress((void**)&xnh, g_xn_h);
    cudaGetSymbolAddress((void**)&lath, g_lat_h);
    cudaGetSymbolAddress((void**)&kvh, g_kv_h);
    cudaGetSymbolAddress((void**)&attnh, g_attn_h);
    cudaGetSymbolAddress((void**)&hnh, g_hn_h);
    cudaGetSymbolAddress((void**)&acth, g_act_h);
    cudaGetSymbolAddress((void**)&ehacth, g_ehact_h);
    cudaGetSymbolAddress((void**)&wqkvh, g_wqkv_h);
    cudaGetSymbolAddress((void**)&kvuh, g_kvu_h);
    cudaGetSymbolAddress((void**)&owh, g_ow_h);
    cudaGetSymbolAddress((void**)&w13h, g_w13_h);
    cudaGetSymbolAddress((void**)&w2h, g_w2_h);
    cudaGetSymbolAddress((void**)&rw13h, g_rw13_h);
    cudaGetSymbolAddress((void**)&rw2h, g_rw2_h);
    cudaGetSymbolAddress((void**)&qlat, g_qlat);
    cudaGetSymbolAddress((void**)&hb, g_h);
    cudaGetSymbolAddress((void**)&hnb, g_hn);
    cudaGetSymbolAddress((void**)&shb, g_shared);
    cudaGetSymbolAddress((void**)&eo, g_eo);
    int* idxp; int* cntp;
    cudaGetSymbolAddress((void**)&idxp, g_idx);
    cudaGetSymbolAddress((void**)&cntp, g_cnt);

    cudaFuncSetAttribute((const void*)gemm_h<false, false, false, 0>,
                         cudaFuncAttributeMaxDynamicSharedMemorySize, GSMEM);
    cudaFuncSetAttribute((const void*)gemm_h<false, false, true, 0>,
                         cudaFuncAttributeMaxDynamicSharedMemorySize, GSMEM);
    cudaFuncSetAttribute((const void*)gemm_h<false, false, false, 1>,
                         cudaFuncAttributeMaxDynamicSharedMemorySize, GSMEM);
    cudaFuncSetAttribute((const void*)gemm_h<false, false, false, 2>,
                         cudaFuncAttributeMaxDynamicSharedMemorySize, GSMEM);
    cudaFuncSetAttribute((const void*)gemm_h<true, true, false, 1>,
                         cudaFuncAttributeMaxDynamicSharedMemorySize, GSMEM);
    cudaFuncSetAttribute((const void*)gemm_h<false, true, false, 0>,
                         cudaFuncAttributeMaxDynamicSharedMemorySize, GSMEM);
    cudaFuncSetAttribute((const void*)attn_h_kernel,
                         cudaFuncAttributeMaxDynamicSharedMemorySize, ATT_SMEM);

    cvt_weights_k<<<dim3(16384, 8), 256>>>(q_w, kvd_w, kvu_w, o_w, sh_w1, sh_w2, sh_w3,
                                           re_w1, re_w2, re_w3);

    // ---- attention path ----
    rmsnorm_k<<<Tc, 256>>>(x, ln1_w, xnh, nullptr, Dc, Dc);
    gemm_h<false, false, false, 0><<<dim3(5, 32, 1), 256, GSMEM>>>(
        xnh, wqkvh, qlat, nullptr, nullptr, nullptr, nullptr, Tc, 1280, 1024, 0, 0, 0, 0, 0);
    rmsnorm_k<<<Tc, 256>>>(qlat + 1024, kvn_w, lath, nullptr, Rc, 1280);
    gemm_h<false, false, false, 2><<<dim3(8, 32, 1), 256, GSMEM>>>(
        lath, kvuh, nullptr, nullptr, kvh, nullptr, nullptr, Tc, 2048, 256, 0, 0, 0, 0, 0);
    attn_h_kernel<<<dim3(Lc / 64, Hc, Bc), 128, ATT_SMEM>>>(qlat, kvh, attnh);
    gemm_h<false, false, true, 0><<<dim3(4, 32, 1), 256, GSMEM>>>(
        attnh, owh, hb, x, nullptr, nullptr, nullptr, Tc, 1024, 1024, 0, 0, 0, 0, 0);

    // ---- MoE path ----
    rmsnorm_k<<<Tc, 256>>>(hb, ln2_w, hnh, hnb, Dc, Dc);
    gemm_h<false, false, false, 1><<<dim3(8, 32, 1), 256, GSMEM>>>(
        hnh, w13h, nullptr, nullptr, acth, nullptr, nullptr, Tc, 2048, 1024, 0, 0, 0, 0, 0);
    gemm_h<false, false, false, 0><<<dim3(4, 32, 1), 256, GSMEM>>>(
        acth, w2h, shb, nullptr, nullptr, nullptr, nullptr, Tc, 1024, 1024, 0, 0, 0, 0, 0);

    zero_cnt_k<<<1, 32>>>();
    router_kernel<<<Tc / 8, 256>>>(hnb, gate_w, outp);

    gemm_h<true, true, false, 1><<<dim3(8, 32, Ec), 256, GSMEM>>>(
        hnh, rw13h, nullptr, nullptr, ehacth, idxp, cntp,
        Tc, 2048, 1024, 0, (long)1024 * 2048, 0, (long)Tc * Fc, Tc);
    gemm_h<false, true, false, 0><<<dim3(4, 32, Ec), 256, GSMEM>>>(
        ehacth, rw2h, eo, nullptr, nullptr, nullptr, cntp,
        Tc, 1024, 1024, (long)Tc * Fc, (long)1024 * 1024, (long)Tc * Dc, 0, 0);

    final_kernel<<<(Tc * Dc / 4 + 255) / 256, 256>>>(hb, shb, outy);
}

// round 15
// speedup vs baseline: 4.6418x; 1.1072x over previous
#include <cuda_runtime.h>
#include <mma.h>
#include <cuda_fp16.h>
#include <math.h>
#include <stdint.h>

using namespace nvcuda;

#define Bc 2
#define Lc 2048
#define Dc 1024
#define Hc 16
#define HDc 64
#define Rc 256
#define Ec 8
#define Kc 2
#define Fc 1024
#define Tc (Bc*Lc)   // 4096

// ---------------- scratch ----------------
__device__ __half g_xn_h[Tc*Dc];
__device__ float  g_qlat[Tc*1280];
__device__ __half g_lat_h[Tc*Rc];
__device__ __half g_kv_h[Tc*2*Hc*HDc];
__device__ __half g_attn_h[Tc*Hc*HDc];
__device__ float  g_h[Tc*Dc];
__device__ float  g_hn[Tc*Dc];
__device__ __half g_hn_h[Tc*Dc];
__device__ __half g_act_h[Tc*Fc];
__device__ float  g_shared[Tc*Dc];
__device__ __half g_wqkv_h[Dc*1280];
__device__ __half g_kvu_h[Rc*2048];
__device__ __half g_ow_h[Dc*Dc];
__device__ __half g_w13_h[Dc*2048];              // pair-interleaved w1/w3
__device__ __half g_w2_h[Dc*Dc];
__device__ __half g_rw13_h[(long)Ec*Dc*2048];    // pair-interleaved
__device__ __half g_rw2_h[(long)Ec*Dc*Dc];
__device__ __half g_ehact_h[(long)Ec*Tc*Fc];
__device__ float  g_eo[(long)Ec*Tc*Dc];
__device__ int    g_cnt[Ec];
__device__ int    g_idx[Ec*Tc];
__device__ int    g_slot[Tc*Kc];
__device__ float  g_tw[Tc*Kc];

// ---------------- helpers ----------------
__device__ __forceinline__ void st_half4(__half* p, float a, float b, float c, float d) {
    *(__half2*)p       = __floats2half2_rn(a, b);
    *(__half2*)(p + 2) = __floats2half2_rn(c, d);
}
__device__ __forceinline__ void cp16(void* sdst, const void* g) {
    unsigned s = (unsigned)__cvta_generic_to_shared(sdst);
    asm volatile("cp.async.cg.shared.global [%0], [%1], 16;" :: "r"(s), "l"(g));
}
#define CP_COMMIT() asm volatile("cp.async.commit_group;")
#define CP_WAIT2()  asm volatile("cp.async.wait_group 2;")

// ---------------- small kernels ----------------
__global__ void zero_cnt_k() {
    if (threadIdx.x < Ec) g_cnt[threadIdx.x] = 0;
}

// convert + pack all weights to half (8 segments)
__global__ void cvt_weights_k(const float* __restrict__ q_w, const float* __restrict__ kvd_w,
                              const float* __restrict__ kvu_w, const float* __restrict__ o_w,
                              const float* __restrict__ sh_w1, const float* __restrict__ sh_w2,
                              const float* __restrict__ sh_w3,
                              const float* __restrict__ re_w1, const float* __restrict__ re_w2,
                              const float* __restrict__ re_w3) {
    int seg = blockIdx.y;
    long i = (long)blockIdx.x * blockDim.x + threadIdx.x;
    switch (seg) {
    case 0: {
        if (i >= (long)Dc * Dc / 4) return;
        long r = i / 256; int c4 = (int)(i % 256);
        float4 v = ((const float4*)q_w)[i];
        st_half4(g_wqkv_h + r * 1280 + c4 * 4, v.x, v.y, v.z, v.w);
        break; }
    case 1: {
        if (i >= (long)Dc * Rc / 4) return;
        long r = i / 64; int c4 = (int)(i % 64);
        float4 v = ((const float4*)kvd_w)[i];
        st_half4(g_wqkv_h + r * 1280 + 1024 + c4 * 4, v.x, v.y, v.z, v.w);
        break; }
    case 2: {
        if (i >= (long)Rc * 2048 / 4) return;
        float4 v = ((const float4*)kvu_w)[i];
        st_half4(g_kvu_h + i * 4, v.x, v.y, v.z, v.w);
        break; }
    case 3: {
        if (i >= (long)Dc * Dc / 4) return;
        float4 v = ((const float4*)o_w)[i];
        st_half4(g_ow_h + i * 4, v.x, v.y, v.z, v.w);
        break; }
    case 4: {
        if (i >= (long)Dc * Dc / 4) return;
        float4 v = ((const float4*)sh_w2)[i];
        st_half4(g_w2_h + i * 4, v.x, v.y, v.z, v.w);
        break; }
    case 5: {
        if (i >= (long)Ec * Dc * Dc / 4) return;
        float4 v = ((const float4*)re_w2)[i];
        st_half4(g_rw2_h + i * 4, v.x, v.y, v.z, v.w);
        break; }
    case 6: {
        if (i >= (long)Dc * Fc / 2) return;
        long r = i / 512; int j2 = (int)(i % 512);
        float2 a = ((const float2*)sh_w1)[r * 512 + j2];
        float2 b = ((const float2*)sh_w3)[r * 512 + j2];
        st_half4(g_w13_h + r * 2048 + j2 * 4, a.x, b.x, a.y, b.y);
        break; }
    default: {
        if (i >= (long)Ec * Dc * Fc / 2) return;
        long r = i / 512; int j2 = (int)(i % 512);
        float2 a = ((const float2*)re_w1)[r * 512 + j2];
        float2 b = ((const float2*)re_w3)[r * 512 + j2];
        st_half4(g_rw13_h + r * 2048 + j2 * 4, a.x, b.x, a.y, b.y);
        break; }
    }
}

// rmsnorm: half output always, fp32 optional
__global__ void rmsnorm_k(const float* __restrict__ x, const float* __restrict__ w,
                          __half* __restrict__ oh, float* __restrict__ of,
                          int dim, int xs) {
    int row = blockIdx.x;
    int tid = threadIdx.x;
    const float* xr = x + (long)row * xs;
    float s = 0.f;
    for (int d = tid; d < dim; d += blockDim.x) { float v = xr[d]; s += v * v; }
    __shared__ float red[256];
    red[tid] = s;
    __syncthreads();
    for (int off = 128; off > 0; off >>= 1) {
        if (tid < off) red[tid] += red[tid + off];
        __syncthreads();
    }
    float inv = rsqrtf(red[0] / (float)dim + 1e-6f);
    __half* ohr = oh + (long)row * dim;
    float* ofr = of ? of + (long)row * dim : nullptr;
    for (int d = tid; d < dim; d += blockDim.x) {
        float v = w[d] * xr[d] * inv;
        ohr[d] = __float2half_rn(v);
        if (of) ofr[d] = v;
    }
}

// ---------------- fp16 TC GEMM: 128x256 tile, m16n16k16, 4-stage cp.async ----------------
// EPI: 0 = fp32 C, 1 = silu-pair -> half, 2 = plain -> half
// Merged mode: if HAS_CNT and aSh != nullptr, block z == gridDim.z-1 runs the
// "shared" problem: A=aSh, B=bSh, full M, no gather, outputs to cSh/actSh.
#define BM 128
#define BN 256
#define BK 32
#define ASTH 40
#define BSTH 264
#define SMAH (BM*ASTH)
#define SMBH (BK*BSTH)
#define STGH (SMAH+SMBH)
#define EPST 68
#define GSMEM 139264

template<bool GATHER, bool HAS_CNT, bool RESID, int EPI>
__global__ void __launch_bounds__(256)
gemm_h(const __half* __restrict__ A, const __half* __restrict__ Bw,
       float* __restrict__ C, const float* __restrict__ resid,
       __half* __restrict__ actOut,
       const int* __restrict__ gidx, const int* __restrict__ cntp,
       const __half* __restrict__ aSh, const __half* __restrict__ bSh,
       float* __restrict__ cSh, __half* __restrict__ actSh,
       int M, int N, int Kd,
       long aEs, long bEs, long cEs, long actEs, int iEs) {
    extern __shared__ char smx[];

    int e = blockIdx.z;
    bool sh = HAS_CNT && (aSh != nullptr) && (e == (int)gridDim.z - 1);
    const __half* Ap;
    const __half* Bp;
    int Me;
    if (sh) {
        Ap = aSh; Bp = bSh; Me = M;
    } else {
        Ap = A + (long)e * aEs;
        Bp = Bw + (long)e * bEs;
        Me = HAS_CNT ? cntp[e] : M;
    }
    int bm = blockIdx.y * BM, bn = blockIdx.x * BN;
    if (bm >= Me) return;

    const int tid = threadIdx.x;
    const int warpId = tid >> 5;
    const int wm = warpId >> 2;
    const int wn = warpId & 3;

    const int ar0 = tid >> 2;
    const int ac8 = (tid & 3) * 8;
    const int br0 = tid >> 5;
    const int bc8 = (tid & 31) * 8;

    long aBase[2];
    int aS[2];
    #pragma unroll
    for (int i = 0; i < 2; i++) {
        int row = ar0 + 64 * i;
        int am = bm + row;
        long ar;
        if (GATHER && !sh) {
            int g = gidx[e * iEs + am];
            if (g < 0 || g >= Tc) g = 0;
            ar = (long)g * Kd;
        } else ar = (long)am * Kd;
        aBase[i] = ar + ac8;
        aS[i] = row * ASTH + ac8;
    }
    long bOff[4];
    int bS[4];
    #pragma unroll
    for (int i = 0; i < 4; i++) {
        int row = br0 + 8 * i;
        bOff[i] = (long)row * N + bn + bc8;
        bS[i] = row * BSTH + bc8;
    }

    wmma::fragment<wmma::accumulator, 16, 16, 16, float> cf[4][4];
    if (RESID) {
        #pragma unroll
        for (int i = 0; i < 4; i++)
            #pragma unroll
            for (int j = 0; j < 4; j++)
                wmma::load_matrix_sync(cf[i][j],
                    resid + (long)(bm + wm * 64 + i * 16) * N + bn + wn * 64 + j * 16,
                    N, wmma::mem_row_major);
    } else {
        #pragma unroll
        for (int i = 0; i < 4; i++)
            #pragma unroll
            for (int j = 0; j < 4; j++)
                wmma::fill_fragment(cf[i][j], 0.f);
    }

    const int T = Kd / BK;

    auto load_tile = [&](int t, int s) {
        __half* As_ = (__half*)smx + s * STGH;
        __half* Bs_ = As_ + SMAH;
        int k0 = t * BK;
        #pragma unroll
        for (int i = 0; i < 2; i++)
            cp16(As_ + aS[i], Ap + aBase[i] + k0);
        #pragma unroll
        for (int i = 0; i < 4; i++)
            cp16(Bs_ + bS[i], Bp + (long)k0 * N + bOff[i]);
    };

    load_tile(0, 0);
    CP_COMMIT();
    if (T > 1) load_tile(1, 1);
    CP_COMMIT();

    for (int t = 0; t < T; t++) {
        if (t + 2 < T) load_tile(t + 2, (t + 2) & 3);
        CP_COMMIT();
        CP_WAIT2();
        __syncthreads();

        int s = t & 3;
        const __half* As_ = (const __half*)smx + s * STGH;
        const __half* Bs_ = As_ + SMAH;
        #pragma unroll
        for (int kk = 0; kk < 2; kk++) {
            wmma::fragment<wmma::matrix_a, 16, 16, 16, __half, wmma::row_major> af[4];
            wmma::fragment<wmma::matrix_b, 16, 16, 16, __half, wmma::row_major> bf[4];
            #pragma unroll
            for (int i = 0; i < 4; i++)
                wmma::load_matrix_sync(af[i], &As_[(wm * 64 + i * 16) * ASTH + kk * 16], ASTH);
            #pragma unroll
            for (int j = 0; j < 4; j++)
                wmma::load_matrix_sync(bf[j], &Bs_[(kk * 16) * BSTH + wn * 64 + j * 16], BSTH);
            #pragma unroll
            for (int i = 0; i < 4; i++)
                #pragma unroll
                for (int j = 0; j < 4; j++)
                    wmma::mma_sync(cf[i][j], af[i], bf[j], cf[i][j]);
        }
    }

    if (EPI >= 1) {
        __syncthreads();
        float* St = (float*)smx;
        #pragma unroll
        for (int i = 0; i < 4; i++)
            #pragma unroll
            for (int j = 0; j < 4; j++)
                wmma::store_matrix_sync(&St[((warpId * 64) + i * 16) * EPST + j * 16],
                                        cf[i][j], EPST, wmma::mem_row_major);
        __syncthreads();
        int r = tid >> 1;
        int wmr = r >> 6, wr = r & 63;
        __half* aOut = (EPI == 1 || EPI == 2)
                     ? (sh ? actSh : actOut + (long)e * actEs) : actOut;
        if (EPI == 1) {
            int co0 = (tid & 1) * 64;
            long obase = (long)(bm + r) * (N >> 1) + (bn >> 1) + co0;
            #pragma unroll 4
            for (int c = 0; c < 64; c += 4) {
                int bc0 = 2 * (co0 + c);
                int wnn = bc0 >> 6, wc = bc0 & 63;
                const float* p = &St[((wmr * 4 + wnn) * 64 + wr) * EPST + wc];
                float4 p0 = *(const float4*)(p);
                float4 p1 = *(const float4*)(p + 4);
                st_half4(aOut + obase + c,
                         p0.x / (1.f + expf(-p0.x)) * p0.y,
                         p0.z / (1.f + expf(-p0.z)) * p0.w,
                         p1.x / (1.f + expf(-p1.x)) * p1.y,
                         p1.z / (1.f + expf(-p1.z)) * p1.w);
            }
        } else {
            int co0 = (tid & 1) * 128;
            long obase = (long)(bm + r) * N + bn + co0;
            #pragma unroll 4
            for (int c = 0; c < 128; c += 4) {
                int bc = co0 + c;
                int wnn = bc >> 6, wc = bc & 63;
                const float* p = &St[((wmr * 4 + wnn) * 64 + wr) * EPST + wc];
                float4 v = *(const float4*)p;
                st_half4(aOut + obase + c, v.x, v.y, v.z, v.w);
            }
        }
    } else {
        float* Cc = sh ? cSh : C + (long)e * cEs;
        #pragma unroll
        for (int i = 0; i < 4; i++)
            #pragma unroll
            for (int j = 0; j < 4; j++)
                wmma::store_matrix_sync(
                    Cc + (long)(bm + wm * 64 + i * 16) * N + bn + wn * 64 + j * 16,
                    cf[i][j], N, wmma::mem_row_major);
    }
}

// ---------------- fp16 TC causal flash attention, register-resident O ----------------
// 64 queries/block, 128 threads (4 warps). O held in wmma accumulator fragments
// across the whole KV loop; per-row rescale via the sm_80+ accumulator mapping:
//   elem k: row = (lane>>2) + 8*((k>>1)&1), col = (lane&3)*2 + (k&1) + 8*(k>>2)
#define HSTR 72
#define FSTR 68
#define ATT_SMEM (4*64*HSTR*2 + 64*FSTR*4 + 2*64*4)   // 54784 B

__global__ void __launch_bounds__(128)
attn_h_kernel(const float* __restrict__ q, const __half* __restrict__ kv,
              __half* __restrict__ o) {
    extern __shared__ char smema[];
    __half* Qs = (__half*)smema;
    __half* Ks = Qs + 64 * HSTR;
    __half* Vs = Ks + 64 * HSTR;
    __half* Ph = Vs + 64 * HSTR;
    float* Sf = (float*)(Ph + 64 * HSTR);
    float* crow = Sf + 64 * FSTR;
    float* lrow = crow + 64;

    const int b = blockIdx.z, h = blockIdx.y, iq = blockIdx.x;
    const int q0 = iq * 64;
    const int tid = threadIdx.x;
    const int warpId = tid >> 5;
    const int lane = tid & 31;
    const int r = tid >> 1;              // softmax row owner
    const int hf = tid & 1;
    const int c0 = hf * 32;

    // O accumulators live in registers for the whole loop
    wmma::fragment<wmma::accumulator, 16, 16, 16, float> of[4];
    #pragma unroll
    for (int n = 0; n < 4; n++) wmma::fill_fragment(of[n], 0.f);
    float m_run = -INFINITY, l_run = 0.f;

    // load Q (scaled)
    {
        long qb = ((long)(b * Lc + q0 + r)) * 1280 + h * HDc + c0;
        #pragma unroll
        for (int dd = 0; dd < 32; dd += 4) {
            float4 v = *(const float4*)(q + qb + dd);
            st_half4(Qs + r * HSTR + c0 + dd, v.x * 0.125f, v.y * 0.125f,
                     v.z * 0.125f, v.w * 0.125f);
        }
    }
    __syncthreads();

    for (int kt = 0; kt <= q0; kt += 64) {
        // load K/V tile (half)
        {
            long kvb = ((long)(b * Lc + kt + r)) * (2 * Hc * HDc) + h * HDc + c0;
            #pragma unroll
            for (int dd = 0; dd < 32; dd += 8) {
                *(int4*)&Ks[r * HSTR + c0 + dd] = *(const int4*)(kv + kvb + dd);
                *(int4*)&Vs[r * HSTR + c0 + dd] = *(const int4*)(kv + kvb + Hc * HDc + dd);
            }
        }
        __syncthreads();

        // S = Q @ K^T
        {
            wmma::fragment<wmma::accumulator, 16, 16, 16, float> sf[4];
            #pragma unroll
            for (int n = 0; n < 4; n++) wmma::fill_fragment(sf[n], 0.f);
            #pragma unroll
            for (int kk = 0; kk < 4; kk++) {
                wmma::fragment<wmma::matrix_a, 16, 16, 16, __half, wmma::row_major> aq;
                wmma::load_matrix_sync(aq, &Qs[(warpId * 16) * HSTR + kk * 16], HSTR);
                #pragma unroll
                for (int n = 0; n < 4; n++) {
                    wmma::fragment<wmma::matrix_b, 16, 16, 16, __half, wmma::col_major> bk;
                    wmma::load_matrix_sync(bk, &Ks[(n * 16) * HSTR + kk * 16], HSTR);
                    wmma::mma_sync(sf[n], aq, bk, sf[n]);
                }
            }
            #pragma unroll
            for (int n = 0; n < 4; n++)
                wmma::store_matrix_sync(&Sf[(warpId * 16) * FSTR + n * 16], sf[n], FSTR, wmma::mem_row_major);
        }
        __syncthreads();

        // online softmax (2 threads/row) + write P (half) + publish corr
        {
            int limit = (kt == q0) ? (r + 1) : 64;
            int vend = limit - c0;
            if (vend > 32) vend = 32;
            float mx = -INFINITY;
            for (int c = 0; c < vend; c++) mx = fmaxf(mx, Sf[r * FSTR + c0 + c]);
            mx = fmaxf(mx, __shfl_xor_sync(0xffffffffu, mx, 1));
            float nm = fmaxf(m_run, mx);
            float corr = __expf(m_run - nm);
            float sum = 0.f;
            for (int c = 0; c < vend; c++) {
                float p = __expf(Sf[r * FSTR + c0 + c] - nm);
                Ph[r * HSTR + c0 + c] = __float2half_rn(p);
                sum += p;
            }
            for (int c = (vend < 0 ? 0 : vend); c < 32; c++)
                Ph[r * HSTR + c0 + c] = __float2half_rn(0.f);
            sum += __shfl_xor_sync(0xffffffffu, sum, 1);
            l_run = l_run * corr + sum;
            m_run = nm;
            if (hf == 0) crow[r] = corr;
        }
        __syncthreads();

        // rescale O fragments in registers, then O += P @ V
        {
            #pragma unroll
            for (int n = 0; n < 4; n++) {
                #pragma unroll
                for (int k = 0; k < 8; k++) {
                    int rl = (lane >> 2) + (((k >> 1) & 1) << 3);
                    of[n].x[k] *= crow[warpId * 16 + rl];
                }
            }
            #pragma unroll
            for (int kk = 0; kk < 4; kk++) {
                wmma::fragment<wmma::matrix_a, 16, 16, 16, __half, wmma::row_major> ap;
                wmma::load_matrix_sync(ap, &Ph[(warpId * 16) * HSTR + kk * 16], HSTR);
                #pragma unroll
                for (int n = 0; n < 4; n++) {
                    wmma::fragment<wmma::matrix_b, 16, 16, 16, __half, wmma::row_major> bv;
                    wmma::load_matrix_sync(bv, &Vs[(kk * 16) * HSTR + n * 16], HSTR);
                    wmma::mma_sync(of[n], ap, bv, of[n]);
                }
            }
        }
        __syncthreads();
    }

    // publish l, then write normalized O directly from fragments (half2 stores)
    if (hf == 0) lrow[r] = l_run;
    __syncthreads();
    {
        #pragma unroll
        for (int n = 0; n < 4; n++) {
            #pragma unroll
            for (int k = 0; k < 8; k += 2) {
                int rl = (lane >> 2) + (((k >> 1) & 1) << 3);
                int col = (lane & 3) * 2 + ((k >> 2) << 3);
                float inv = 1.f / lrow[warpId * 16 + rl];
                long ob = ((long)(b * Lc + q0 + warpId * 16 + rl)) * (Hc * HDc)
                        + h * HDc + n * 16 + col;
                *(__half2*)(o + ob) = __floats2half2_rn(of[n].x[k] * inv,
                                                        of[n].x[k + 1] * inv);
            }
        }
    }
}

// ---------------- router (fp32 hn) ----------------
__global__ void router_kernel(const float* __restrict__ hn, const float* __restrict__ gw,
                              float* __restrict__ probs_out) {
    int warp = (blockIdx.x * blockDim.x + threadIdx.x) >> 5;
    int lane = threadIdx.x & 31;
    if (warp >= Tc) return;
    const float* row = hn + (long)warp * Dc;
    float acc[8] = {0, 0, 0, 0, 0, 0, 0, 0};
    for (int d = lane; d < Dc; d += 32) {
        float xv = row[d];
        const float* g = gw + d * 8;
        #pragma unroll
        for (int e = 0; e < 8; e++) acc[e] += xv * g[e];
    }
    #pragma unroll
    for (int e = 0; e < 8; e++)
        #pragma unroll
        for (int off = 16; off > 0; off >>= 1)
            acc[e] += __shfl_xor_sync(0xffffffffu, acc[e], off);

    if (lane == 0) {
        float mx = acc[0];
        #pragma unroll
        for (int e = 1; e < 8; e++) mx = fmaxf(mx, acc[e]);
        float p[8], s = 0.f;
        #pragma unroll
        for (int e = 0; e < 8; e++) { p[e] = expf(acc[e] - mx); s += p[e]; }
        float invs = 1.f / s;
        #pragma unroll
        for (int e = 0; e < 8; e++) { p[e] *= invs; probs_out[(long)warp * 8 + e] = p[e]; }
        int i1 = 0;
        #pragma unroll
        for (int e = 1; e < 8; e++) if (p[e] > p[i1]) i1 = e;
        int i2 = (i1 == 0) ? 1 : 0;
        #pragma unroll
        for (int e = 0; e < 8; e++) if (e != i1 && p[e] > p[i2]) i2 = e;
        float w1 = p[i1], w2 = p[i2];
        float inv2 = 1.f / (w1 + w2);
        w1 *= inv2; w2 *= inv2;
        int pos1 = atomicAdd(&g_cnt[i1], 1);
        g_idx[i1 * Tc + pos1] = warp;
        g_slot[warp * 2 + 0] = i1 * Tc + pos1;
        g_tw[warp * 2 + 0] = w1;
        int pos2 = atomicAdd(&g_cnt[i2], 1);
        g_idx[i2 * Tc + pos2] = warp;
        g_slot[warp * 2 + 1] = i2 * Tc + pos2;
        g_tw[warp * 2 + 1] = w2;
    }
}

// ---------------- final combine ----------------
__global__ void final_kernel(const float* __restrict__ h, const float* __restrict__ sh,
                             float* __restrict__ out) {
    long i4 = (long)blockIdx.x * blockDim.x + threadIdx.x;
    if (i4 >= (long)Tc * Dc / 4) return;
    int t = (int)(i4 / (Dc / 4));
    int d4 = (int)(i4 % (Dc / 4));
    int s0 = g_slot[t * 2 + 0], s1 = g_slot[t * 2 + 1];
    float w0 = g_tw[t * 2 + 0], w1 = g_tw[t * 2 + 1];
    float4 e0 = *(const float4*)(g_eo + (long)s0 * Dc + d4 * 4);
    float4 e1 = *(const float4*)(g_eo + (long)s1 * Dc + d4 * 4);
    float4 hv = ((const float4*)h)[i4];
    float4 sv = ((const float4*)sh)[i4];
    float4 r;
    r.x = hv.x + sv.x + w0 * e0.x + w1 * e1.x;
    r.y = hv.y + sv.y + w0 * e0.y + w1 * e1.y;
    r.z = hv.z + sv.z + w0 * e0.z + w1 * e1.z;
    r.w = hv.w + sv.w + w0 * e0.w + w1 * e1.w;
    ((float4*)out)[i4] = r;
}

// ---------------- launch ----------------
extern "C" void kernel_launch(void* const* d_in, const int* in_sizes, int n_in,
                              void* d_out, int out_size) {
    const float* x     = (const float*)d_in[0];
    const float* ln1_w = (const float*)d_in[1];
    const float* q_w   = (const float*)d_in[2];
    const float* kvd_w = (const float*)d_in[3];
    const float* kvn_w = (const float*)d_in[4];
    const float* kvu_w = (const float*)d_in[5];
    const float* o_w   = (const float*)d_in[6];
    const float* ln2_w = (const float*)d_in[7];
    const float* gate_w= (const float*)d_in[8];
    const float* sh_w1 = (const float*)d_in[9];
    const float* sh_w2 = (const float*)d_in[10];
    const float* sh_w3 = (const float*)d_in[11];
    const float* re_w1 = (const float*)d_in[12];
    const float* re_w2 = (const float*)d_in[13];
    const float* re_w3 = (const float*)d_in[14];

    float* outy = (float*)d_out;
    float* outp = outy + (long)Tc * Dc;

    __half *xnh, *lath, *kvh, *attnh, *hnh, *acth, *ehacth;
    __half *wqkvh, *kvuh, *owh, *w13h, *w2h, *rw13h, *rw2h;
    float *qlat, *hb, *hnb, *shb, *eo;
    cudaGetSymbolAddress((void**)&xnh, g_xn_h);
    cudaGetSymbolAddress((void**)&lath, g_lat_h);
    cudaGetSymbolAddress((void**)&kvh, g_kv_h);
    cudaGetSymbolAddress((void**)&attnh, g_attn_h);
    cudaGetSymbolAddress((void**)&hnh, g_hn_h);
    cudaGetSymbolAddress((void**)&acth, g_act_h);
    cudaGetSymbolAddress((void**)&ehacth, g_ehact_h);
    cudaGetSymbolAddress((void**)&wqkvh, g_wqkv_h);
    cudaGetSymbolAddress((void**)&kvuh, g_kvu_h);
    cudaGetSymbolAddress((void**)&owh, g_ow_h);
    cudaGetSymbolAddress((void**)&w13h, g_w13_h);
    cudaGetSymbolAddress((void**)&w2h, g_w2_h);
    cudaGetSymbolAddress((void**)&rw13h, g_rw13_h);
    cudaGetSymbolAddress((void**)&rw2h, g_rw2_h);
    cudaGetSymbolAddress((void**)&qlat, g_qlat);
    cudaGetSymbolAddress((void**)&hb, g_h);
    cudaGetSymbolAddress((void**)&hnb, g_hn);
    cudaGetSymbolAddress((void**)&shb, g_shared);
    cudaGetSymbolAddress((void**)&eo, g_eo);
    int* idxp; int* cntp;
    cudaGetSymbolAddress((void**)&idxp, g_idx);
    cudaGetSymbolAddress((void**)&cntp, g_cnt);

    cudaFuncSetAttribute((const void*)gemm_h<false, false, false, 0>,
                         cudaFuncAttributeMaxDynamicSharedMemorySize, GSMEM);
    cudaFuncSetAttribute((const void*)gemm_h<false, false, true, 0>,
                         cudaFuncAttributeMaxDynamicSharedMemorySize, GSMEM);
    cudaFuncSetAttribute((const void*)gemm_h<false, false, false, 2>,
                         cudaFuncAttributeMaxDynamicSharedMemorySize, GSMEM);
    cudaFuncSetAttribute((const void*)gemm_h<true, true, false, 1>,
                         cudaFuncAttributeMaxDynamicSharedMemorySize, GSMEM);
    cudaFuncSetAttribute((const void*)gemm_h<false, true, false, 0>,
                         cudaFuncAttributeMaxDynamicSharedMemorySize, GSMEM);
    cudaFuncSetAttribute((const void*)attn_h_kernel,
                         cudaFuncAttributeMaxDynamicSharedMemorySize, ATT_SMEM);

    // launch 0: zero counters (so profile slot 3 lands on gemm_qkv)
    zero_cnt_k<<<1, 32>>>();
    // launch 1: weight conversion/packing
    cvt_weights_k<<<dim3(16384, 8), 256>>>(q_w, kvd_w, kvu_w, o_w, sh_w1, sh_w2, sh_w3,
                                           re_w1, re_w2, re_w3);

    // ---- attention path ----
    rmsnorm_k<<<Tc, 256>>>(x, ln1_w, xnh, nullptr, Dc, Dc);                       // 2
    gemm_h<false, false, false, 0><<<dim3(5, 32, 1), 256, GSMEM>>>(               // 3 <- profiled
        xnh, wqkvh, qlat, nullptr, nullptr, nullptr, nullptr,
        nullptr, nullptr, nullptr, nullptr, Tc, 1280, 1024, 0, 0, 0, 0, 0);
    rmsnorm_k<<<Tc, 256>>>(qlat + 1024, kvn_w, lath, nullptr, Rc, 1280);
    gemm_h<false, false, false, 2><<<dim3(8, 32, 1), 256, GSMEM>>>(
        lath, kvuh, nullptr, nullptr, kvh, nullptr, nullptr,
        nullptr, nullptr, nullptr, nullptr, Tc, 2048, 256, 0, 0, 0, 0, 0);
    attn_h_kernel<<<dim3(Lc / 64, Hc, Bc), 128, ATT_SMEM>>>(qlat, kvh, attnh);
    gemm_h<false, false, true, 0><<<dim3(4, 32, 1), 256, GSMEM>>>(
        attnh, owh, hb, x, nullptr, nullptr, nullptr,
        nullptr, nullptr, nullptr, nullptr, Tc, 1024, 1024, 0, 0, 0, 0, 0);

    // ---- MoE path ----
    rmsnorm_k<<<Tc, 256>>>(hb, ln2_w, hnh, hnb, Dc, Dc);
    router_kernel<<<Tc / 8, 256>>>(hnb, gate_w, outp);

    // merged w13: z=0..7 routed (gather, cnt), z=8 shared (full M)
    gemm_h<true, true, false, 1><<<dim3(8, 32, Ec + 1), 256, GSMEM>>>(
        hnh, rw13h, nullptr, nullptr, ehacth, idxp, cntp,
        hnh, w13h, nullptr, acth,
        Tc, 2048, 1024, 0, (long)1024 * 2048, 0, (long)Tc * Fc, Tc);
    // merged w2: z=0..7 routed (cnt), z=8 shared
    gemm_h<false, true, false, 0><<<dim3(4, 32, Ec + 1), 256, GSMEM>>>(
        ehacth, rw2h, eo, nullptr, nullptr, nullptr, cntp,
        acth, w2h, shb, nullptr,
        Tc, 1024, 1024, (long)Tc * Fc, (long)1024 * 1024, (long)Tc * Dc, 0, 0);

    final_kernel<<<(Tc * Dc / 4 + 255) / 256, 256>>>(hb, shb, outy);
}

// round 16
// speedup vs baseline: 5.0900x; 1.0965x over previous
#include <cuda_runtime.h>
#include <mma.h>
#include <cuda_fp16.h>
#include <math.h>
#include <stdint.h>

using namespace nvcuda;

#define Bc 2
#define Lc 2048
#define Dc 1024
#define Hc 16
#define HDc 64
#define Rc 256
#define Ec 8
#define Kc 2
#define Fc 1024
#define Tc (Bc*Lc)   // 4096

// ---------------- scratch ----------------
__device__ __half g_xn_h[Tc*Dc];
__device__ float  g_qlat[Tc*1280];
__device__ __half g_lat_h[Tc*Rc];
__device__ __half g_kv_h[Tc*2*Hc*HDc];
__device__ __half g_attn_h[Tc*Hc*HDc];
__device__ float  g_h[Tc*Dc];
__device__ float  g_hn[Tc*Dc];
__device__ __half g_hn_h[Tc*Dc];
__device__ __half g_act_h[Tc*Fc];
__device__ float  g_shared[Tc*Dc];
__device__ __half g_wqkv_h[Dc*1280];
__device__ __half g_kvu_h[Rc*2048];
__device__ __half g_ow_h[Dc*Dc];
__device__ __half g_w13_h[Dc*2048];              // pair-interleaved w1/w3
__device__ __half g_w2_h[Dc*Dc];
__device__ __half g_rw13_h[(long)Ec*Dc*2048];    // pair-interleaved
__device__ __half g_rw2_h[(long)Ec*Dc*Dc];
__device__ __half g_ehact_h[(long)Ec*Tc*Fc];
__device__ float  g_eo[(long)Ec*Tc*Dc];
__device__ int    g_cnt[Ec];
__device__ int    g_idx[Ec*Tc];
__device__ int    g_slot[Tc*Kc];
__device__ float  g_tw[Tc*Kc];

// ---------------- helpers ----------------
__device__ __forceinline__ void st_half4(__half* p, float a, float b, float c, float d) {
    *(__half2*)p       = __floats2half2_rn(a, b);
    *(__half2*)(p + 2) = __floats2half2_rn(c, d);
}
__device__ __forceinline__ void cp16(void* sdst, const void* g) {
    unsigned s = (unsigned)__cvta_generic_to_shared(sdst);
    asm volatile("cp.async.cg.shared.global [%0], [%1], 16;" :: "r"(s), "l"(g));
}
#define CP_COMMIT() asm volatile("cp.async.commit_group;")
#define CP_WAIT2()  asm volatile("cp.async.wait_group 2;")

// ---------------- small kernels ----------------
__global__ void zero_cnt_k() {
    if (threadIdx.x < Ec) g_cnt[threadIdx.x] = 0;
}

// convert + pack all weights to half (8 segments)
__global__ void cvt_weights_k(const float* __restrict__ q_w, const float* __restrict__ kvd_w,
                              const float* __restrict__ kvu_w, const float* __restrict__ o_w,
                              const float* __restrict__ sh_w1, const float* __restrict__ sh_w2,
                              const float* __restrict__ sh_w3,
                              const float* __restrict__ re_w1, const float* __restrict__ re_w2,
                              const float* __restrict__ re_w3) {
    int seg = blockIdx.y;
    long i = (long)blockIdx.x * blockDim.x + threadIdx.x;
    switch (seg) {
    case 0: {
        if (i >= (long)Dc * Dc / 4) return;
        long r = i / 256; int c4 = (int)(i % 256);
        float4 v = ((const float4*)q_w)[i];
        st_half4(g_wqkv_h + r * 1280 + c4 * 4, v.x, v.y, v.z, v.w);
        break; }
    case 1: {
        if (i >= (long)Dc * Rc / 4) return;
        long r = i / 64; int c4 = (int)(i % 64);
        float4 v = ((const float4*)kvd_w)[i];
        st_half4(g_wqkv_h + r * 1280 + 1024 + c4 * 4, v.x, v.y, v.z, v.w);
        break; }
    case 2: {
        if (i >= (long)Rc * 2048 / 4) return;
        float4 v = ((const float4*)kvu_w)[i];
        st_half4(g_kvu_h + i * 4, v.x, v.y, v.z, v.w);
        break; }
    case 3: {
        if (i >= (long)Dc * Dc / 4) return;
        float4 v = ((const float4*)o_w)[i];
        st_half4(g_ow_h + i * 4, v.x, v.y, v.z, v.w);
        break; }
    case 4: {
        if (i >= (long)Dc * Dc / 4) return;
        float4 v = ((const float4*)sh_w2)[i];
        st_half4(g_w2_h + i * 4, v.x, v.y, v.z, v.w);
        break; }
    case 5: {
        if (i >= (long)Ec * Dc * Dc / 4) return;
        float4 v = ((const float4*)re_w2)[i];
        st_half4(g_rw2_h + i * 4, v.x, v.y, v.z, v.w);
        break; }
    case 6: {
        if (i >= (long)Dc * Fc / 2) return;
        long r = i / 512; int j2 = (int)(i % 512);
        float2 a = ((const float2*)sh_w1)[r * 512 + j2];
        float2 b = ((const float2*)sh_w3)[r * 512 + j2];
        st_half4(g_w13_h + r * 2048 + j2 * 4, a.x, b.x, a.y, b.y);
        break; }
    default: {
        if (i >= (long)Ec * Dc * Fc / 2) return;
        long r = i / 512; int j2 = (int)(i % 512);
        float2 a = ((const float2*)re_w1)[r * 512 + j2];
        float2 b = ((const float2*)re_w3)[r * 512 + j2];
        st_half4(g_rw13_h + r * 2048 + j2 * 4, a.x, b.x, a.y, b.y);
        break; }
    }
}

// rmsnorm: half output always, fp32 optional
__global__ void rmsnorm_k(const float* __restrict__ x, const float* __restrict__ w,
                          __half* __restrict__ oh, float* __restrict__ of,
                          int dim, int xs) {
    int row = blockIdx.x;
    int tid = threadIdx.x;
    const float* xr = x + (long)row * xs;
    float s = 0.f;
    for (int d = tid; d < dim; d += blockDim.x) { float v = xr[d]; s += v * v; }
    __shared__ float red[256];
    red[tid] = s;
    __syncthreads();
    for (int off = 128; off > 0; off >>= 1) {
        if (tid < off) red[tid] += red[tid + off];
        __syncthreads();
    }
    float inv = rsqrtf(red[0] / (float)dim + 1e-6f);
    __half* ohr = oh + (long)row * dim;
    float* ofr = of ? of + (long)row * dim : nullptr;
    for (int d = tid; d < dim; d += blockDim.x) {
        float v = w[d] * xr[d] * inv;
        ohr[d] = __float2half_rn(v);
        if (of) ofr[d] = v;
    }
}

// ---------------- fp16 TC GEMM: 128x128 tile, 128 threads (4 warps, 64x64 each) ----------------
// m16n16k16, 4-stage cp.async, 2 CTAs/SM target.
// EPI: 0 = fp32 C, 1 = silu-pair -> half, 2 = plain -> half
// Merged mode: if HAS_CNT and aSh != nullptr, block z == gridDim.z-1 runs the
// "shared" problem: A=aSh, B=bSh, full M, no gather, outputs to cSh/actSh.
#define BM 128
#define BN 128
#define BK 32
#define ASTH 40
#define BSTH 136
#define SMAH (BM*ASTH)          // 5120 halfs
#define SMBH (BK*BSTH)          // 4352 halfs
#define STGH (SMAH+SMBH)        // 9472 halfs = 18944 B
#define SST 132
#define GSMEM 75776             // 4*18944; epi staging 128*132*4=67584 fits

template<bool GATHER, bool HAS_CNT, bool RESID, int EPI>
__global__ void __launch_bounds__(128, 2)
gemm_h(const __half* __restrict__ A, const __half* __restrict__ Bw,
       float* __restrict__ C, const float* __restrict__ resid,
       __half* __restrict__ actOut,
       const int* __restrict__ gidx, const int* __restrict__ cntp,
       const __half* __restrict__ aSh, const __half* __restrict__ bSh,
       float* __restrict__ cSh, __half* __restrict__ actSh,
       int M, int N, int Kd,
       long aEs, long bEs, long cEs, long actEs, int iEs) {
    extern __shared__ char smx[];

    int e = blockIdx.z;
    bool sh = HAS_CNT && (aSh != nullptr) && (e == (int)gridDim.z - 1);
    const __half* Ap;
    const __half* Bp;
    int Me;
    if (sh) {
        Ap = aSh; Bp = bSh; Me = M;
    } else {
        Ap = A + (long)e * aEs;
        Bp = Bw + (long)e * bEs;
        Me = HAS_CNT ? cntp[e] : M;
    }
    int bm = blockIdx.y * BM, bn = blockIdx.x * BN;
    if (bm >= Me) return;

    const int tid = threadIdx.x;
    const int warpId = tid >> 5;
    const int wm = warpId >> 1;        // 0..1
    const int wn = warpId & 1;         // 0..1

    // A: 128 rows x 32 halfs = 512 chunks; 4/thread (rows ar0+32i)
    const int ar0 = tid >> 2;          // 0..31
    const int ac8 = (tid & 3) * 8;
    // B: 32 rows x 128 halfs = 512 chunks; 4/thread (rows br0+8i)
    const int br0 = tid >> 4;          // 0..7
    const int bc8 = (tid & 15) * 8;

    long aBase[4];
    int aS[4];
    #pragma unroll
    for (int i = 0; i < 4; i++) {
        int row = ar0 + 32 * i;
        int am = bm + row;
        long ar;
        if (GATHER && !sh) {
            int g = gidx[e * iEs + am];
            if (g < 0 || g >= Tc) g = 0;
            ar = (long)g * Kd;
        } else ar = (long)am * Kd;
        aBase[i] = ar + ac8;
        aS[i] = row * ASTH + ac8;
    }
    long bOff[4];
    int bS[4];
    #pragma unroll
    for (int i = 0; i < 4; i++) {
        int row = br0 + 8 * i;
        bOff[i] = (long)row * N + bn + bc8;
        bS[i] = row * BSTH + bc8;
    }

    wmma::fragment<wmma::accumulator, 16, 16, 16, float> cf[4][4];
    if (RESID) {
        #pragma unroll
        for (int i = 0; i < 4; i++)
            #pragma unroll
            for (int j = 0; j < 4; j++)
                wmma::load_matrix_sync(cf[i][j],
                    resid + (long)(bm + wm * 64 + i * 16) * N + bn + wn * 64 + j * 16,
                    N, wmma::mem_row_major);
    } else {
        #pragma unroll
        for (int i = 0; i < 4; i++)
            #pragma unroll
            for (int j = 0; j < 4; j++)
                wmma::fill_fragment(cf[i][j], 0.f);
    }

    const int T = Kd / BK;

    auto load_tile = [&](int t, int s) {
        __half* As_ = (__half*)smx + s * STGH;
        __half* Bs_ = As_ + SMAH;
        int k0 = t * BK;
        #pragma unroll
        for (int i = 0; i < 4; i++)
            cp16(As_ + aS[i], Ap + aBase[i] + k0);
        #pragma unroll
        for (int i = 0; i < 4; i++)
            cp16(Bs_ + bS[i], Bp + (long)k0 * N + bOff[i]);
    };

    load_tile(0, 0);
    CP_COMMIT();
    if (T > 1) load_tile(1, 1);
    CP_COMMIT();

    for (int t = 0; t < T; t++) {
        if (t + 2 < T) load_tile(t + 2, (t + 2) & 3);
        CP_COMMIT();
        CP_WAIT2();
        __syncthreads();

        int s = t & 3;
        const __half* As_ = (const __half*)smx + s * STGH;
        const __half* Bs_ = As_ + SMAH;
        #pragma unroll
        for (int kk = 0; kk < 2; kk++) {
            wmma::fragment<wmma::matrix_a, 16, 16, 16, __half, wmma::row_major> af[4];
            wmma::fragment<wmma::matrix_b, 16, 16, 16, __half, wmma::row_major> bf[4];
            #pragma unroll
            for (int i = 0; i < 4; i++)
                wmma::load_matrix_sync(af[i], &As_[(wm * 64 + i * 16) * ASTH + kk * 16], ASTH);
            #pragma unroll
            for (int j = 0; j < 4; j++)
                wmma::load_matrix_sync(bf[j], &Bs_[(kk * 16) * BSTH + wn * 64 + j * 16], BSTH);
            #pragma unroll
            for (int i = 0; i < 4; i++)
                #pragma unroll
                for (int j = 0; j < 4; j++)
                    wmma::mma_sync(cf[i][j], af[i], bf[j], cf[i][j]);
        }
    }

    if (EPI >= 1) {
        __syncthreads();
        float* St = (float*)smx;       // [128][SST]
        #pragma unroll
        for (int i = 0; i < 4; i++)
            #pragma unroll
            for (int j = 0; j < 4; j++)
                wmma::store_matrix_sync(&St[(wm * 64 + i * 16) * SST + wn * 64 + j * 16],
                                        cf[i][j], SST, wmma::mem_row_major);
        __syncthreads();
        int r = tid;                    // one row per thread
        __half* aOut = sh ? actSh : actOut + (long)e * actEs;
        if (EPI == 1) {
            long obase = (long)(bm + r) * (N >> 1) + (bn >> 1);
            #pragma unroll 4
            for (int c = 0; c < 64; c += 4) {
                float4 p0 = *(const float4*)&St[r * SST + 2 * c];
                float4 p1 = *(const float4*)&St[r * SST + 2 * c + 4];
                st_half4(aOut + obase + c,
                         p0.x / (1.f + expf(-p0.x)) * p0.y,
                         p0.z / (1.f + expf(-p0.z)) * p0.w,
                         p1.x / (1.f + expf(-p1.x)) * p1.y,
                         p1.z / (1.f + expf(-p1.z)) * p1.w);
            }
        } else {
            long obase = (long)(bm + r) * N + bn;
            #pragma unroll 4
            for (int c = 0; c < 128; c += 4) {
                float4 v = *(const float4*)&St[r * SST + c];
                st_half4(aOut + obase + c, v.x, v.y, v.z, v.w);
            }
        }
    } else {
        float* Cc = sh ? cSh : C + (long)e * cEs;
        #pragma unroll
        for (int i = 0; i < 4; i++)
            #pragma unroll
            for (int j = 0; j < 4; j++)
                wmma::store_matrix_sync(
                    Cc + (long)(bm + wm * 64 + i * 16) * N + bn + wn * 64 + j * 16,
                    cf[i][j], N, wmma::mem_row_major);
    }
}

// ---------------- fp16 TC causal flash attention, register-resident O ----------------
#define HSTR 72
#define FSTR 68
#define ATT_SMEM (4*64*HSTR*2 + 64*FSTR*4 + 2*64*4)   // 54784 B

__global__ void __launch_bounds__(128)
attn_h_kernel(const float* __restrict__ q, const __half* __restrict__ kv,
              __half* __restrict__ o) {
    extern __shared__ char smema[];
    __half* Qs = (__half*)smema;
    __half* Ks = Qs + 64 * HSTR;
    __half* Vs = Ks + 64 * HSTR;
    __half* Ph = Vs + 64 * HSTR;
    float* Sf = (float*)(Ph + 64 * HSTR);
    float* crow = Sf + 64 * FSTR;
    float* lrow = crow + 64;

    const int b = blockIdx.z, h = blockIdx.y, iq = blockIdx.x;
    const int q0 = iq * 64;
    const int tid = threadIdx.x;
    const int warpId = tid >> 5;
    const int lane = tid & 31;
    const int r = tid >> 1;
    const int hf = tid & 1;
    const int c0 = hf * 32;

    wmma::fragment<wmma::accumulator, 16, 16, 16, float> of[4];
    #pragma unroll
    for (int n = 0; n < 4; n++) wmma::fill_fragment(of[n], 0.f);
    float m_run = -INFINITY, l_run = 0.f;

    {
        long qb = ((long)(b * Lc + q0 + r)) * 1280 + h * HDc + c0;
        #pragma unroll
        for (int dd = 0; dd < 32; dd += 4) {
            float4 v = *(const float4*)(q + qb + dd);
            st_half4(Qs + r * HSTR + c0 + dd, v.x * 0.125f, v.y * 0.125f,
                     v.z * 0.125f, v.w * 0.125f);
        }
    }
    __syncthreads();

    for (int kt = 0; kt <= q0; kt += 64) {
        {
            long kvb = ((long)(b * Lc + kt + r)) * (2 * Hc * HDc) + h * HDc + c0;
            #pragma unroll
            for (int dd = 0; dd < 32; dd += 8) {
                *(int4*)&Ks[r * HSTR + c0 + dd] = *(const int4*)(kv + kvb + dd);
                *(int4*)&Vs[r * HSTR + c0 + dd] = *(const int4*)(kv + kvb + Hc * HDc + dd);
            }
        }
        __syncthreads();

        {
            wmma::fragment<wmma::accumulator, 16, 16, 16, float> sf[4];
            #pragma unroll
            for (int n = 0; n < 4; n++) wmma::fill_fragment(sf[n], 0.f);
            #pragma unroll
            for (int kk = 0; kk < 4; kk++) {
                wmma::fragment<wmma::matrix_a, 16, 16, 16, __half, wmma::row_major> aq;
                wmma::load_matrix_sync(aq, &Qs[(warpId * 16) * HSTR + kk * 16], HSTR);
                #pragma unroll
                for (int n = 0; n < 4; n++) {
                    wmma::fragment<wmma::matrix_b, 16, 16, 16, __half, wmma::col_major> bk;
                    wmma::load_matrix_sync(bk, &Ks[(n * 16) * HSTR + kk * 16], HSTR);
                    wmma::mma_sync(sf[n], aq, bk, sf[n]);
                }
            }
            #pragma unroll
            for (int n = 0; n < 4; n++)
                wmma::store_matrix_sync(&Sf[(warpId * 16) * FSTR + n * 16], sf[n], FSTR, wmma::mem_row_major);
        }
        __syncthreads();

        {
            int limit = (kt == q0) ? (r + 1) : 64;
            int vend = limit - c0;
            if (vend > 32) vend = 32;
            float mx = -INFINITY;
            for (int c = 0; c < vend; c++) mx = fmaxf(mx, Sf[r * FSTR + c0 + c]);
            mx = fmaxf(mx, __shfl_xor_sync(0xffffffffu, mx, 1));
            float nm = fmaxf(m_run, mx);
            float corr = __expf(m_run - nm);
            float sum = 0.f;
            for (int c = 0; c < vend; c++) {
                float p = __expf(Sf[r * FSTR + c0 + c] - nm);
                Ph[r * HSTR + c0 + c] = __float2half_rn(p);
                sum += p;
            }
            for (int c = (vend < 0 ? 0 : vend); c < 32; c++)
                Ph[r * HSTR + c0 + c] = __float2half_rn(0.f);
            sum += __shfl_xor_sync(0xffffffffu, sum, 1);
            l_run = l_run * corr + sum;
            m_run = nm;
            if (hf == 0) crow[r] = corr;
        }
        __syncthreads();

        {
            #pragma unroll
            for (int n = 0; n < 4; n++) {
                #pragma unroll
                for (int k = 0; k < 8; k++) {
                    int rl = (lane >> 2) + (((k >> 1) & 1) << 3);
                    of[n].x[k] *= crow[warpId * 16 + rl];
                }
            }
            #pragma unroll
            for (int kk = 0; kk < 4; kk++) {
                wmma::fragment<wmma::matrix_a, 16, 16, 16, __half, wmma::row_major> ap;
                wmma::load_matrix_sync(ap, &Ph[(warpId * 16) * HSTR + kk * 16], HSTR);
                #pragma unroll
                for (int n = 0; n < 4; n++) {
                    wmma::fragment<wmma::matrix_b, 16, 16, 16, __half, wmma::row_major> bv;
                    wmma::load_matrix_sync(bv, &Vs[(kk * 16) * HSTR + n * 16], HSTR);
                    wmma::mma_sync(of[n], ap, bv, of[n]);
                }
            }
        }
        __syncthreads();
    }

    if (hf == 0) lrow[r] = l_run;
    __syncthreads();
    {
        #pragma unroll
        for (int n = 0; n < 4; n++) {
            #pragma unroll
            for (int k = 0; k < 8; k += 2) {
                int rl = (lane >> 2) + (((k >> 1) & 1) << 3);
                int col = (lane & 3) * 2 + ((k >> 2) << 3);
                float inv = 1.f / lrow[warpId * 16 + rl];
                long ob = ((long)(b * Lc + q0 + warpId * 16 + rl)) * (Hc * HDc)
                        + h * HDc + n * 16 + col;
                *(__half2*)(o + ob) = __floats2half2_rn(of[n].x[k] * inv,
                                                        of[n].x[k + 1] * inv);
            }
        }
    }
}

// ---------------- router (fp32 hn) ----------------
__global__ void router_kernel(const float* __restrict__ hn, const float* __restrict__ gw,
                              float* __restrict__ probs_out) {
    int warp = (blockIdx.x * blockDim.x + threadIdx.x) >> 5;
    int lane = threadIdx.x & 31;
    if (warp >= Tc) return;
    const float* row = hn + (long)warp * Dc;
    float acc[8] = {0, 0, 0, 0, 0, 0, 0, 0};
    for (int d = lane; d < Dc; d += 32) {
        float xv = row[d];
        const float* g = gw + d * 8;
        #pragma unroll
        for (int e = 0; e < 8; e++) acc[e] += xv * g[e];
    }
    #pragma unroll
    for (int e = 0; e < 8; e++)
        #pragma unroll
        for (int off = 16; off > 0; off >>= 1)
            acc[e] += __shfl_xor_sync(0xffffffffu, acc[e], off);

    if (lane == 0) {
        float mx = acc[0];
        #pragma unroll
        for (int e = 1; e < 8; e++) mx = fmaxf(mx, acc[e]);
        float p[8], s = 0.f;
        #pragma unroll
        for (int e = 0; e < 8; e++) { p[e] = expf(acc[e] - mx); s += p[e]; }
        float invs = 1.f / s;
        #pragma unroll
        for (int e = 0; e < 8; e++) { p[e] *= invs; probs_out[(long)warp * 8 + e] = p[e]; }
        int i1 = 0;
        #pragma unroll
        for (int e = 1; e < 8; e++) if (p[e] > p[i1]) i1 = e;
        int i2 = (i1 == 0) ? 1 : 0;
        #pragma unroll
        for (int e = 0; e < 8; e++) if (e != i1 && p[e] > p[i2]) i2 = e;
        float w1 = p[i1], w2 = p[i2];
        float inv2 = 1.f / (w1 + w2);
        w1 *= inv2; w2 *= inv2;
        int pos1 = atomicAdd(&g_cnt[i1], 1);
        g_idx[i1 * Tc + pos1] = warp;
        g_slot[warp * 2 + 0] = i1 * Tc + pos1;
        g_tw[warp * 2 + 0] = w1;
        int pos2 = atomicAdd(&g_cnt[i2], 1);
        g_idx[i2 * Tc + pos2] = warp;
        g_slot[warp * 2 + 1] = i2 * Tc + pos2;
        g_tw[warp * 2 + 1] = w2;
    }
}

// ---------------- final combine ----------------
__global__ void final_kernel(const float* __restrict__ h, const float* __restrict__ sh,
                             float* __restrict__ out) {
    long i4 = (long)blockIdx.x * blockDim.x + threadIdx.x;
    if (i4 >= (long)Tc * Dc / 4) return;
    int t = (int)(i4 / (Dc / 4));
    int d4 = (int)(i4 % (Dc / 4));
    int s0 = g_slot[t * 2 + 0], s1 = g_slot[t * 2 + 1];
    float w0 = g_tw[t * 2 + 0], w1 = g_tw[t * 2 + 1];
    float4 e0 = *(const float4*)(g_eo + (long)s0 * Dc + d4 * 4);
    float4 e1 = *(const float4*)(g_eo + (long)s1 * Dc + d4 * 4);
    float4 hv = ((const float4*)h)[i4];
    float4 sv = ((const float4*)sh)[i4];
    float4 r;
    r.x = hv.x + sv.x + w0 * e0.x + w1 * e1.x;
    r.y = hv.y + sv.y + w0 * e0.y + w1 * e1.y;
    r.z = hv.z + sv.z + w0 * e0.z + w1 * e1.z;
    r.w = hv.w + sv.w + w0 * e0.w + w1 * e1.w;
    ((float4*)out)[i4] = r;
}

// ---------------- launch ----------------
extern "C" void kernel_launch(void* const* d_in, const int* in_sizes, int n_in,
                              void* d_out, int out_size) {
    const float* x     = (const float*)d_in[0];
    const float* ln1_w = (const float*)d_in[1];
    const float* q_w   = (const float*)d_in[2];
    const float* kvd_w = (const float*)d_in[3];
    const float* kvn_w = (const float*)d_in[4];
    const float* kvu_w = (const float*)d_in[5];
    const float* o_w   = (const float*)d_in[6];
    const float* ln2_w = (const float*)d_in[7];
    const float* gate_w= (const float*)d_in[8];
    const float* sh_w1 = (const float*)d_in[9];
    const float* sh_w2 = (const float*)d_in[10];
    const float* sh_w3 = (const float*)d_in[11];
    const float* re_w1 = (const float*)d_in[12];
    const float* re_w2 = (const float*)d_in[13];
    const float* re_w3 = (const float*)d_in[14];

    float* outy = (float*)d_out;
    float* outp = outy + (long)Tc * Dc;

    __half *xnh, *lath, *kvh, *attnh, *hnh, *acth, *ehacth;
    __half *wqkvh, *kvuh, *owh, *w13h, *w2h, *rw13h, *rw2h;
    float *qlat, *hb, *hnb, *shb, *eo;
    cudaGetSymbolAddress((void**)&xnh, g_xn_h);
    cudaGetSymbolAddress((void**)&lath, g_lat_h);
    cudaGetSymbolAddress((void**)&kvh, g_kv_h);
    cudaGetSymbolAddress((void**)&attnh, g_attn_h);
    cudaGetSymbolAddress((void**)&hnh, g_hn_h);
    cudaGetSymbolAddress((void**)&acth, g_act_h);
    cudaGetSymbolAddress((void**)&ehacth, g_ehact_h);
    cudaGetSymbolAddress((void**)&wqkvh, g_wqkv_h);
    cudaGetSymbolAddress((void**)&kvuh, g_kvu_h);
    cudaGetSymbolAddress((void**)&owh, g_ow_h);
    cudaGetSymbolAddress((void**)&w13h, g_w13_h);
    cudaGetSymbolAddress((void**)&w2h, g_w2_h);
    cudaGetSymbolAddress((void**)&rw13h, g_rw13_h);
    cudaGetSymbolAddress((void**)&rw2h, g_rw2_h);
    cudaGetSymbolAddress((void**)&qlat, g_qlat);
    cudaGetSymbolAddress((void**)&hb, g_h);
    cudaGetSymbolAddress((void**)&hnb, g_hn);
    cudaGetSymbolAddress((void**)&shb, g_shared);
    cudaGetSymbolAddress((void**)&eo, g_eo);
    int* idxp; int* cntp;
    cudaGetSymbolAddress((void**)&idxp, g_idx);
    cudaGetSymbolAddress((void**)&cntp, g_cnt);

    cudaFuncSetAttribute((const void*)gemm_h<false, false, false, 0>,
                         cudaFuncAttributeMaxDynamicSharedMemorySize, GSMEM);
    cudaFuncSetAttribute((const void*)gemm_h<false, false, true, 0>,
                         cudaFuncAttributeMaxDynamicSharedMemorySize, GSMEM);
    cudaFuncSetAttribute((const void*)gemm_h<false, false, false, 2>,
                         cudaFuncAttributeMaxDynamicSharedMemorySize, GSMEM);
    cudaFuncSetAttribute((const void*)gemm_h<true, true, false, 1>,
                         cudaFuncAttributeMaxDynamicSharedMemorySize, GSMEM);
    cudaFuncSetAttribute((const void*)gemm_h<false, true, false, 0>,
                         cudaFuncAttributeMaxDynamicSharedMemorySize, GSMEM);
    cudaFuncSetAttribute((const void*)attn_h_kernel,
                         cudaFuncAttributeMaxDynamicSharedMemorySize, ATT_SMEM);

    // launch 0: zero counters; launch 1: weight conversion
    zero_cnt_k<<<1, 32>>>();
    cvt_weights_k<<<dim3(16384, 8), 256>>>(q_w, kvd_w, kvu_w, o_w, sh_w1, sh_w2, sh_w3,
                                           re_w1, re_w2, re_w3);

    // ---- attention path ----
    rmsnorm_k<<<Tc, 256>>>(x, ln1_w, xnh, nullptr, Dc, Dc);                       // 2
    gemm_h<false, false, false, 0><<<dim3(10, 32, 1), 128, GSMEM>>>(              // 3 <- profiled
        xnh, wqkvh, qlat, nullptr, nullptr, nullptr, nullptr,
        nullptr, nullptr, nullptr, nullptr, Tc, 1280, 1024, 0, 0, 0, 0, 0);
    rmsnorm_k<<<Tc, 256>>>(qlat + 1024, kvn_w, lath, nullptr, Rc, 1280);
    gemm_h<false, false, false, 2><<<dim3(16, 32, 1), 128, GSMEM>>>(
        lath, kvuh, nullptr, nullptr, kvh, nullptr, nullptr,
        nullptr, nullptr, nullptr, nullptr, Tc, 2048, 256, 0, 0, 0, 0, 0);
    attn_h_kernel<<<dim3(Lc / 64, Hc, Bc), 128, ATT_SMEM>>>(qlat, kvh, attnh);
    gemm_h<false, false, true, 0><<<dim3(8, 32, 1), 128, GSMEM>>>(
        attnh, owh, hb, x, nullptr, nullptr, nullptr,
        nullptr, nullptr, nullptr, nullptr, Tc, 1024, 1024, 0, 0, 0, 0, 0);

    // ---- MoE path ----
    rmsnorm_k<<<Tc, 256>>>(hb, ln2_w, hnh, hnb, Dc, Dc);
    router_kernel<<<Tc / 8, 256>>>(hnb, gate_w, outp);

    // merged w13: z=0..7 routed (gather, cnt), z=8 shared (full M)
    gemm_h<true, true, false, 1><<<dim3(16, 32, Ec + 1), 128, GSMEM>>>(
        hnh, rw13h, nullptr, nullptr, ehacth, idxp, cntp,
        hnh, w13h, nullptr, acth,
        Tc, 2048, 1024, 0, (long)1024 * 2048, 0, (long)Tc * Fc, Tc);
    // merged w2: z=0..7 routed (cnt), z=8 shared
    gemm_h<false, true, false, 0><<<dim3(8, 32, Ec + 1), 128, GSMEM>>>(
        ehacth, rw2h, eo, nullptr, nullptr, nullptr, cntp,
        acth, w2h, shb, nullptr,
        Tc, 1024, 1024, (long)Tc * Fc, (long)1024 * 1024, (long)Tc * Dc, 0, 0);

    final_kernel<<<(Tc * Dc / 4 + 255) / 256, 256>>>(hb, shb, outy);
}